// round 4
// baseline (speedup 1.0000x reference)
#include <cuda_runtime.h>
#include <cuda_bf16.h>
#include <math.h>

// Problem constants
#define BATCH   4
#define SEQ_N   2048
#define SEQ_J   2048
#define DIM     768
#define HEADS   12
#define DHEAD   64
#define INNER   (HEADS * DHEAD)   // 768
#define SCALE   0.125f             // 64^-0.5

#define ROWS_TOTAL (BATCH * SEQ_N) // 8192

// ---------------------------------------------------------------------------
// Scratch (static device allocations; no cudaMalloc allowed)
// ---------------------------------------------------------------------------
__device__ float g_xn[(size_t)ROWS_TOTAL * DIM];     // layernorm(x)        24 MB
__device__ float g_q [(size_t)ROWS_TOTAL * INNER];   // q (natural layout)  24 MB
__device__ float g_kv[(size_t)ROWS_TOTAL * 128];     // [k|v] per context    4 MB
__device__ float g_ao[(size_t)ROWS_TOTAL * INNER];   // attn output         24 MB

// ---------------------------------------------------------------------------
// LayerNorm: one block per row of 768
// ---------------------------------------------------------------------------
__global__ void ln_kernel(const float* __restrict__ x,
                          const float* __restrict__ w,
                          float* __restrict__ y)
{
    const int row = blockIdx.x;
    const float* xr = x + (size_t)row * DIM;
    float v[3];
    float s = 0.f, s2 = 0.f;
#pragma unroll
    for (int t = 0; t < 3; t++) {
        int i = threadIdx.x + t * 256;
        float vv = xr[i];
        v[t] = vv;
        s += vv; s2 += vv * vv;
    }
    // warp reduce
#pragma unroll
    for (int o = 16; o > 0; o >>= 1) {
        s  += __shfl_xor_sync(0xffffffffu, s,  o);
        s2 += __shfl_xor_sync(0xffffffffu, s2, o);
    }
    __shared__ float rs[8], rs2[8];
    int wid = threadIdx.x >> 5, lid = threadIdx.x & 31;
    if (lid == 0) { rs[wid] = s; rs2[wid] = s2; }
    __syncthreads();
    if (wid == 0) {
        s  = (lid < 8) ? rs[lid]  : 0.f;
        s2 = (lid < 8) ? rs2[lid] : 0.f;
#pragma unroll
        for (int o = 4; o > 0; o >>= 1) {
            s  += __shfl_xor_sync(0xffffffffu, s,  o);
            s2 += __shfl_xor_sync(0xffffffffu, s2, o);
        }
        if (lid == 0) { rs[0] = s; rs2[0] = s2; }
    }
    __syncthreads();
    const float mu   = rs[0] * (1.f / DIM);
    const float var  = rs2[0] * (1.f / DIM) - mu * mu;
    const float rstd = rsqrtf(var + 1e-5f);
    float* yr = y + (size_t)row * DIM;
#pragma unroll
    for (int t = 0; t < 3; t++) {
        int i = threadIdx.x + t * 256;
        yr[i] = (v[t] - mu) * rstd * w[i];
    }
}

// ---------------------------------------------------------------------------
// SGEMM: C[M,N] = alpha * A[M,K] @ B[K,N]    (row-major, fp32)
// BM=128, BN=64, BK=16, 256 threads, 8x4 microtile.
// Requires M%128==0, N%64==0, K%16==0 (true for all three calls).
// ---------------------------------------------------------------------------
__global__ __launch_bounds__(256)
void sgemm_kernel(const float* __restrict__ A, const float* __restrict__ B,
                  float* __restrict__ C, int M, int N, int K, float alpha)
{
    __shared__ float As[16][128];
    __shared__ float Bs[16][64];

    const int tid = threadIdx.x;
    const int m0 = blockIdx.y * 128;
    const int n0 = blockIdx.x * 64;
    const int tr = tid >> 4;        // 0..15  (row group, 8 rows each)
    const int tc = tid & 15;        // 0..15  (col group, 4 cols each)

    float acc[8][4];
#pragma unroll
    for (int i = 0; i < 8; i++)
#pragma unroll
        for (int j = 0; j < 4; j++) acc[i][j] = 0.f;

    for (int k0 = 0; k0 < K; k0 += 16) {
        // load A tile (128x16) transposed into As[16][128]
#pragma unroll
        for (int t = 0; t < 2; t++) {
            int e  = tid + t * 256;          // 0..511 float4 slots
            int m  = e >> 2;
            int kq = (e & 3) * 4;
            float4 a4 = *reinterpret_cast<const float4*>(
                &A[(size_t)(m0 + m) * K + k0 + kq]);
            As[kq + 0][m] = a4.x;
            As[kq + 1][m] = a4.y;
            As[kq + 2][m] = a4.z;
            As[kq + 3][m] = a4.w;
        }
        // load B tile (16x64)
        {
            int r = tid >> 4;
            int c = (tid & 15) * 4;
            *reinterpret_cast<float4*>(&Bs[r][c]) =
                *reinterpret_cast<const float4*>(&B[(size_t)(k0 + r) * N + n0 + c]);
        }
        __syncthreads();
#pragma unroll
        for (int kk = 0; kk < 16; kk++) {
            float a[8], bb[4];
#pragma unroll
            for (int i = 0; i < 8; i++) a[i] = As[kk][tr * 8 + i];
#pragma unroll
            for (int j = 0; j < 4; j++) bb[j] = Bs[kk][tc * 4 + j];
#pragma unroll
            for (int i = 0; i < 8; i++)
#pragma unroll
                for (int j = 0; j < 4; j++) acc[i][j] += a[i] * bb[j];
        }
        __syncthreads();
    }

#pragma unroll
    for (int i = 0; i < 8; i++) {
        float4 r;
        r.x = acc[i][0] * alpha;
        r.y = acc[i][1] * alpha;
        r.z = acc[i][2] * alpha;
        r.w = acc[i][3] * alpha;
        *reinterpret_cast<float4*>(
            &C[(size_t)(m0 + tr * 8 + i) * N + n0 + tc * 4]) = r;
    }
}

// ---------------------------------------------------------------------------
// Flash attention (fp32). One thread owns one q-row; K/V tiles in smem.
// q layout: [b, n, h, d] (natural from GEMM). kv layout: [b*j, 128] (k|v).
// Output: [b, n, h*d].
// Grid: (SEQ_N/128, HEADS, BATCH), 128 threads.
// ---------------------------------------------------------------------------
#define TJ 64
__global__ __launch_bounds__(128)
void attn_kernel(const float* __restrict__ q, const float* __restrict__ kv,
                 const float* __restrict__ mask, float* __restrict__ o)
{
    __shared__ float4 Ks[TJ][16];
    __shared__ float4 Vs[TJ][16];

    const int row_l = threadIdx.x;
    const int row   = blockIdx.x * 128 + row_l;
    const int h     = blockIdx.y;
    const int b     = blockIdx.z;

    // load q row (scaled) into registers
    float4 qv[16];
    {
        const float4* qr = reinterpret_cast<const float4*>(
            &q[((size_t)(b * SEQ_N) + row) * INNER + h * DHEAD]);
#pragma unroll
        for (int dv = 0; dv < 16; dv++) {
            float4 t = qr[dv];
            t.x *= SCALE; t.y *= SCALE; t.z *= SCALE; t.w *= SCALE;
            qv[dv] = t;
        }
    }

    float4 acc[16];
#pragma unroll
    for (int dv = 0; dv < 16; dv++) acc[dv] = make_float4(0.f, 0.f, 0.f, 0.f);
    float m = -INFINITY, l = 0.f;

    const size_t bj_base = (size_t)b * SEQ_J;
    const float* mrow_base = &mask[((size_t)(b * SEQ_N) + row) * SEQ_J];

    for (int jt = 0; jt < SEQ_J; jt += TJ) {
        __syncthreads();
        // cooperative load of K,V tiles (64 rows x 64 floats each)
#pragma unroll
        for (int t = 0; t < 8; t++) {
            int e  = threadIdx.x + t * 128;   // 0..1023
            int jj = e >> 4;
            int dv = e & 15;
            const float4* src = reinterpret_cast<const float4*>(
                &kv[(bj_base + jt + jj) * 128]);
            Ks[jj][dv] = src[dv];
            Vs[jj][dv] = src[16 + dv];
        }
        __syncthreads();

        const float* mrow = mrow_base + jt;
#pragma unroll 2
        for (int jj = 0; jj < TJ; jj++) {
            float s = 0.f;
#pragma unroll
            for (int dv = 0; dv < 16; dv++) {
                float4 k4 = Ks[jj][dv];
                float4 q4 = qv[dv];
                s += q4.x * k4.x + q4.y * k4.y + q4.z * k4.z + q4.w * k4.w;
            }
            s += mrow[jj];

            if (s > m) {                      // rare after warmup
                float corr = __expf(m - s);   // exp(-inf)=0 on first hit
                m = s;
                l *= corr;
#pragma unroll
                for (int dv = 0; dv < 16; dv++) {
                    acc[dv].x *= corr; acc[dv].y *= corr;
                    acc[dv].z *= corr; acc[dv].w *= corr;
                }
            }
            float p = __expf(s - m);
            l += p;
#pragma unroll
            for (int dv = 0; dv < 16; dv++) {
                float4 v4 = Vs[jj][dv];
                acc[dv].x += p * v4.x; acc[dv].y += p * v4.y;
                acc[dv].z += p * v4.z; acc[dv].w += p * v4.w;
            }
        }
    }

    const float inv = 1.f / l;
    float4* orow = reinterpret_cast<float4*>(
        &o[((size_t)(b * SEQ_N) + row) * INNER + h * DHEAD]);
#pragma unroll
    for (int dv = 0; dv < 16; dv++) {
        float4 r = acc[dv];
        r.x *= inv; r.y *= inv; r.z *= inv; r.w *= inv;
        orow[dv] = r;
    }
}

// ---------------------------------------------------------------------------
// Launch
// ---------------------------------------------------------------------------
extern "C" void kernel_launch(void* const* d_in, const int* in_sizes, int n_in,
                              void* d_out, int out_size)
{
    const float* x       = (const float*)d_in[0];
    const float* context = (const float*)d_in[1];
    const float* mask    = (const float*)d_in[2];
    const float* ln_w    = (const float*)d_in[3];
    const float* Wq      = (const float*)d_in[4];
    const float* Wkv     = (const float*)d_in[5];
    const float* Wo      = (const float*)d_in[6];
    float* out = (float*)d_out;

    float *xn, *q, *kvb, *ao;
    cudaGetSymbolAddress((void**)&xn,  g_xn);
    cudaGetSymbolAddress((void**)&q,   g_q);
    cudaGetSymbolAddress((void**)&kvb, g_kv);
    cudaGetSymbolAddress((void**)&ao,  g_ao);

    // 1. layernorm
    ln_kernel<<<ROWS_TOTAL, 256>>>(x, ln_w, xn);

    // 2. q = ln(x) @ Wq   (scale folded into epilogue is NOT applied here;
    //    attention applies SCALE at q load — pass alpha=1)
    sgemm_kernel<<<dim3(INNER / 64, ROWS_TOTAL / 128), 256>>>(
        xn, Wq, q, ROWS_TOTAL, INNER, DIM, 1.0f);

    // 3. kv = context @ Wkv  ([8192, 128], k = cols 0..63, v = 64..127)
    sgemm_kernel<<<dim3(128 / 64, ROWS_TOTAL / 128), 256>>>(
        context, Wkv, kvb, ROWS_TOTAL, 128, DIM, 1.0f);

    // 4. attention
    attn_kernel<<<dim3(SEQ_N / 128, HEADS, BATCH), 128>>>(q, kvb, mask, ao);

    // 5. out = ao @ Wo
    sgemm_kernel<<<dim3(DIM / 64, ROWS_TOTAL / 128), 256>>>(
        ao, Wo, out, ROWS_TOTAL, DIM, INNER, 1.0f);
}

// round 5
// speedup vs baseline: 1.5029x; 1.5029x over previous
#include <cuda_runtime.h>
#include <cuda_bf16.h>
#include <math.h>

// Problem constants
#define BATCH   4
#define SEQ_N   2048
#define SEQ_J   2048
#define DIM     768
#define HEADS   12
#define DHEAD   64
#define INNER   (HEADS * DHEAD)   // 768
#define SCALE   0.125f            // 64^-0.5

#define ROWS_TOTAL (BATCH * SEQ_N) // 8192

// ---------------------------------------------------------------------------
// Scratch (static device allocations; no cudaMalloc allowed)
// ---------------------------------------------------------------------------
__device__ float g_xn[(size_t)ROWS_TOTAL * DIM];     // layernorm(x)
__device__ float g_q [(size_t)ROWS_TOTAL * INNER];   // q
__device__ float g_kv[(size_t)ROWS_TOTAL * 128];     // [k|v] per context row
__device__ float g_ao[(size_t)ROWS_TOTAL * INNER];   // attn output

// ---------------------------------------------------------------------------
// LayerNorm: one block per row of 768
// ---------------------------------------------------------------------------
__global__ void ln_kernel(const float* __restrict__ x,
                          const float* __restrict__ w,
                          float* __restrict__ y)
{
    const int row = blockIdx.x;
    const float* xr = x + (size_t)row * DIM;
    float v[3];
    float s = 0.f, s2 = 0.f;
#pragma unroll
    for (int t = 0; t < 3; t++) {
        int i = threadIdx.x + t * 256;
        float vv = xr[i];
        v[t] = vv;
        s += vv; s2 += vv * vv;
    }
#pragma unroll
    for (int o = 16; o > 0; o >>= 1) {
        s  += __shfl_xor_sync(0xffffffffu, s,  o);
        s2 += __shfl_xor_sync(0xffffffffu, s2, o);
    }
    __shared__ float rs[8], rs2[8];
    int wid = threadIdx.x >> 5, lid = threadIdx.x & 31;
    if (lid == 0) { rs[wid] = s; rs2[wid] = s2; }
    __syncthreads();
    if (wid == 0) {
        s  = (lid < 8) ? rs[lid]  : 0.f;
        s2 = (lid < 8) ? rs2[lid] : 0.f;
#pragma unroll
        for (int o = 4; o > 0; o >>= 1) {
            s  += __shfl_xor_sync(0xffffffffu, s,  o);
            s2 += __shfl_xor_sync(0xffffffffu, s2, o);
        }
        if (lid == 0) { rs[0] = s; rs2[0] = s2; }
    }
    __syncthreads();
    const float mu   = rs[0] * (1.f / DIM);
    const float var  = rs2[0] * (1.f / DIM) - mu * mu;
    const float rstd = rsqrtf(var + 1e-5f);
    float* yr = y + (size_t)row * DIM;
#pragma unroll
    for (int t = 0; t < 3; t++) {
        int i = threadIdx.x + t * 256;
        yr[i] = (v[t] - mu) * rstd * w[i];
    }
}

// ---------------------------------------------------------------------------
// SGEMM: C[M,N] = alpha * A[M,K] @ B[K,N]    (row-major, fp32)
// BM=128, BN=64, BK=16, 256 threads, 8x4 microtile.
// ---------------------------------------------------------------------------
__global__ __launch_bounds__(256)
void sgemm_kernel(const float* __restrict__ A, const float* __restrict__ B,
                  float* __restrict__ C, int M, int N, int K, float alpha)
{
    __shared__ float As[16][128];
    __shared__ float Bs[16][64];

    const int tid = threadIdx.x;
    const int m0 = blockIdx.y * 128;
    const int n0 = blockIdx.x * 64;
    const int tr = tid >> 4;
    const int tc = tid & 15;

    float acc[8][4];
#pragma unroll
    for (int i = 0; i < 8; i++)
#pragma unroll
        for (int j = 0; j < 4; j++) acc[i][j] = 0.f;

    for (int k0 = 0; k0 < K; k0 += 16) {
#pragma unroll
        for (int t = 0; t < 2; t++) {
            int e  = tid + t * 256;
            int m  = e >> 2;
            int kq = (e & 3) * 4;
            float4 a4 = *reinterpret_cast<const float4*>(
                &A[(size_t)(m0 + m) * K + k0 + kq]);
            As[kq + 0][m] = a4.x;
            As[kq + 1][m] = a4.y;
            As[kq + 2][m] = a4.z;
            As[kq + 3][m] = a4.w;
        }
        {
            int r = tid >> 4;
            int c = (tid & 15) * 4;
            *reinterpret_cast<float4*>(&Bs[r][c]) =
                *reinterpret_cast<const float4*>(&B[(size_t)(k0 + r) * N + n0 + c]);
        }
        __syncthreads();
#pragma unroll
        for (int kk = 0; kk < 16; kk++) {
            float a[8], bb[4];
#pragma unroll
            for (int i = 0; i < 8; i++) a[i] = As[kk][tr * 8 + i];
#pragma unroll
            for (int j = 0; j < 4; j++) bb[j] = Bs[kk][tc * 4 + j];
#pragma unroll
            for (int i = 0; i < 8; i++)
#pragma unroll
                for (int j = 0; j < 4; j++) acc[i][j] += a[i] * bb[j];
        }
        __syncthreads();
    }

#pragma unroll
    for (int i = 0; i < 8; i++) {
        float4 r;
        r.x = acc[i][0] * alpha;
        r.y = acc[i][1] * alpha;
        r.z = acc[i][2] * alpha;
        r.w = acc[i][3] * alpha;
        *reinterpret_cast<float4*>(
            &C[(size_t)(m0 + tr * 8 + i) * N + n0 + tc * 4]) = r;
    }
}

// ---------------------------------------------------------------------------
// Flash attention, register-blocked (two GEMMs per tile + online softmax).
// Block: 128 q-rows of one (b, h). 256 threads, 8x4 micro-tiles.
// Thread (tr=tid>>4, tc=tid&15) owns rows tr*8..tr*8+7 and cols {tc+16j}.
// Smem (dynamic, 100 KB):
//   Qs[64][132]  (d, row)  transposed Q tile, pre-scaled
//   Ks[64][68]   (d, jj)   transposed K tile
//   Vs[64][68]   (jj, d)   V tile, natural layout
//   Ps[64][132]  (jj, row) softmax probabilities
// Grid: (SEQ_N/128, HEADS, BATCH)
// ---------------------------------------------------------------------------
#define QS_STRIDE 132
#define KS_STRIDE 68
#define VS_STRIDE 68
#define PS_STRIDE 132
#define SM_QS 0
#define SM_KS (SM_QS + 64 * QS_STRIDE)          // 8448
#define SM_VS (SM_KS + 64 * KS_STRIDE)          // 12800
#define SM_PS (SM_VS + 64 * VS_STRIDE)          // 17152
#define SM_TOTAL (SM_PS + 64 * PS_STRIDE)       // 25600 floats = 100 KB

__global__ __launch_bounds__(256)
void attn_kernel(const float* __restrict__ q, const float* __restrict__ kv,
                 const float* __restrict__ mask, float* __restrict__ o)
{
    extern __shared__ float sm[];
    float* Qs = sm + SM_QS;
    float* Ks = sm + SM_KS;
    float* Vs = sm + SM_VS;
    float* Ps = sm + SM_PS;

    const int tid = threadIdx.x;
    const int tr  = tid >> 4;        // 0..15 (8 rows each)
    const int tc  = tid & 15;        // 0..15 (4 strided cols: tc + 16j)
    const int h   = blockIdx.y;
    const int b   = blockIdx.z;
    const int row0 = blockIdx.x * 128;

    // ---- Load Q tile (128 x 64), transposed + pre-scaled ----
#pragma unroll
    for (int t = 0; t < 8; t++) {
        int e  = tid + t * 256;          // 0..2047 float4 slots
        int r  = e >> 4;                 // q row within tile
        int dq = (e & 15) * 4;           // d offset
        float4 v = *reinterpret_cast<const float4*>(
            &q[((size_t)(b * SEQ_N) + row0 + r) * INNER + h * DHEAD + dq]);
        Qs[(dq + 0) * QS_STRIDE + r] = v.x * SCALE;
        Qs[(dq + 1) * QS_STRIDE + r] = v.y * SCALE;
        Qs[(dq + 2) * QS_STRIDE + r] = v.z * SCALE;
        Qs[(dq + 3) * QS_STRIDE + r] = v.w * SCALE;
    }

    float acc[8][4];
    float mrow[8], lrow[8];
#pragma unroll
    for (int i = 0; i < 8; i++) {
        mrow[i] = -INFINITY; lrow[i] = 0.f;
#pragma unroll
        for (int j = 0; j < 4; j++) acc[i][j] = 0.f;
    }

    const size_t bj_base = (size_t)b * SEQ_J;
    const float* mbase = &mask[((size_t)(b * SEQ_N) + row0 + tr * 8) * SEQ_J + tc];

    for (int jt = 0; jt < SEQ_J; jt += 64) {
        __syncthreads();   // previous PV finished reading Ps/Vs
        // ---- Load K (transposed) and V (natural) tiles ----
#pragma unroll
        for (int t = 0; t < 4; t++) {
            int e  = tid + t * 256;      // 0..1023
            int jj = e >> 4;
            int dq = (e & 15) * 4;
            const float4* src = reinterpret_cast<const float4*>(
                &kv[(bj_base + jt + jj) * 128]);
            float4 k4 = src[dq >> 2];
            float4 v4 = src[16 + (dq >> 2)];
            Ks[(dq + 0) * KS_STRIDE + jj] = k4.x;
            Ks[(dq + 1) * KS_STRIDE + jj] = k4.y;
            Ks[(dq + 2) * KS_STRIDE + jj] = k4.z;
            Ks[(dq + 3) * KS_STRIDE + jj] = k4.w;
            *reinterpret_cast<float4*>(&Vs[jj * VS_STRIDE + dq]) = v4;
        }
        __syncthreads();

        // ---- S = Q @ K^T (8x4 micro-tile) ----
        float s[8][4];
#pragma unroll
        for (int i = 0; i < 8; i++)
#pragma unroll
            for (int j = 0; j < 4; j++) s[i][j] = 0.f;

#pragma unroll 8
        for (int kk = 0; kk < 64; kk++) {
            float a[8], bb[4];
            float4 a0 = *reinterpret_cast<const float4*>(&Qs[kk * QS_STRIDE + tr * 8]);
            float4 a1 = *reinterpret_cast<const float4*>(&Qs[kk * QS_STRIDE + tr * 8 + 4]);
            a[0] = a0.x; a[1] = a0.y; a[2] = a0.z; a[3] = a0.w;
            a[4] = a1.x; a[5] = a1.y; a[6] = a1.z; a[7] = a1.w;
#pragma unroll
            for (int j = 0; j < 4; j++) bb[j] = Ks[kk * KS_STRIDE + tc + 16 * j];
#pragma unroll
            for (int i = 0; i < 8; i++)
#pragma unroll
                for (int j = 0; j < 4; j++) s[i][j] += a[i] * bb[j];
        }

        // ---- add mask ----
#pragma unroll
        for (int i = 0; i < 8; i++) {
            const float* mr = mbase + (size_t)i * SEQ_J + jt;
#pragma unroll
            for (int j = 0; j < 4; j++) s[i][j] += mr[16 * j];
        }

        // ---- online softmax (row state reduced over the 16 tc lanes) ----
#pragma unroll
        for (int i = 0; i < 8; i++) {
            float mx = fmaxf(fmaxf(s[i][0], s[i][1]), fmaxf(s[i][2], s[i][3]));
#pragma unroll
            for (int off = 8; off > 0; off >>= 1)
                mx = fmaxf(mx, __shfl_xor_sync(0xffffffffu, mx, off));
            float mn   = fmaxf(mrow[i], mx);
            float corr = __expf(mrow[i] - mn);   // exp(-inf)=0 first tile
            mrow[i] = mn;
            float rs = 0.f;
#pragma unroll
            for (int j = 0; j < 4; j++) {
                float p = __expf(s[i][j] - mn);
                rs += p;
                Ps[(tc + 16 * j) * PS_STRIDE + tr * 8 + i] = p;
            }
#pragma unroll
            for (int off = 8; off > 0; off >>= 1)
                rs += __shfl_xor_sync(0xffffffffu, rs, off);
            lrow[i] = lrow[i] * corr + rs;
#pragma unroll
            for (int j = 0; j < 4; j++) acc[i][j] *= corr;
        }
        __syncthreads();   // Ps visible to all

        // ---- O += P @ V ----
#pragma unroll 8
        for (int kk = 0; kk < 64; kk++) {
            float a[8], bb[4];
            float4 a0 = *reinterpret_cast<const float4*>(&Ps[kk * PS_STRIDE + tr * 8]);
            float4 a1 = *reinterpret_cast<const float4*>(&Ps[kk * PS_STRIDE + tr * 8 + 4]);
            a[0] = a0.x; a[1] = a0.y; a[2] = a0.z; a[3] = a0.w;
            a[4] = a1.x; a[5] = a1.y; a[6] = a1.z; a[7] = a1.w;
#pragma unroll
            for (int j = 0; j < 4; j++) bb[j] = Vs[kk * VS_STRIDE + tc + 16 * j];
#pragma unroll
            for (int i = 0; i < 8; i++)
#pragma unroll
                for (int j = 0; j < 4; j++) acc[i][j] += a[i] * bb[j];
        }
    }

    // ---- epilogue: normalize and store ----
#pragma unroll
    for (int i = 0; i < 8; i++) {
        float inv = 1.f / lrow[i];
        float* orow = &o[((size_t)(b * SEQ_N) + row0 + tr * 8 + i) * INNER
                         + h * DHEAD + tc];
#pragma unroll
        for (int j = 0; j < 4; j++) orow[16 * j] = acc[i][j] * inv;
    }
}

// ---------------------------------------------------------------------------
// Launch
// ---------------------------------------------------------------------------
extern "C" void kernel_launch(void* const* d_in, const int* in_sizes, int n_in,
                              void* d_out, int out_size)
{
    const float* x       = (const float*)d_in[0];
    const float* context = (const float*)d_in[1];
    const float* mask    = (const float*)d_in[2];
    const float* ln_w    = (const float*)d_in[3];
    const float* Wq      = (const float*)d_in[4];
    const float* Wkv     = (const float*)d_in[5];
    const float* Wo      = (const float*)d_in[6];
    float* out = (float*)d_out;

    float *xn, *q, *kvb, *ao;
    cudaGetSymbolAddress((void**)&xn,  g_xn);
    cudaGetSymbolAddress((void**)&q,   g_q);
    cudaGetSymbolAddress((void**)&kvb, g_kv);
    cudaGetSymbolAddress((void**)&ao,  g_ao);

    const int attn_smem = SM_TOTAL * sizeof(float);   // 102400 B
    cudaFuncSetAttribute(attn_kernel,
                         cudaFuncAttributeMaxDynamicSharedMemorySize, attn_smem);

    // 1. layernorm
    ln_kernel<<<ROWS_TOTAL, 256>>>(x, ln_w, xn);

    // 2. q = ln(x) @ Wq  (SCALE applied at attention q load)
    sgemm_kernel<<<dim3(INNER / 64, ROWS_TOTAL / 128), 256>>>(
        xn, Wq, q, ROWS_TOTAL, INNER, DIM, 1.0f);

    // 3. kv = context @ Wkv
    sgemm_kernel<<<dim3(128 / 64, ROWS_TOTAL / 128), 256>>>(
        context, Wkv, kvb, ROWS_TOTAL, 128, DIM, 1.0f);

    // 4. attention (register-blocked flash)
    attn_kernel<<<dim3(SEQ_N / 128, HEADS, BATCH), 256, attn_smem>>>(
        q, kvb, mask, ao);

    // 5. out = ao @ Wo
    sgemm_kernel<<<dim3(DIM / 64, ROWS_TOTAL / 128), 256>>>(
        ao, Wo, out, ROWS_TOTAL, DIM, INNER, 1.0f);
}

// round 7
// speedup vs baseline: 3.4360x; 2.2862x over previous
#include <cuda_runtime.h>
#include <cuda_bf16.h>
#include <cstdint>
#include <math.h>

// Problem constants
#define BATCH   4
#define SEQ_N   2048
#define SEQ_J   2048
#define DIM     768
#define HEADS   12
#define DHEAD   64
#define INNER   (HEADS * DHEAD)   // 768
#define SCALE   0.125f            // 64^-0.5

#define ROWS_TOTAL (BATCH * SEQ_N) // 8192

// ---------------------------------------------------------------------------
// Scratch (static device allocations; no cudaMalloc allowed)
// ---------------------------------------------------------------------------
__device__ float g_xn[(size_t)ROWS_TOTAL * DIM];     // layernorm(x)
__device__ float g_q [(size_t)ROWS_TOTAL * INNER];   // q
__device__ float g_kv[(size_t)ROWS_TOTAL * 128];     // [k|v] per context row
__device__ float g_ao[(size_t)ROWS_TOTAL * INNER];   // attn output

// ===========================================================================
// tf32 mma.sync helpers (sm_80+ portable PTX — compiles for plain sm_103)
// ===========================================================================
__device__ __forceinline__ uint32_t f2tf32(float f) {
    uint32_t r;
    asm("cvt.rna.tf32.f32 %0, %1;" : "=r"(r) : "f"(f));
    return r;
}
__device__ __forceinline__ uint4 cvt4(float4 v) {
    uint4 r;
    r.x = f2tf32(v.x); r.y = f2tf32(v.y); r.z = f2tf32(v.z); r.w = f2tf32(v.w);
    return r;
}
// D += A(16x8,row) * B(8x8,col), tf32 in, f32 acc
__device__ __forceinline__ void mma_tf32(float* d, const uint32_t* a,
                                         const uint32_t* b) {
    asm volatile(
        "mma.sync.aligned.m16n8k8.row.col.f32.tf32.tf32.f32 "
        "{%0,%1,%2,%3}, {%4,%5,%6,%7}, {%8,%9}, {%0,%1,%2,%3};"
        : "+f"(d[0]), "+f"(d[1]), "+f"(d[2]), "+f"(d[3])
        : "r"(a[0]), "r"(a[1]), "r"(a[2]), "r"(a[3]), "r"(b[0]), "r"(b[1]));
}
__device__ __forceinline__ uint32_t fbits(float f) { return __float_as_uint(f); }

// ---------------------------------------------------------------------------
// LayerNorm: one block per row of 768
// ---------------------------------------------------------------------------
__global__ void ln_kernel(const float* __restrict__ x,
                          const float* __restrict__ w,
                          float* __restrict__ y)
{
    const int row = blockIdx.x;
    const float* xr = x + (size_t)row * DIM;
    float v[3];
    float s = 0.f, s2 = 0.f;
#pragma unroll
    for (int t = 0; t < 3; t++) {
        int i = threadIdx.x + t * 256;
        float vv = xr[i];
        v[t] = vv;
        s += vv; s2 += vv * vv;
    }
#pragma unroll
    for (int o = 16; o > 0; o >>= 1) {
        s  += __shfl_xor_sync(0xffffffffu, s,  o);
        s2 += __shfl_xor_sync(0xffffffffu, s2, o);
    }
    __shared__ float rs[8], rs2[8];
    int wid = threadIdx.x >> 5, lid = threadIdx.x & 31;
    if (lid == 0) { rs[wid] = s; rs2[wid] = s2; }
    __syncthreads();
    if (wid == 0) {
        s  = (lid < 8) ? rs[lid]  : 0.f;
        s2 = (lid < 8) ? rs2[lid] : 0.f;
#pragma unroll
        for (int o = 4; o > 0; o >>= 1) {
            s  += __shfl_xor_sync(0xffffffffu, s,  o);
            s2 += __shfl_xor_sync(0xffffffffu, s2, o);
        }
        if (lid == 0) { rs[0] = s; rs2[0] = s2; }
    }
    __syncthreads();
    const float mu   = rs[0] * (1.f / DIM);
    const float var  = rs2[0] * (1.f / DIM) - mu * mu;
    const float rstd = rsqrtf(var + 1e-5f);
    float* yr = y + (size_t)row * DIM;
#pragma unroll
    for (int t = 0; t < 3; t++) {
        int i = threadIdx.x + t * 256;
        yr[i] = (v[t] - mu) * rstd * w[i];
    }
}

// ---------------------------------------------------------------------------
// tf32 tensor-core GEMM: C[M,N] = A[M,K] @ B[K,N], fp32 in/out.
// BM=128, BN=128, BK=16, 256 threads = 8 warps (4x2), warp tile 32x64.
// Requires M%128==0, N%128==0, K%16==0.
// ---------------------------------------------------------------------------
#define GA_ST 20     // As stride (floats): (20m+k)%32 distinct per frag
#define GB_ST 136    // Bs stride (floats): (136k+n)%32 = (8k+n) distinct

__global__ __launch_bounds__(256)
void gemm_tc_kernel(const float* __restrict__ A, const float* __restrict__ B,
                    float* __restrict__ C, int M, int N, int K)
{
    __shared__ float As[128 * GA_ST];
    __shared__ float Bs[16 * GB_ST];

    const int tid  = threadIdx.x;
    const int wid  = tid >> 5;
    const int lane = tid & 31;
    const int gr   = lane >> 2;    // 0..7
    const int gq   = lane & 3;     // 0..3
    const int wm   = (wid & 3) * 32;   // warp m offset
    const int wn   = (wid >> 2) * 64;  // warp n offset
    const int m0   = blockIdx.y * 128;
    const int n0   = blockIdx.x * 128;

    float acc[2][8][4];
#pragma unroll
    for (int ms = 0; ms < 2; ms++)
#pragma unroll
        for (int nt = 0; nt < 8; nt++)
#pragma unroll
            for (int i = 0; i < 4; i++) acc[ms][nt][i] = 0.f;

    // prefetch registers
    uint4 pa[2], pb[2];
    // indices for staging (constant across tiles)
    const int am[2] = { (tid + 0) >> 2, (tid + 256) >> 2 };
    const int ak[2] = { ((tid + 0) & 3) * 4, ((tid + 256) & 3) * 4 };
    const int br[2] = { (tid + 0) >> 5, (tid + 256) >> 5 };
    const int bc[2] = { ((tid + 0) & 31) * 4, ((tid + 256) & 31) * 4 };

    // prologue load (k0 = 0)
#pragma unroll
    for (int t = 0; t < 2; t++) {
        pa[t] = cvt4(*reinterpret_cast<const float4*>(
            &A[(size_t)(m0 + am[t]) * K + ak[t]]));
        pb[t] = cvt4(*reinterpret_cast<const float4*>(
            &B[(size_t)br[t] * N + n0 + bc[t]]));
    }

    for (int kt = 0; kt < K; kt += 16) {
        // store staged tile
#pragma unroll
        for (int t = 0; t < 2; t++) {
            *reinterpret_cast<uint4*>(&As[am[t] * GA_ST + ak[t]]) = pa[t];
            *reinterpret_cast<uint4*>(&Bs[br[t] * GB_ST + bc[t]]) = pb[t];
        }
        __syncthreads();

        // prefetch next tile
        if (kt + 16 < K) {
#pragma unroll
            for (int t = 0; t < 2; t++) {
                pa[t] = cvt4(*reinterpret_cast<const float4*>(
                    &A[(size_t)(m0 + am[t]) * K + kt + 16 + ak[t]]));
                pb[t] = cvt4(*reinterpret_cast<const float4*>(
                    &B[(size_t)(kt + 16 + br[t]) * N + n0 + bc[t]]));
            }
        }

        // compute 2 k-steps of 8
#pragma unroll
        for (int ks = 0; ks < 2; ks++) {
            const int k8 = ks * 8;
            uint32_t af[2][4];
#pragma unroll
            for (int ms = 0; ms < 2; ms++) {
                const int mb = wm + ms * 16;
                af[ms][0] = fbits(As[(mb + gr    ) * GA_ST + k8 + gq]);
                af[ms][1] = fbits(As[(mb + gr + 8) * GA_ST + k8 + gq]);
                af[ms][2] = fbits(As[(mb + gr    ) * GA_ST + k8 + 4 + gq]);
                af[ms][3] = fbits(As[(mb + gr + 8) * GA_ST + k8 + 4 + gq]);
            }
#pragma unroll
            for (int nt = 0; nt < 8; nt++) {
                uint32_t bf[2];
                bf[0] = fbits(Bs[(k8 + gq    ) * GB_ST + wn + nt * 8 + gr]);
                bf[1] = fbits(Bs[(k8 + 4 + gq) * GB_ST + wn + nt * 8 + gr]);
#pragma unroll
                for (int ms = 0; ms < 2; ms++)
                    mma_tf32(acc[ms][nt], af[ms], bf);
            }
        }
        __syncthreads();
    }

    // epilogue
#pragma unroll
    for (int ms = 0; ms < 2; ms++) {
        const int mrow0 = m0 + wm + ms * 16 + gr;
#pragma unroll
        for (int nt = 0; nt < 8; nt++) {
            const int col = n0 + wn + nt * 8 + 2 * gq;
            *reinterpret_cast<float2*>(&C[(size_t)mrow0 * N + col]) =
                make_float2(acc[ms][nt][0], acc[ms][nt][1]);
            *reinterpret_cast<float2*>(&C[(size_t)(mrow0 + 8) * N + col]) =
                make_float2(acc[ms][nt][2], acc[ms][nt][3]);
        }
    }
}

// ---------------------------------------------------------------------------
// tf32 mma.sync flash attention.
// CTA = 128 q-rows of one (b,h), 256 threads = 8 warps; warp owns 16 rows.
// j-tile = 64. Q fragments register-resident (pre-scaled tf32).
// Unstabilized softmax (scores bounded, mask finite): shift-free == reference.
// Smem (dynamic 70656 B): Ks[64][68], Vs[64][72], Ps[128][68] (all tf32-f32).
// ---------------------------------------------------------------------------
#define KS_ST 68
#define VS_ST 72
#define PS_ST 68
#define SM_KS 0
#define SM_VS (64 * KS_ST)                 // 4352
#define SM_PS (SM_VS + 64 * VS_ST)         // 8960
#define ATTN_SM_FLOATS (SM_PS + 128 * PS_ST)  // 17664 floats = 70656 B

__global__ __launch_bounds__(256, 1)
void attn_mma_kernel(const float* __restrict__ q, const float* __restrict__ kv,
                     const float* __restrict__ mask, float* __restrict__ o)
{
    extern __shared__ float sm[];
    float* Ks = sm + SM_KS;
    float* Vs = sm + SM_VS;
    float* Ps = sm + SM_PS;

    const int tid  = threadIdx.x;
    const int wid  = tid >> 5;
    const int lane = tid & 31;
    const int gr   = lane >> 2;
    const int gq   = lane & 3;
    const int h    = blockIdx.y;
    const int b    = blockIdx.z;
    const int row0 = blockIdx.x * 128;
    const int qrb  = row0 + wid * 16;     // this warp's first q row (in-seq)

    // ---- Q fragments: 8 k-steps x 4 regs, pre-scaled, tf32 ----
    uint32_t qf[8][4];
    {
        const float* qb = q + ((size_t)(b * SEQ_N) + qrb) * INNER + h * DHEAD;
#pragma unroll
        for (int c = 0; c < 8; c++) {
            qf[c][0] = f2tf32(qb[(size_t)(gr    ) * INNER + c * 8 + gq    ] * SCALE);
            qf[c][1] = f2tf32(qb[(size_t)(gr + 8) * INNER + c * 8 + gq    ] * SCALE);
            qf[c][2] = f2tf32(qb[(size_t)(gr    ) * INNER + c * 8 + 4 + gq] * SCALE);
            qf[c][3] = f2tf32(qb[(size_t)(gr + 8) * INNER + c * 8 + 4 + gq] * SCALE);
        }
    }

    float oacc[8][4];
#pragma unroll
    for (int nt = 0; nt < 8; nt++)
#pragma unroll
        for (int i = 0; i < 4; i++) oacc[nt][i] = 0.f;
    float l0 = 0.f, l1 = 0.f;

    const float* m0p = mask + ((size_t)(b * SEQ_N) + qrb + gr) * SEQ_J;
    const float* m1p = m0p + (size_t)8 * SEQ_J;
    const size_t kvbase = (size_t)b * SEQ_J;

    const int prow0 = (wid * 16 + gr) * PS_ST;       // own-warp P rows
    const int prow1 = (wid * 16 + 8 + gr) * PS_ST;

    for (int jt = 0; jt < SEQ_J; jt += 64) {
        __syncthreads();   // all warps done with Ks/Vs/Ps of previous tile

        // ---- prefetch mask chunks (lane's 16 cols x 2 rows) ----
        float2 mk0[8], mk1[8];
#pragma unroll
        for (int nt = 0; nt < 8; nt++) {
            const int col = jt + nt * 8 + 2 * gq;
            mk0[nt] = *reinterpret_cast<const float2*>(&m0p[col]);
            mk1[nt] = *reinterpret_cast<const float2*>(&m1p[col]);
        }

        // ---- stage K,V tiles (tf32) ----
#pragma unroll
        for (int t = 0; t < 8; t++) {
            const int e  = tid + t * 256;    // 0..2047 float4 slots
            const int jj = e >> 5;
            const int c4 = e & 31;
            float4 v = *reinterpret_cast<const float4*>(
                &kv[(kvbase + jt + jj) * 128 + c4 * 4]);
            uint4 w = cvt4(v);
            if (c4 < 16)
                *reinterpret_cast<uint4*>(&Ks[jj * KS_ST + c4 * 4]) = w;
            else
                *reinterpret_cast<uint4*>(&Vs[jj * VS_ST + (c4 - 16) * 4]) = w;
        }
        __syncthreads();

        // ---- S = Q @ K^T ----
        float sacc[8][4];
#pragma unroll
        for (int nt = 0; nt < 8; nt++)
#pragma unroll
            for (int i = 0; i < 4; i++) sacc[nt][i] = 0.f;

#pragma unroll
        for (int c = 0; c < 8; c++) {
#pragma unroll
            for (int nt = 0; nt < 8; nt++) {
                uint32_t bf[2];
                bf[0] = fbits(Ks[(nt * 8 + gr) * KS_ST + c * 8 + gq]);
                bf[1] = fbits(Ks[(nt * 8 + gr) * KS_ST + c * 8 + 4 + gq]);
                mma_tf32(sacc[nt], qf[c], bf);
            }
        }

        // ---- softmax (unstabilized) + P -> smem (own rows only) ----
#pragma unroll
        for (int nt = 0; nt < 8; nt++) {
            float p00 = __expf(sacc[nt][0] + mk0[nt].x);
            float p01 = __expf(sacc[nt][1] + mk0[nt].y);
            float p10 = __expf(sacc[nt][2] + mk1[nt].x);
            float p11 = __expf(sacc[nt][3] + mk1[nt].y);
            l0 += p00 + p01;
            l1 += p10 + p11;
            const int cb = nt * 8 + 2 * gq;
            uint2 w0 = make_uint2(f2tf32(p00), f2tf32(p01));
            uint2 w1 = make_uint2(f2tf32(p10), f2tf32(p11));
            *reinterpret_cast<uint2*>(&Ps[prow0 + cb]) = w0;
            *reinterpret_cast<uint2*>(&Ps[prow1 + cb]) = w1;
        }
        __syncwarp();   // own-warp STS -> LDS visibility

        // ---- O += P @ V ----
#pragma unroll
        for (int c = 0; c < 8; c++) {
            uint32_t af[4];
            af[0] = fbits(Ps[prow0 + c * 8 + gq]);
            af[1] = fbits(Ps[prow1 + c * 8 + gq]);
            af[2] = fbits(Ps[prow0 + c * 8 + 4 + gq]);
            af[3] = fbits(Ps[prow1 + c * 8 + 4 + gq]);
#pragma unroll
            for (int nt = 0; nt < 8; nt++) {
                uint32_t bf[2];
                bf[0] = fbits(Vs[(c * 8 + gq    ) * VS_ST + nt * 8 + gr]);
                bf[1] = fbits(Vs[(c * 8 + 4 + gq) * VS_ST + nt * 8 + gr]);
                mma_tf32(oacc[nt], af, bf);
            }
        }
    }

    // ---- finalize: reduce l over quad lanes, normalize, store ----
    l0 += __shfl_xor_sync(0xffffffffu, l0, 1);
    l0 += __shfl_xor_sync(0xffffffffu, l0, 2);
    l1 += __shfl_xor_sync(0xffffffffu, l1, 1);
    l1 += __shfl_xor_sync(0xffffffffu, l1, 2);
    const float inv0 = 1.f / l0;
    const float inv1 = 1.f / l1;

    float* ob = o + ((size_t)(b * SEQ_N) + qrb) * INNER + h * DHEAD;
#pragma unroll
    for (int nt = 0; nt < 8; nt++) {
        const int cb = nt * 8 + 2 * gq;
        *reinterpret_cast<float2*>(&ob[(size_t)gr * INNER + cb]) =
            make_float2(oacc[nt][0] * inv0, oacc[nt][1] * inv0);
        *reinterpret_cast<float2*>(&ob[(size_t)(gr + 8) * INNER + cb]) =
            make_float2(oacc[nt][2] * inv1, oacc[nt][3] * inv1);
    }
}

// ---------------------------------------------------------------------------
// Launch
// ---------------------------------------------------------------------------
extern "C" void kernel_launch(void* const* d_in, const int* in_sizes, int n_in,
                              void* d_out, int out_size)
{
    const float* x       = (const float*)d_in[0];
    const float* context = (const float*)d_in[1];
    const float* mask    = (const float*)d_in[2];
    const float* ln_w    = (const float*)d_in[3];
    const float* Wq      = (const float*)d_in[4];
    const float* Wkv     = (const float*)d_in[5];
    const float* Wo      = (const float*)d_in[6];
    float* out = (float*)d_out;

    float *xn, *q, *kvb, *ao;
    cudaGetSymbolAddress((void**)&xn,  g_xn);
    cudaGetSymbolAddress((void**)&q,   g_q);
    cudaGetSymbolAddress((void**)&kvb, g_kv);
    cudaGetSymbolAddress((void**)&ao,  g_ao);

    const int attn_smem = ATTN_SM_FLOATS * sizeof(float);   // 70656 B
    cudaFuncSetAttribute(attn_mma_kernel,
                         cudaFuncAttributeMaxDynamicSharedMemorySize, attn_smem);

    // 1. layernorm
    ln_kernel<<<ROWS_TOTAL, 256>>>(x, ln_w, xn);

    // 2. q = ln(x) @ Wq   (tf32 tensor GEMM; SCALE applied at attention q load)
    gemm_tc_kernel<<<dim3(INNER / 128, ROWS_TOTAL / 128), 256>>>(
        xn, Wq, q, ROWS_TOTAL, INNER, DIM);

    // 3. kv = context @ Wkv
    gemm_tc_kernel<<<dim3(128 / 128, ROWS_TOTAL / 128), 256>>>(
        context, Wkv, kvb, ROWS_TOTAL, 128, DIM);

    // 4. attention (tf32 mma.sync flash)
    attn_mma_kernel<<<dim3(SEQ_N / 128, HEADS, BATCH), 256, attn_smem>>>(
        q, kvb, mask, ao);

    // 5. out = ao @ Wo
    gemm_tc_kernel<<<dim3(DIM / 128, ROWS_TOTAL / 128), 256>>>(
        ao, Wo, out, ROWS_TOTAL, DIM, INNER);
}

// round 8
// speedup vs baseline: 3.5738x; 1.0401x over previous
#include <cuda_runtime.h>
#include <cuda_bf16.h>
#include <cstdint>
#include <math.h>

// Problem constants
#define BATCH   4
#define SEQ_N   2048
#define SEQ_J   2048
#define DIM     768
#define HEADS   12
#define DHEAD   64
#define INNER   (HEADS * DHEAD)   // 768
#define SCALE   0.125f            // 64^-0.5

#define ROWS_TOTAL (BATCH * SEQ_N) // 8192

// ---------------------------------------------------------------------------
// Scratch (static device allocations; no cudaMalloc allowed)
// ---------------------------------------------------------------------------
__device__ float g_xn[(size_t)ROWS_TOTAL * DIM];     // layernorm(x)
__device__ float g_q [(size_t)ROWS_TOTAL * INNER];   // q
__device__ float g_kv[(size_t)ROWS_TOTAL * 128];     // [k|v] per context row
__device__ float g_ao[(size_t)ROWS_TOTAL * INNER];   // attn output

// ===========================================================================
// tf32 mma.sync helpers (sm_80+ portable PTX — compiles for plain sm_103)
// ===========================================================================
__device__ __forceinline__ uint32_t f2tf32(float f) {
    uint32_t r;
    asm("cvt.rna.tf32.f32 %0, %1;" : "=r"(r) : "f"(f));
    return r;
}
__device__ __forceinline__ uint4 cvt4(float4 v) {
    uint4 r;
    r.x = f2tf32(v.x); r.y = f2tf32(v.y); r.z = f2tf32(v.z); r.w = f2tf32(v.w);
    return r;
}
// D += A(16x8,row) * B(8x8,col), tf32 in, f32 acc
__device__ __forceinline__ void mma_tf32(float* d, const uint32_t* a,
                                         const uint32_t* b) {
    asm volatile(
        "mma.sync.aligned.m16n8k8.row.col.f32.tf32.tf32.f32 "
        "{%0,%1,%2,%3}, {%4,%5,%6,%7}, {%8,%9}, {%0,%1,%2,%3};"
        : "+f"(d[0]), "+f"(d[1]), "+f"(d[2]), "+f"(d[3])
        : "r"(a[0]), "r"(a[1]), "r"(a[2]), "r"(a[3]), "r"(b[0]), "r"(b[1]));
}
__device__ __forceinline__ uint32_t fbits(float f) { return __float_as_uint(f); }
__device__ __forceinline__ uint32_t smem_to_u32(const void* p) {
    uint32_t a;
    asm("{ .reg .u64 t; cvta.to.shared.u64 t, %1; cvt.u32.u64 %0, t; }"
        : "=r"(a) : "l"(p));
    return a;
}
#define CP_ASYNC16(dst_u32, src_ptr) \
    asm volatile("cp.async.cg.shared.global [%0], [%1], 16;" \
        :: "r"(dst_u32), "l"(src_ptr))
#define CP_COMMIT() asm volatile("cp.async.commit_group;" ::: "memory")
#define CP_WAIT_ALL() asm volatile("cp.async.wait_group 0;" ::: "memory")

// ---------------------------------------------------------------------------
// LayerNorm: one block per row of 768
// ---------------------------------------------------------------------------
__global__ void ln_kernel(const float* __restrict__ x,
                          const float* __restrict__ w,
                          float* __restrict__ y)
{
    const int row = blockIdx.x;
    const float* xr = x + (size_t)row * DIM;
    float v[3];
    float s = 0.f, s2 = 0.f;
#pragma unroll
    for (int t = 0; t < 3; t++) {
        int i = threadIdx.x + t * 256;
        float vv = xr[i];
        v[t] = vv;
        s += vv; s2 += vv * vv;
    }
#pragma unroll
    for (int o = 16; o > 0; o >>= 1) {
        s  += __shfl_xor_sync(0xffffffffu, s,  o);
        s2 += __shfl_xor_sync(0xffffffffu, s2, o);
    }
    __shared__ float rs[8], rs2[8];
    int wid = threadIdx.x >> 5, lid = threadIdx.x & 31;
    if (lid == 0) { rs[wid] = s; rs2[wid] = s2; }
    __syncthreads();
    if (wid == 0) {
        s  = (lid < 8) ? rs[lid]  : 0.f;
        s2 = (lid < 8) ? rs2[lid] : 0.f;
#pragma unroll
        for (int o = 4; o > 0; o >>= 1) {
            s  += __shfl_xor_sync(0xffffffffu, s,  o);
            s2 += __shfl_xor_sync(0xffffffffu, s2, o);
        }
        if (lid == 0) { rs[0] = s; rs2[0] = s2; }
    }
    __syncthreads();
    const float mu   = rs[0] * (1.f / DIM);
    const float var  = rs2[0] * (1.f / DIM) - mu * mu;
    const float rstd = rsqrtf(var + 1e-5f);
    float* yr = y + (size_t)row * DIM;
#pragma unroll
    for (int t = 0; t < 3; t++) {
        int i = threadIdx.x + t * 256;
        yr[i] = (v[t] - mu) * rstd * w[i];
    }
}

// ---------------------------------------------------------------------------
// tf32 tensor-core GEMM: C[M,N] = A[M,K] @ B[K,N], fp32 in/out.
// BM=128, BN=128, BK=16, 256 threads = 8 warps (4x2), warp tile 32x64.
// (unchanged from round 7)
// ---------------------------------------------------------------------------
#define GA_ST 20
#define GB_ST 136

__global__ __launch_bounds__(256)
void gemm_tc_kernel(const float* __restrict__ A, const float* __restrict__ B,
                    float* __restrict__ C, int M, int N, int K)
{
    __shared__ float As[128 * GA_ST];
    __shared__ float Bs[16 * GB_ST];

    const int tid  = threadIdx.x;
    const int wid  = tid >> 5;
    const int lane = tid & 31;
    const int gr   = lane >> 2;
    const int gq   = lane & 3;
    const int wm   = (wid & 3) * 32;
    const int wn   = (wid >> 2) * 64;
    const int m0   = blockIdx.y * 128;
    const int n0   = blockIdx.x * 128;

    float acc[2][8][4];
#pragma unroll
    for (int ms = 0; ms < 2; ms++)
#pragma unroll
        for (int nt = 0; nt < 8; nt++)
#pragma unroll
            for (int i = 0; i < 4; i++) acc[ms][nt][i] = 0.f;

    uint4 pa[2], pb[2];
    const int am[2] = { (tid + 0) >> 2, (tid + 256) >> 2 };
    const int ak[2] = { ((tid + 0) & 3) * 4, ((tid + 256) & 3) * 4 };
    const int br[2] = { (tid + 0) >> 5, (tid + 256) >> 5 };
    const int bc[2] = { ((tid + 0) & 31) * 4, ((tid + 256) & 31) * 4 };

#pragma unroll
    for (int t = 0; t < 2; t++) {
        pa[t] = cvt4(*reinterpret_cast<const float4*>(
            &A[(size_t)(m0 + am[t]) * K + ak[t]]));
        pb[t] = cvt4(*reinterpret_cast<const float4*>(
            &B[(size_t)br[t] * N + n0 + bc[t]]));
    }

    for (int kt = 0; kt < K; kt += 16) {
#pragma unroll
        for (int t = 0; t < 2; t++) {
            *reinterpret_cast<uint4*>(&As[am[t] * GA_ST + ak[t]]) = pa[t];
            *reinterpret_cast<uint4*>(&Bs[br[t] * GB_ST + bc[t]]) = pb[t];
        }
        __syncthreads();

        if (kt + 16 < K) {
#pragma unroll
            for (int t = 0; t < 2; t++) {
                pa[t] = cvt4(*reinterpret_cast<const float4*>(
                    &A[(size_t)(m0 + am[t]) * K + kt + 16 + ak[t]]));
                pb[t] = cvt4(*reinterpret_cast<const float4*>(
                    &B[(size_t)(kt + 16 + br[t]) * N + n0 + bc[t]]));
            }
        }

#pragma unroll
        for (int ks = 0; ks < 2; ks++) {
            const int k8 = ks * 8;
            uint32_t af[2][4];
#pragma unroll
            for (int ms = 0; ms < 2; ms++) {
                const int mb = wm + ms * 16;
                af[ms][0] = fbits(As[(mb + gr    ) * GA_ST + k8 + gq]);
                af[ms][1] = fbits(As[(mb + gr + 8) * GA_ST + k8 + gq]);
                af[ms][2] = fbits(As[(mb + gr    ) * GA_ST + k8 + 4 + gq]);
                af[ms][3] = fbits(As[(mb + gr + 8) * GA_ST + k8 + 4 + gq]);
            }
#pragma unroll
            for (int nt = 0; nt < 8; nt++) {
                uint32_t bf[2];
                bf[0] = fbits(Bs[(k8 + gq    ) * GB_ST + wn + nt * 8 + gr]);
                bf[1] = fbits(Bs[(k8 + 4 + gq) * GB_ST + wn + nt * 8 + gr]);
#pragma unroll
                for (int ms = 0; ms < 2; ms++)
                    mma_tf32(acc[ms][nt], af[ms], bf);
            }
        }
        __syncthreads();
    }

#pragma unroll
    for (int ms = 0; ms < 2; ms++) {
        const int mrow0 = m0 + wm + ms * 16 + gr;
#pragma unroll
        for (int nt = 0; nt < 8; nt++) {
            const int col = n0 + wn + nt * 8 + 2 * gq;
            *reinterpret_cast<float2*>(&C[(size_t)mrow0 * N + col]) =
                make_float2(acc[ms][nt][0], acc[ms][nt][1]);
            *reinterpret_cast<float2*>(&C[(size_t)(mrow0 + 8) * N + col]) =
                make_float2(acc[ms][nt][2], acc[ms][nt][3]);
        }
    }
}

// ---------------------------------------------------------------------------
// tf32 mma.sync flash attention with cp.async double-buffered K/V staging.
// CTA = 128 q-rows of one (b,h), 256 threads = 8 warps; warp owns 16 rows.
// j-tile = 64. K/V staged raw fp32 via cp.async; tf32 cvt at fragment load
// (bit-identical numerics to cvt-at-staging). Mask regs ping-pong one tile
// ahead. Unstabilized softmax (scores bounded, mask finite).
// Smem (floats): K0[64*68] V0[64*72] K1[64*68] V1[64*72] Ps[128*68]
// ---------------------------------------------------------------------------
#define KS_ST 68
#define VS_ST 72
#define PS_ST 68
#define SM_K0 0
#define SM_V0 (SM_K0 + 64 * KS_ST)     // 4352
#define SM_K1 (SM_V0 + 64 * VS_ST)     // 8960
#define SM_V1 (SM_K1 + 64 * KS_ST)     // 13312
#define SM_PS (SM_V1 + 64 * VS_ST)     // 17920
#define ATTN_SM_FLOATS (SM_PS + 128 * PS_ST)  // 26624 floats = 106496 B
#define NTILES (SEQ_J / 64)            // 32

__device__ __forceinline__ void stage_kv_async(uint32_t smem_u32, int buf,
                                               const float* kv_tile, int tid)
{
    const uint32_t kbase = smem_u32 + (buf ? SM_K1 : SM_K0) * 4;
    const uint32_t vbase = smem_u32 + (buf ? SM_V1 : SM_V0) * 4;
#pragma unroll
    for (int t = 0; t < 8; t++) {
        const int e  = tid + t * 256;    // 0..2047 float4 chunks
        const int jj = e >> 5;
        const int c4 = e & 31;
        const float* src = kv_tile + (size_t)jj * 128 + c4 * 4;
        const uint32_t dst = (c4 < 16)
            ? kbase + (uint32_t)(jj * KS_ST + c4 * 4) * 4
            : vbase + (uint32_t)(jj * VS_ST + (c4 - 16) * 4) * 4;
        CP_ASYNC16(dst, src);
    }
    CP_COMMIT();
}

__global__ __launch_bounds__(256, 1)
void attn_mma_kernel(const float* __restrict__ q, const float* __restrict__ kv,
                     const float* __restrict__ mask, float* __restrict__ o)
{
    extern __shared__ float sm[];
    const uint32_t smem_u32 = smem_to_u32(sm);
    float* Ps = sm + SM_PS;

    const int tid  = threadIdx.x;
    const int wid  = tid >> 5;
    const int lane = tid & 31;
    const int gr   = lane >> 2;
    const int gq   = lane & 3;
    const int h    = blockIdx.y;
    const int b    = blockIdx.z;
    const int row0 = blockIdx.x * 128;
    const int qrb  = row0 + wid * 16;

    // ---- Q fragments: 8 k-steps x 4 regs, pre-scaled, tf32 ----
    uint32_t qf[8][4];
    {
        const float* qb = q + ((size_t)(b * SEQ_N) + qrb) * INNER + h * DHEAD;
#pragma unroll
        for (int c = 0; c < 8; c++) {
            qf[c][0] = f2tf32(qb[(size_t)(gr    ) * INNER + c * 8 + gq    ] * SCALE);
            qf[c][1] = f2tf32(qb[(size_t)(gr + 8) * INNER + c * 8 + gq    ] * SCALE);
            qf[c][2] = f2tf32(qb[(size_t)(gr    ) * INNER + c * 8 + 4 + gq] * SCALE);
            qf[c][3] = f2tf32(qb[(size_t)(gr + 8) * INNER + c * 8 + 4 + gq] * SCALE);
        }
    }

    float oacc[8][4];
#pragma unroll
    for (int nt = 0; nt < 8; nt++)
#pragma unroll
        for (int i = 0; i < 4; i++) oacc[nt][i] = 0.f;
    float l0 = 0.f, l1 = 0.f;

    const float* m0p = mask + ((size_t)(b * SEQ_N) + qrb + gr) * SEQ_J;
    const float* m1p = m0p + (size_t)8 * SEQ_J;
    const float* kv_base = kv + (size_t)b * SEQ_J * 128;

    const int prow0 = (wid * 16 + gr) * PS_ST;
    const int prow1 = (wid * 16 + 8 + gr) * PS_ST;

    // ---- prologue: stage tile 0, load mask tile 0 ----
    stage_kv_async(smem_u32, 0, kv_base, tid);
    float2 mk0[2][8], mk1[2][8];
#pragma unroll
    for (int nt = 0; nt < 8; nt++) {
        const int col = nt * 8 + 2 * gq;
        mk0[0][nt] = *reinterpret_cast<const float2*>(&m0p[col]);
        mk1[0][nt] = *reinterpret_cast<const float2*>(&m1p[col]);
    }

#pragma unroll 2
    for (int t = 0; t < NTILES; t++) {
        const int cur = t & 1;
        const int nxt = cur ^ 1;

        CP_WAIT_ALL();          // tile t landed (only group outstanding)
        __syncthreads();        // visible to all; all warps done with buf t-1

        // issue copy + mask prefetch for tile t+1 (overlaps tile-t compute)
        if (t + 1 < NTILES) {
            stage_kv_async(smem_u32, nxt, kv_base + (size_t)(t + 1) * 64 * 128, tid);
            const int colb = (t + 1) * 64 + 2 * gq;
#pragma unroll
            for (int nt = 0; nt < 8; nt++) {
                mk0[nxt][nt] = *reinterpret_cast<const float2*>(&m0p[colb + nt * 8]);
                mk1[nxt][nt] = *reinterpret_cast<const float2*>(&m1p[colb + nt * 8]);
            }
        }

        const float* Kf = sm + (cur ? SM_K1 : SM_K0);
        const float* Vf = sm + (cur ? SM_V1 : SM_V0);

        // ---- S = Q @ K^T ----
        float sacc[8][4];
#pragma unroll
        for (int nt = 0; nt < 8; nt++)
#pragma unroll
            for (int i = 0; i < 4; i++) sacc[nt][i] = 0.f;

#pragma unroll
        for (int c = 0; c < 8; c++) {
#pragma unroll
            for (int nt = 0; nt < 8; nt++) {
                uint32_t bf[2];
                bf[0] = f2tf32(Kf[(nt * 8 + gr) * KS_ST + c * 8 + gq]);
                bf[1] = f2tf32(Kf[(nt * 8 + gr) * KS_ST + c * 8 + 4 + gq]);
                mma_tf32(sacc[nt], qf[c], bf);
            }
        }

        // ---- softmax (unstabilized) + P -> smem (own rows only) ----
#pragma unroll
        for (int nt = 0; nt < 8; nt++) {
            float p00 = __expf(sacc[nt][0] + mk0[cur][nt].x);
            float p01 = __expf(sacc[nt][1] + mk0[cur][nt].y);
            float p10 = __expf(sacc[nt][2] + mk1[cur][nt].x);
            float p11 = __expf(sacc[nt][3] + mk1[cur][nt].y);
            l0 += p00 + p01;
            l1 += p10 + p11;
            const int cb = nt * 8 + 2 * gq;
            *reinterpret_cast<uint2*>(&Ps[prow0 + cb]) =
                make_uint2(f2tf32(p00), f2tf32(p01));
            *reinterpret_cast<uint2*>(&Ps[prow1 + cb]) =
                make_uint2(f2tf32(p10), f2tf32(p11));
        }
        __syncwarp();

        // ---- O += P @ V ----
#pragma unroll
        for (int c = 0; c < 8; c++) {
            uint32_t af[4];
            af[0] = fbits(Ps[prow0 + c * 8 + gq]);
            af[1] = fbits(Ps[prow1 + c * 8 + gq]);
            af[2] = fbits(Ps[prow0 + c * 8 + 4 + gq]);
            af[3] = fbits(Ps[prow1 + c * 8 + 4 + gq]);
#pragma unroll
            for (int nt = 0; nt < 8; nt++) {
                uint32_t bf[2];
                bf[0] = f2tf32(Vf[(c * 8 + gq    ) * VS_ST + nt * 8 + gr]);
                bf[1] = f2tf32(Vf[(c * 8 + 4 + gq) * VS_ST + nt * 8 + gr]);
                mma_tf32(oacc[nt], af, bf);
            }
        }
    }

    // ---- finalize: reduce l over quad lanes, normalize, store ----
    l0 += __shfl_xor_sync(0xffffffffu, l0, 1);
    l0 += __shfl_xor_sync(0xffffffffu, l0, 2);
    l1 += __shfl_xor_sync(0xffffffffu, l1, 1);
    l1 += __shfl_xor_sync(0xffffffffu, l1, 2);
    const float inv0 = 1.f / l0;
    const float inv1 = 1.f / l1;

    float* ob = o + ((size_t)(b * SEQ_N) + qrb) * INNER + h * DHEAD;
#pragma unroll
    for (int nt = 0; nt < 8; nt++) {
        const int cb = nt * 8 + 2 * gq;
        *reinterpret_cast<float2*>(&ob[(size_t)gr * INNER + cb]) =
            make_float2(oacc[nt][0] * inv0, oacc[nt][1] * inv0);
        *reinterpret_cast<float2*>(&ob[(size_t)(gr + 8) * INNER + cb]) =
            make_float2(oacc[nt][2] * inv1, oacc[nt][3] * inv1);
    }
}

// ---------------------------------------------------------------------------
// Launch
// ---------------------------------------------------------------------------
extern "C" void kernel_launch(void* const* d_in, const int* in_sizes, int n_in,
                              void* d_out, int out_size)
{
    const float* x       = (const float*)d_in[0];
    const float* context = (const float*)d_in[1];
    const float* mask    = (const float*)d_in[2];
    const float* ln_w    = (const float*)d_in[3];
    const float* Wq      = (const float*)d_in[4];
    const float* Wkv     = (const float*)d_in[5];
    const float* Wo      = (const float*)d_in[6];
    float* out = (float*)d_out;

    float *xn, *q, *kvb, *ao;
    cudaGetSymbolAddress((void**)&xn,  g_xn);
    cudaGetSymbolAddress((void**)&q,   g_q);
    cudaGetSymbolAddress((void**)&kvb, g_kv);
    cudaGetSymbolAddress((void**)&ao,  g_ao);

    const int attn_smem = ATTN_SM_FLOATS * sizeof(float);   // 106496 B
    cudaFuncSetAttribute(attn_mma_kernel,
                         cudaFuncAttributeMaxDynamicSharedMemorySize, attn_smem);

    // 1. layernorm
    ln_kernel<<<ROWS_TOTAL, 256>>>(x, ln_w, xn);

    // 2. q = ln(x) @ Wq
    gemm_tc_kernel<<<dim3(INNER / 128, ROWS_TOTAL / 128), 256>>>(
        xn, Wq, q, ROWS_TOTAL, INNER, DIM);

    // 3. kv = context @ Wkv
    gemm_tc_kernel<<<dim3(128 / 128, ROWS_TOTAL / 128), 256>>>(
        context, Wkv, kvb, ROWS_TOTAL, 128, DIM);

    // 4. attention (tf32 mma.sync flash, cp.async pipelined)
    attn_mma_kernel<<<dim3(SEQ_N / 128, HEADS, BATCH), 256, attn_smem>>>(
        q, kvb, mask, ao);

    // 5. out = ao @ Wo
    gemm_tc_kernel<<<dim3(DIM / 128, ROWS_TOTAL / 128), 256>>>(
        ao, Wo, out, ROWS_TOTAL, DIM, INNER);
}

// round 9
// speedup vs baseline: 3.6300x; 1.0157x over previous
#include <cuda_runtime.h>
#include <cuda_bf16.h>
#include <cstdint>
#include <math.h>

// Problem constants
#define BATCH   4
#define SEQ_N   2048
#define SEQ_J   2048
#define DIM     768
#define HEADS   12
#define DHEAD   64
#define INNER   (HEADS * DHEAD)   // 768
#define SCALE   0.125f            // 64^-0.5

#define ROWS_TOTAL (BATCH * SEQ_N) // 8192

// ---------------------------------------------------------------------------
// Scratch (static device allocations; no cudaMalloc allowed)
// ---------------------------------------------------------------------------
__device__ float g_xn[(size_t)ROWS_TOTAL * DIM];     // layernorm(x)
__device__ float g_q [(size_t)ROWS_TOTAL * INNER];   // q
__device__ float g_kv[(size_t)ROWS_TOTAL * 128];     // [k|v] per context row
__device__ float g_ao[(size_t)ROWS_TOTAL * INNER];   // attn output

// ===========================================================================
// tf32 mma.sync helpers (sm_80+ portable PTX — compiles for plain sm_103)
// ===========================================================================
__device__ __forceinline__ uint32_t f2tf32(float f) {
    uint32_t r;
    asm("cvt.rna.tf32.f32 %0, %1;" : "=r"(r) : "f"(f));
    return r;
}
__device__ __forceinline__ uint4 cvt4(float4 v) {
    uint4 r;
    r.x = f2tf32(v.x); r.y = f2tf32(v.y); r.z = f2tf32(v.z); r.w = f2tf32(v.w);
    return r;
}
// D += A(16x8,row) * B(8x8,col), tf32 in, f32 acc
__device__ __forceinline__ void mma_tf32(float* d, const uint32_t* a,
                                         const uint32_t* b) {
    asm volatile(
        "mma.sync.aligned.m16n8k8.row.col.f32.tf32.tf32.f32 "
        "{%0,%1,%2,%3}, {%4,%5,%6,%7}, {%8,%9}, {%0,%1,%2,%3};"
        : "+f"(d[0]), "+f"(d[1]), "+f"(d[2]), "+f"(d[3])
        : "r"(a[0]), "r"(a[1]), "r"(a[2]), "r"(a[3]), "r"(b[0]), "r"(b[1]));
}
__device__ __forceinline__ uint32_t fbits(float f) { return __float_as_uint(f); }

// ---------------------------------------------------------------------------
// LayerNorm: one block per row of 768
// ---------------------------------------------------------------------------
__global__ void ln_kernel(const float* __restrict__ x,
                          const float* __restrict__ w,
                          float* __restrict__ y)
{
    const int row = blockIdx.x;
    const float* xr = x + (size_t)row * DIM;
    float v[3];
    float s = 0.f, s2 = 0.f;
#pragma unroll
    for (int t = 0; t < 3; t++) {
        int i = threadIdx.x + t * 256;
        float vv = xr[i];
        v[t] = vv;
        s += vv; s2 += vv * vv;
    }
#pragma unroll
    for (int o = 16; o > 0; o >>= 1) {
        s  += __shfl_xor_sync(0xffffffffu, s,  o);
        s2 += __shfl_xor_sync(0xffffffffu, s2, o);
    }
    __shared__ float rs[8], rs2[8];
    int wid = threadIdx.x >> 5, lid = threadIdx.x & 31;
    if (lid == 0) { rs[wid] = s; rs2[wid] = s2; }
    __syncthreads();
    if (wid == 0) {
        s  = (lid < 8) ? rs[lid]  : 0.f;
        s2 = (lid < 8) ? rs2[lid] : 0.f;
#pragma unroll
        for (int o = 4; o > 0; o >>= 1) {
            s  += __shfl_xor_sync(0xffffffffu, s,  o);
            s2 += __shfl_xor_sync(0xffffffffu, s2, o);
        }
        if (lid == 0) { rs[0] = s; rs2[0] = s2; }
    }
    __syncthreads();
    const float mu   = rs[0] * (1.f / DIM);
    const float var  = rs2[0] * (1.f / DIM) - mu * mu;
    const float rstd = rsqrtf(var + 1e-5f);
    float* yr = y + (size_t)row * DIM;
#pragma unroll
    for (int t = 0; t < 3; t++) {
        int i = threadIdx.x + t * 256;
        yr[i] = (v[t] - mu) * rstd * w[i];
    }
}

// ---------------------------------------------------------------------------
// tf32 tensor-core GEMM: C[M,N] = A[M,K] @ B[K,N], fp32 in/out.
// BM=128, BN=128, BK=16, 256 threads = 8 warps (4x2), warp tile 32x64.
// Register prefetch + DOUBLE-BUFFERED smem: one __syncthreads per k-iter.
// ---------------------------------------------------------------------------
#define GA_ST 20
#define GB_ST 136

__global__ __launch_bounds__(256)
void gemm_tc_kernel(const float* __restrict__ A, const float* __restrict__ B,
                    float* __restrict__ C, int M, int N, int K)
{
    __shared__ float As[2][128 * GA_ST];
    __shared__ float Bs[2][16 * GB_ST];

    const int tid  = threadIdx.x;
    const int wid  = tid >> 5;
    const int lane = tid & 31;
    const int gr   = lane >> 2;
    const int gq   = lane & 3;
    const int wm   = (wid & 3) * 32;
    const int wn   = (wid >> 2) * 64;
    const int m0   = blockIdx.y * 128;
    const int n0   = blockIdx.x * 128;

    float acc[2][8][4];
#pragma unroll
    for (int ms = 0; ms < 2; ms++)
#pragma unroll
        for (int nt = 0; nt < 8; nt++)
#pragma unroll
            for (int i = 0; i < 4; i++) acc[ms][nt][i] = 0.f;

    uint4 pa[2], pb[2];
    const int am[2] = { (tid + 0) >> 2, (tid + 256) >> 2 };
    const int ak[2] = { ((tid + 0) & 3) * 4, ((tid + 256) & 3) * 4 };
    const int br[2] = { (tid + 0) >> 5, (tid + 256) >> 5 };
    const int bc[2] = { ((tid + 0) & 31) * 4, ((tid + 256) & 31) * 4 };

#pragma unroll
    for (int t = 0; t < 2; t++) {
        pa[t] = cvt4(*reinterpret_cast<const float4*>(
            &A[(size_t)(m0 + am[t]) * K + ak[t]]));
        pb[t] = cvt4(*reinterpret_cast<const float4*>(
            &B[(size_t)br[t] * N + n0 + bc[t]]));
    }

    int ib = 0;
    for (int kt = 0; kt < K; kt += 16, ib ^= 1) {
        float* Asb = As[ib];
        float* Bsb = Bs[ib];
#pragma unroll
        for (int t = 0; t < 2; t++) {
            *reinterpret_cast<uint4*>(&Asb[am[t] * GA_ST + ak[t]]) = pa[t];
            *reinterpret_cast<uint4*>(&Bsb[br[t] * GB_ST + bc[t]]) = pb[t];
        }
        __syncthreads();

        if (kt + 16 < K) {
#pragma unroll
            for (int t = 0; t < 2; t++) {
                pa[t] = cvt4(*reinterpret_cast<const float4*>(
                    &A[(size_t)(m0 + am[t]) * K + kt + 16 + ak[t]]));
                pb[t] = cvt4(*reinterpret_cast<const float4*>(
                    &B[(size_t)(kt + 16 + br[t]) * N + n0 + bc[t]]));
            }
        }

#pragma unroll
        for (int ks = 0; ks < 2; ks++) {
            const int k8 = ks * 8;
            uint32_t af[2][4];
#pragma unroll
            for (int ms = 0; ms < 2; ms++) {
                const int mb = wm + ms * 16;
                af[ms][0] = fbits(Asb[(mb + gr    ) * GA_ST + k8 + gq]);
                af[ms][1] = fbits(Asb[(mb + gr + 8) * GA_ST + k8 + gq]);
                af[ms][2] = fbits(Asb[(mb + gr    ) * GA_ST + k8 + 4 + gq]);
                af[ms][3] = fbits(Asb[(mb + gr + 8) * GA_ST + k8 + 4 + gq]);
            }
#pragma unroll
            for (int nt = 0; nt < 8; nt++) {
                uint32_t bf[2];
                bf[0] = fbits(Bsb[(k8 + gq    ) * GB_ST + wn + nt * 8 + gr]);
                bf[1] = fbits(Bsb[(k8 + 4 + gq) * GB_ST + wn + nt * 8 + gr]);
#pragma unroll
                for (int ms = 0; ms < 2; ms++)
                    mma_tf32(acc[ms][nt], af[ms], bf);
            }
        }
        // no trailing sync: next iter stores into the other buffer
    }

#pragma unroll
    for (int ms = 0; ms < 2; ms++) {
        const int mrow0 = m0 + wm + ms * 16 + gr;
#pragma unroll
        for (int nt = 0; nt < 8; nt++) {
            const int col = n0 + wn + nt * 8 + 2 * gq;
            *reinterpret_cast<float2*>(&C[(size_t)mrow0 * N + col]) =
                make_float2(acc[ms][nt][0], acc[ms][nt][1]);
            *reinterpret_cast<float2*>(&C[(size_t)(mrow0 + 8) * N + col]) =
                make_float2(acc[ms][nt][2], acc[ms][nt][3]);
        }
    }
}

// ---------------------------------------------------------------------------
// tf32 mma.sync flash attention, register-prefetch staged K/V.
// CTA = 128 q-rows of one (b,h), 256 threads = 8 warps; warp owns 16 rows.
// j-tile = 64. Next tile's K/V prefetched into 32 regs (LDG) during compute;
// staged to smem with ONE tf32 cvt per element. Smem holds tf32 bits, so
// fragment loads need no cvt (alu pipe freed). Mask loaded per tile at tile
// start (latency hidden by staging + S-MMA). Unstabilized softmax.
// Smem (floats): Ks[64*68] Vs[64*72] Ps[128*68] = 17664 floats = 70656 B.
// ---------------------------------------------------------------------------
#define KS_ST 68
#define VS_ST 72
#define PS_ST 68
#define SM_KS 0
#define SM_VS (SM_KS + 64 * KS_ST)           // 4352
#define SM_PS (SM_VS + 64 * VS_ST)           // 8960
#define ATTN_SM_FLOATS (SM_PS + 128 * PS_ST) // 17664 floats
#define NTILES (SEQ_J / 64)                  // 32

__global__ __launch_bounds__(256, 1)
void attn_mma_kernel(const float* __restrict__ q, const float* __restrict__ kv,
                     const float* __restrict__ mask, float* __restrict__ o)
{
    extern __shared__ float sm[];
    float* Ks = sm + SM_KS;
    float* Vs = sm + SM_VS;
    float* Ps = sm + SM_PS;

    const int tid  = threadIdx.x;
    const int wid  = tid >> 5;
    const int lane = tid & 31;
    const int gr   = lane >> 2;
    const int gq   = lane & 3;
    const int h    = blockIdx.y;
    const int b    = blockIdx.z;
    const int row0 = blockIdx.x * 128;
    const int qrb  = row0 + wid * 16;

    // staging indices (fixed per thread): 8 float4 chunks of the 64x128 kv tile
    int sjj[8], sc4[8];
#pragma unroll
    for (int t = 0; t < 8; t++) {
        const int e = tid + t * 256;
        sjj[t] = e >> 5;
        sc4[t] = e & 31;
    }

    // ---- Q fragments: 8 k-steps x 4 regs, pre-scaled, tf32 ----
    uint32_t qf[8][4];
    {
        const float* qb = q + ((size_t)(b * SEQ_N) + qrb) * INNER + h * DHEAD;
#pragma unroll
        for (int c = 0; c < 8; c++) {
            qf[c][0] = f2tf32(qb[(size_t)(gr    ) * INNER + c * 8 + gq    ] * SCALE);
            qf[c][1] = f2tf32(qb[(size_t)(gr + 8) * INNER + c * 8 + gq    ] * SCALE);
            qf[c][2] = f2tf32(qb[(size_t)(gr    ) * INNER + c * 8 + 4 + gq] * SCALE);
            qf[c][3] = f2tf32(qb[(size_t)(gr + 8) * INNER + c * 8 + 4 + gq] * SCALE);
        }
    }

    float oacc[8][4];
#pragma unroll
    for (int nt = 0; nt < 8; nt++)
#pragma unroll
        for (int i = 0; i < 4; i++) oacc[nt][i] = 0.f;
    float l0 = 0.f, l1 = 0.f;

    const float* m0p = mask + ((size_t)(b * SEQ_N) + qrb + gr) * SEQ_J;
    const float* m1p = m0p + (size_t)8 * SEQ_J;
    const float* kv_base = kv + (size_t)b * SEQ_J * 128;

    const int prow0 = (wid * 16 + gr) * PS_ST;
    const int prow1 = (wid * 16 + 8 + gr) * PS_ST;

    // ---- prologue: prefetch tile 0 K/V into registers ----
    float4 pf[8];
#pragma unroll
    for (int t = 0; t < 8; t++)
        pf[t] = *reinterpret_cast<const float4*>(
            &kv_base[(size_t)sjj[t] * 128 + sc4[t] * 4]);

#pragma unroll 1
    for (int t = 0; t < NTILES; t++) {
        __syncthreads();   // all warps done reading Ks/Vs/Ps of tile t-1

        // mask loads for THIS tile (issued early; consumed after S-MMA)
        float2 mk0[8], mk1[8];
        {
            const int colb = t * 64 + 2 * gq;
#pragma unroll
            for (int nt = 0; nt < 8; nt++) {
                mk0[nt] = *reinterpret_cast<const float2*>(&m0p[colb + nt * 8]);
                mk1[nt] = *reinterpret_cast<const float2*>(&m1p[colb + nt * 8]);
            }
        }

        // stage prefetched K/V to smem with single tf32 cvt
#pragma unroll
        for (int tt = 0; tt < 8; tt++) {
            uint4 w = cvt4(pf[tt]);
            if (sc4[tt] < 16)
                *reinterpret_cast<uint4*>(&Ks[sjj[tt] * KS_ST + sc4[tt] * 4]) = w;
            else
                *reinterpret_cast<uint4*>(
                    &Vs[sjj[tt] * VS_ST + (sc4[tt] - 16) * 4]) = w;
        }
        __syncthreads();

        // prefetch tile t+1 K/V (overlaps all of tile-t compute)
        if (t + 1 < NTILES) {
            const float* src = kv_base + (size_t)(t + 1) * 64 * 128;
#pragma unroll
            for (int tt = 0; tt < 8; tt++)
                pf[tt] = *reinterpret_cast<const float4*>(
                    &src[(size_t)sjj[tt] * 128 + sc4[tt] * 4]);
        }

        // ---- S = Q @ K^T (smem already tf32: no cvt) ----
        float sacc[8][4];
#pragma unroll
        for (int nt = 0; nt < 8; nt++)
#pragma unroll
            for (int i = 0; i < 4; i++) sacc[nt][i] = 0.f;

#pragma unroll
        for (int c = 0; c < 8; c++) {
#pragma unroll
            for (int nt = 0; nt < 8; nt++) {
                uint32_t bf[2];
                bf[0] = fbits(Ks[(nt * 8 + gr) * KS_ST + c * 8 + gq]);
                bf[1] = fbits(Ks[(nt * 8 + gr) * KS_ST + c * 8 + 4 + gq]);
                mma_tf32(sacc[nt], qf[c], bf);
            }
        }

        // ---- softmax (unstabilized) + P -> smem (own rows only) ----
#pragma unroll
        for (int nt = 0; nt < 8; nt++) {
            float p00 = __expf(sacc[nt][0] + mk0[nt].x);
            float p01 = __expf(sacc[nt][1] + mk0[nt].y);
            float p10 = __expf(sacc[nt][2] + mk1[nt].x);
            float p11 = __expf(sacc[nt][3] + mk1[nt].y);
            l0 += p00 + p01;
            l1 += p10 + p11;
            const int cb = nt * 8 + 2 * gq;
            *reinterpret_cast<uint2*>(&Ps[prow0 + cb]) =
                make_uint2(f2tf32(p00), f2tf32(p01));
            *reinterpret_cast<uint2*>(&Ps[prow1 + cb]) =
                make_uint2(f2tf32(p10), f2tf32(p11));
        }
        __syncwarp();

        // ---- O += P @ V (smem already tf32: no cvt) ----
#pragma unroll
        for (int c = 0; c < 8; c++) {
            uint32_t af[4];
            af[0] = fbits(Ps[prow0 + c * 8 + gq]);
            af[1] = fbits(Ps[prow1 + c * 8 + gq]);
            af[2] = fbits(Ps[prow0 + c * 8 + 4 + gq]);
            af[3] = fbits(Ps[prow1 + c * 8 + 4 + gq]);
#pragma unroll
            for (int nt = 0; nt < 8; nt++) {
                uint32_t bf[2];
                bf[0] = fbits(Vs[(c * 8 + gq    ) * VS_ST + nt * 8 + gr]);
                bf[1] = fbits(Vs[(c * 8 + 4 + gq) * VS_ST + nt * 8 + gr]);
                mma_tf32(oacc[nt], af, bf);
            }
        }
    }

    // ---- finalize: reduce l over quad lanes, normalize, store ----
    l0 += __shfl_xor_sync(0xffffffffu, l0, 1);
    l0 += __shfl_xor_sync(0xffffffffu, l0, 2);
    l1 += __shfl_xor_sync(0xffffffffu, l1, 1);
    l1 += __shfl_xor_sync(0xffffffffu, l1, 2);
    const float inv0 = 1.f / l0;
    const float inv1 = 1.f / l1;

    float* ob = o + ((size_t)(b * SEQ_N) + qrb) * INNER + h * DHEAD;
#pragma unroll
    for (int nt = 0; nt < 8; nt++) {
        const int cb = nt * 8 + 2 * gq;
        *reinterpret_cast<float2*>(&ob[(size_t)gr * INNER + cb]) =
            make_float2(oacc[nt][0] * inv0, oacc[nt][1] * inv0);
        *reinterpret_cast<float2*>(&ob[(size_t)(gr + 8) * INNER + cb]) =
            make_float2(oacc[nt][2] * inv1, oacc[nt][3] * inv1);
    }
}

// ---------------------------------------------------------------------------
// Launch
// ---------------------------------------------------------------------------
extern "C" void kernel_launch(void* const* d_in, const int* in_sizes, int n_in,
                              void* d_out, int out_size)
{
    const float* x       = (const float*)d_in[0];
    const float* context = (const float*)d_in[1];
    const float* mask    = (const float*)d_in[2];
    const float* ln_w    = (const float*)d_in[3];
    const float* Wq      = (const float*)d_in[4];
    const float* Wkv     = (const float*)d_in[5];
    const float* Wo      = (const float*)d_in[6];
    float* out = (float*)d_out;

    float *xn, *q, *kvb, *ao;
    cudaGetSymbolAddress((void**)&xn,  g_xn);
    cudaGetSymbolAddress((void**)&q,   g_q);
    cudaGetSymbolAddress((void**)&kvb, g_kv);
    cudaGetSymbolAddress((void**)&ao,  g_ao);

    const int attn_smem = ATTN_SM_FLOATS * sizeof(float);   // 70656 B
    cudaFuncSetAttribute(attn_mma_kernel,
                         cudaFuncAttributeMaxDynamicSharedMemorySize, attn_smem);

    // 1. layernorm
    ln_kernel<<<ROWS_TOTAL, 256>>>(x, ln_w, xn);

    // 2. q = ln(x) @ Wq
    gemm_tc_kernel<<<dim3(INNER / 128, ROWS_TOTAL / 128), 256>>>(
        xn, Wq, q, ROWS_TOTAL, INNER, DIM);

    // 3. kv = context @ Wkv
    gemm_tc_kernel<<<dim3(128 / 128, ROWS_TOTAL / 128), 256>>>(
        context, Wkv, kvb, ROWS_TOTAL, 128, DIM);

    // 4. attention (tf32 mma.sync flash, register-prefetch staged)
    attn_mma_kernel<<<dim3(SEQ_N / 128, HEADS, BATCH), 256, attn_smem>>>(
        q, kvb, mask, ao);

    // 5. out = ao @ Wo
    gemm_tc_kernel<<<dim3(DIM / 128, ROWS_TOTAL / 128), 256>>>(
        ao, Wo, out, ROWS_TOTAL, DIM, INNER);
}

// round 10
// speedup vs baseline: 4.1022x; 1.1301x over previous
#include <cuda_runtime.h>
#include <cuda_bf16.h>
#include <cstdint>
#include <math.h>

// Problem constants
#define BATCH   4
#define SEQ_N   2048
#define SEQ_J   2048
#define DIM     768
#define HEADS   12
#define DHEAD   64
#define INNER   (HEADS * DHEAD)   // 768
#define SCALE   0.125f            // 64^-0.5

#define ROWS_TOTAL (BATCH * SEQ_N) // 8192

// ---------------------------------------------------------------------------
// Scratch (static device allocations; no cudaMalloc allowed)
// g_q / g_kv hold tf32 BIT PATTERNS (written by GEMM epilogue).
// ---------------------------------------------------------------------------
__device__ float g_xn[(size_t)ROWS_TOTAL * DIM];     // layernorm(x), fp32
__device__ float g_q [(size_t)ROWS_TOTAL * INNER];   // q, tf32 bits, pre-scaled
__device__ float g_kv[(size_t)ROWS_TOTAL * 128];     // [k|v], tf32 bits
__device__ float g_ao[(size_t)ROWS_TOTAL * INNER];   // attn output, fp32

// ===========================================================================
// tf32 mma.sync helpers (sm_80+ portable PTX — compiles for plain sm_103)
// ===========================================================================
__device__ __forceinline__ uint32_t f2tf32(float f) {
    uint32_t r;
    asm("cvt.rna.tf32.f32 %0, %1;" : "=r"(r) : "f"(f));
    return r;
}
__device__ __forceinline__ uint4 cvt4(float4 v) {
    uint4 r;
    r.x = f2tf32(v.x); r.y = f2tf32(v.y); r.z = f2tf32(v.z); r.w = f2tf32(v.w);
    return r;
}
// D += A(16x8,row) * B(8x8,col), tf32 in, f32 acc
__device__ __forceinline__ void mma_tf32(float* d, const uint32_t* a,
                                         const uint32_t* b) {
    asm volatile(
        "mma.sync.aligned.m16n8k8.row.col.f32.tf32.tf32.f32 "
        "{%0,%1,%2,%3}, {%4,%5,%6,%7}, {%8,%9}, {%0,%1,%2,%3};"
        : "+f"(d[0]), "+f"(d[1]), "+f"(d[2]), "+f"(d[3])
        : "r"(a[0]), "r"(a[1]), "r"(a[2]), "r"(a[3]), "r"(b[0]), "r"(b[1]));
}
__device__ __forceinline__ uint32_t fbits(float f) { return __float_as_uint(f); }
__device__ __forceinline__ uint32_t smem_to_u32(const void* p) {
    uint32_t a;
    asm("{ .reg .u64 t; cvta.to.shared.u64 t, %1; cvt.u32.u64 %0, t; }"
        : "=r"(a) : "l"(p));
    return a;
}
#define CP_ASYNC16(dst_u32, src_ptr) \
    asm volatile("cp.async.cg.shared.global [%0], [%1], 16;" \
        :: "r"(dst_u32), "l"(src_ptr))
#define CP_COMMIT() asm volatile("cp.async.commit_group;" ::: "memory")
#define CP_WAIT_ALL() asm volatile("cp.async.wait_group 0;" ::: "memory")

// ---------------------------------------------------------------------------
// LayerNorm: one block per row of 768
// ---------------------------------------------------------------------------
__global__ void ln_kernel(const float* __restrict__ x,
                          const float* __restrict__ w,
                          float* __restrict__ y)
{
    const int row = blockIdx.x;
    const float* xr = x + (size_t)row * DIM;
    float v[3];
    float s = 0.f, s2 = 0.f;
#pragma unroll
    for (int t = 0; t < 3; t++) {
        int i = threadIdx.x + t * 256;
        float vv = xr[i];
        v[t] = vv;
        s += vv; s2 += vv * vv;
    }
#pragma unroll
    for (int o = 16; o > 0; o >>= 1) {
        s  += __shfl_xor_sync(0xffffffffu, s,  o);
        s2 += __shfl_xor_sync(0xffffffffu, s2, o);
    }
    __shared__ float rs[8], rs2[8];
    int wid = threadIdx.x >> 5, lid = threadIdx.x & 31;
    if (lid == 0) { rs[wid] = s; rs2[wid] = s2; }
    __syncthreads();
    if (wid == 0) {
        s  = (lid < 8) ? rs[lid]  : 0.f;
        s2 = (lid < 8) ? rs2[lid] : 0.f;
#pragma unroll
        for (int o = 4; o > 0; o >>= 1) {
            s  += __shfl_xor_sync(0xffffffffu, s,  o);
            s2 += __shfl_xor_sync(0xffffffffu, s2, o);
        }
        if (lid == 0) { rs[0] = s; rs2[0] = s2; }
    }
    __syncthreads();
    const float mu   = rs[0] * (1.f / DIM);
    const float var  = rs2[0] * (1.f / DIM) - mu * mu;
    const float rstd = rsqrtf(var + 1e-5f);
    float* yr = y + (size_t)row * DIM;
#pragma unroll
    for (int t = 0; t < 3; t++) {
        int i = threadIdx.x + t * 256;
        yr[i] = (v[t] - mu) * rstd * w[i];
    }
}

// ---------------------------------------------------------------------------
// tf32 tensor-core GEMM: C[M,N] = A[M,K] @ B[K,N].
// out_mode: 0 = fp32, 1 = tf32 bits, 2 = tf32 bits of (acc * SCALE).
// BM=128, BN=128, BK=16, 256 threads = 8 warps (4x2), warp tile 32x64.
// Register prefetch + double-buffered smem: one __syncthreads per k-iter.
// ---------------------------------------------------------------------------
#define GA_ST 20
#define GB_ST 136

__global__ __launch_bounds__(256)
void gemm_tc_kernel(const float* __restrict__ A, const float* __restrict__ B,
                    float* __restrict__ C, int M, int N, int K, int out_mode)
{
    __shared__ float As[2][128 * GA_ST];
    __shared__ float Bs[2][16 * GB_ST];

    const int tid  = threadIdx.x;
    const int wid  = tid >> 5;
    const int lane = tid & 31;
    const int gr   = lane >> 2;
    const int gq   = lane & 3;
    const int wm   = (wid & 3) * 32;
    const int wn   = (wid >> 2) * 64;
    const int m0   = blockIdx.y * 128;
    const int n0   = blockIdx.x * 128;

    float acc[2][8][4];
#pragma unroll
    for (int ms = 0; ms < 2; ms++)
#pragma unroll
        for (int nt = 0; nt < 8; nt++)
#pragma unroll
            for (int i = 0; i < 4; i++) acc[ms][nt][i] = 0.f;

    uint4 pa[2], pb[2];
    const int am[2] = { (tid + 0) >> 2, (tid + 256) >> 2 };
    const int ak[2] = { ((tid + 0) & 3) * 4, ((tid + 256) & 3) * 4 };
    const int br[2] = { (tid + 0) >> 5, (tid + 256) >> 5 };
    const int bc[2] = { ((tid + 0) & 31) * 4, ((tid + 256) & 31) * 4 };

#pragma unroll
    for (int t = 0; t < 2; t++) {
        pa[t] = cvt4(*reinterpret_cast<const float4*>(
            &A[(size_t)(m0 + am[t]) * K + ak[t]]));
        pb[t] = cvt4(*reinterpret_cast<const float4*>(
            &B[(size_t)br[t] * N + n0 + bc[t]]));
    }

    int ib = 0;
    for (int kt = 0; kt < K; kt += 16, ib ^= 1) {
        float* Asb = As[ib];
        float* Bsb = Bs[ib];
#pragma unroll
        for (int t = 0; t < 2; t++) {
            *reinterpret_cast<uint4*>(&Asb[am[t] * GA_ST + ak[t]]) = pa[t];
            *reinterpret_cast<uint4*>(&Bsb[br[t] * GB_ST + bc[t]]) = pb[t];
        }
        __syncthreads();

        if (kt + 16 < K) {
#pragma unroll
            for (int t = 0; t < 2; t++) {
                pa[t] = cvt4(*reinterpret_cast<const float4*>(
                    &A[(size_t)(m0 + am[t]) * K + kt + 16 + ak[t]]));
                pb[t] = cvt4(*reinterpret_cast<const float4*>(
                    &B[(size_t)(kt + 16 + br[t]) * N + n0 + bc[t]]));
            }
        }

#pragma unroll
        for (int ks = 0; ks < 2; ks++) {
            const int k8 = ks * 8;
            uint32_t af[2][4];
#pragma unroll
            for (int ms = 0; ms < 2; ms++) {
                const int mb = wm + ms * 16;
                af[ms][0] = fbits(Asb[(mb + gr    ) * GA_ST + k8 + gq]);
                af[ms][1] = fbits(Asb[(mb + gr + 8) * GA_ST + k8 + gq]);
                af[ms][2] = fbits(Asb[(mb + gr    ) * GA_ST + k8 + 4 + gq]);
                af[ms][3] = fbits(Asb[(mb + gr + 8) * GA_ST + k8 + 4 + gq]);
            }
#pragma unroll
            for (int nt = 0; nt < 8; nt++) {
                uint32_t bf[2];
                bf[0] = fbits(Bsb[(k8 + gq    ) * GB_ST + wn + nt * 8 + gr]);
                bf[1] = fbits(Bsb[(k8 + 4 + gq) * GB_ST + wn + nt * 8 + gr]);
#pragma unroll
                for (int ms = 0; ms < 2; ms++)
                    mma_tf32(acc[ms][nt], af[ms], bf);
            }
        }
    }

    const float alpha = (out_mode == 2) ? SCALE : 1.0f;
#pragma unroll
    for (int ms = 0; ms < 2; ms++) {
        const int mrow0 = m0 + wm + ms * 16 + gr;
#pragma unroll
        for (int nt = 0; nt < 8; nt++) {
            const int col = n0 + wn + nt * 8 + 2 * gq;
            if (out_mode == 0) {
                *reinterpret_cast<float2*>(&C[(size_t)mrow0 * N + col]) =
                    make_float2(acc[ms][nt][0], acc[ms][nt][1]);
                *reinterpret_cast<float2*>(&C[(size_t)(mrow0 + 8) * N + col]) =
                    make_float2(acc[ms][nt][2], acc[ms][nt][3]);
            } else {
                *reinterpret_cast<uint2*>(&C[(size_t)mrow0 * N + col]) =
                    make_uint2(f2tf32(acc[ms][nt][0] * alpha),
                               f2tf32(acc[ms][nt][1] * alpha));
                *reinterpret_cast<uint2*>(&C[(size_t)(mrow0 + 8) * N + col]) =
                    make_uint2(f2tf32(acc[ms][nt][2] * alpha),
                               f2tf32(acc[ms][nt][3] * alpha));
            }
        }
    }
}

// ---------------------------------------------------------------------------
// tf32 mma.sync flash attention — occupancy 2 CTAs/SM.
// q and kv arrive as tf32 BIT PATTERNS (pre-scaled q), so the kernel does
// zero input conversion: cp.async bits straight into smem, fragment loads are
// raw. Mask float2 loaded inline in the softmax loop (16 warps/SM hide it).
// CTA = 128 q-rows of one (b,h), 256 threads = 8 warps; warp owns 16 rows.
// Smem: K0 V0 K1 V1 Ps = 106496 B. __launch_bounds__(256, 2).
// ---------------------------------------------------------------------------
#define KS_ST 68
#define VS_ST 72
#define PS_ST 68
#define SM_K0 0
#define SM_V0 (SM_K0 + 64 * KS_ST)     // 4352
#define SM_K1 (SM_V0 + 64 * VS_ST)     // 8960
#define SM_V1 (SM_K1 + 64 * KS_ST)     // 13312
#define SM_PS (SM_V1 + 64 * VS_ST)     // 17920
#define ATTN_SM_FLOATS (SM_PS + 128 * PS_ST)  // 26624 floats = 106496 B
#define BUF_STRIDE_B ((SM_K1 - SM_K0) * 4)    // bytes between buffers
#define NTILES (SEQ_J / 64)            // 32

__device__ __forceinline__ void stage_kv_async(uint32_t smem_u32, int buf,
                                               const float* kv_tile, int tid)
{
    const uint32_t base = smem_u32 + (buf ? BUF_STRIDE_B : 0);
#pragma unroll
    for (int t = 0; t < 8; t++) {
        const int e  = tid + t * 256;    // 0..2047 float4 chunks
        const int jj = e >> 5;
        const int c4 = e & 31;
        const float* src = kv_tile + (size_t)jj * 128 + c4 * 4;
        const uint32_t dst = (c4 < 16)
            ? base + (uint32_t)(SM_K0 + jj * KS_ST + c4 * 4) * 4
            : base + (uint32_t)(SM_V0 + jj * VS_ST + (c4 - 16) * 4) * 4;
        CP_ASYNC16(dst, src);
    }
    CP_COMMIT();
}

__global__ __launch_bounds__(256, 2)
void attn_mma_kernel(const float* __restrict__ q, const float* __restrict__ kv,
                     const float* __restrict__ mask, float* __restrict__ o)
{
    extern __shared__ float sm[];
    const uint32_t smem_u32 = smem_to_u32(sm);
    float* Ps = sm + SM_PS;

    const int tid  = threadIdx.x;
    const int wid  = tid >> 5;
    const int lane = tid & 31;
    const int gr   = lane >> 2;
    const int gq   = lane & 3;
    const int h    = blockIdx.y;
    const int b    = blockIdx.z;
    const int row0 = blockIdx.x * 128;
    const int qrb  = row0 + wid * 16;

    // ---- Q fragments: raw tf32 bits (pre-scaled by the Wq GEMM epilogue) ----
    uint32_t qf[8][4];
    {
        const uint32_t* qb = reinterpret_cast<const uint32_t*>(
            q + ((size_t)(b * SEQ_N) + qrb) * INNER + h * DHEAD);
#pragma unroll
        for (int c = 0; c < 8; c++) {
            qf[c][0] = qb[(size_t)(gr    ) * INNER + c * 8 + gq    ];
            qf[c][1] = qb[(size_t)(gr + 8) * INNER + c * 8 + gq    ];
            qf[c][2] = qb[(size_t)(gr    ) * INNER + c * 8 + 4 + gq];
            qf[c][3] = qb[(size_t)(gr + 8) * INNER + c * 8 + 4 + gq];
        }
    }

    float oacc[8][4];
#pragma unroll
    for (int nt = 0; nt < 8; nt++)
#pragma unroll
        for (int i = 0; i < 4; i++) oacc[nt][i] = 0.f;
    float l0 = 0.f, l1 = 0.f;

    const float* m0p = mask + ((size_t)(b * SEQ_N) + qrb + gr) * SEQ_J + 2 * gq;
    const float* kv_base = kv + (size_t)b * SEQ_J * 128;

    const int prow0 = (wid * 16 + gr) * PS_ST;
    const int prow1 = (wid * 16 + 8 + gr) * PS_ST;

    // ---- prologue: stage tile 0 into buffer 0 ----
    stage_kv_async(smem_u32, 0, kv_base, tid);

#pragma unroll 1
    for (int t = 0; t < NTILES; t++) {
        const int cur = t & 1;

        CP_WAIT_ALL();
        __syncthreads();   // tile t visible; all warps done with buf t-1

        if (t + 1 < NTILES)
            stage_kv_async(smem_u32, cur ^ 1,
                           kv_base + (size_t)(t + 1) * 64 * 128, tid);

        const float* Kf = sm + (cur ? SM_K1 : SM_K0);
        const float* Vf = sm + (cur ? SM_V1 : SM_V0);

        // ---- S = Q @ K^T (raw tf32 bits from smem) ----
        float sacc[8][4];
#pragma unroll
        for (int nt = 0; nt < 8; nt++)
#pragma unroll
            for (int i = 0; i < 4; i++) sacc[nt][i] = 0.f;

#pragma unroll
        for (int c = 0; c < 8; c++) {
#pragma unroll
            for (int nt = 0; nt < 8; nt++) {
                uint32_t bf[2];
                bf[0] = fbits(Kf[(nt * 8 + gr) * KS_ST + c * 8 + gq]);
                bf[1] = fbits(Kf[(nt * 8 + gr) * KS_ST + c * 8 + 4 + gq]);
                mma_tf32(sacc[nt], qf[c], bf);
            }
        }

        // ---- softmax (unstabilized) with inline mask loads ----
        {
            const float* mrow = m0p + t * 64;
#pragma unroll
            for (int nt = 0; nt < 8; nt++) {
                float2 mk0 = *reinterpret_cast<const float2*>(&mrow[nt * 8]);
                float2 mk1 = *reinterpret_cast<const float2*>(
                    &mrow[(size_t)8 * SEQ_J + nt * 8]);
                float p00 = __expf(sacc[nt][0] + mk0.x);
                float p01 = __expf(sacc[nt][1] + mk0.y);
                float p10 = __expf(sacc[nt][2] + mk1.x);
                float p11 = __expf(sacc[nt][3] + mk1.y);
                l0 += p00 + p01;
                l1 += p10 + p11;
                const int cb = nt * 8 + 2 * gq;
                *reinterpret_cast<uint2*>(&Ps[prow0 + cb]) =
                    make_uint2(f2tf32(p00), f2tf32(p01));
                *reinterpret_cast<uint2*>(&Ps[prow1 + cb]) =
                    make_uint2(f2tf32(p10), f2tf32(p11));
            }
        }
        __syncwarp();

        // ---- O += P @ V ----
#pragma unroll
        for (int c = 0; c < 8; c++) {
            uint32_t af[4];
            af[0] = fbits(Ps[prow0 + c * 8 + gq]);
            af[1] = fbits(Ps[prow1 + c * 8 + gq]);
            af[2] = fbits(Ps[prow0 + c * 8 + 4 + gq]);
            af[3] = fbits(Ps[prow1 + c * 8 + 4 + gq]);
#pragma unroll
            for (int nt = 0; nt < 8; nt++) {
                uint32_t bf[2];
                bf[0] = fbits(Vf[(c * 8 + gq    ) * VS_ST + nt * 8 + gr]);
                bf[1] = fbits(Vf[(c * 8 + 4 + gq) * VS_ST + nt * 8 + gr]);
                mma_tf32(oacc[nt], af, bf);
            }
        }
    }

    // ---- finalize: reduce l over quad lanes, normalize, store ----
    l0 += __shfl_xor_sync(0xffffffffu, l0, 1);
    l0 += __shfl_xor_sync(0xffffffffu, l0, 2);
    l1 += __shfl_xor_sync(0xffffffffu, l1, 1);
    l1 += __shfl_xor_sync(0xffffffffu, l1, 2);
    const float inv0 = 1.f / l0;
    const float inv1 = 1.f / l1;

    float* ob = o + ((size_t)(b * SEQ_N) + qrb) * INNER + h * DHEAD;
#pragma unroll
    for (int nt = 0; nt < 8; nt++) {
        const int cb = nt * 8 + 2 * gq;
        *reinterpret_cast<float2*>(&ob[(size_t)gr * INNER + cb]) =
            make_float2(oacc[nt][0] * inv0, oacc[nt][1] * inv0);
        *reinterpret_cast<float2*>(&ob[(size_t)(gr + 8) * INNER + cb]) =
            make_float2(oacc[nt][2] * inv1, oacc[nt][3] * inv1);
    }
}

// ---------------------------------------------------------------------------
// Launch
// ---------------------------------------------------------------------------
extern "C" void kernel_launch(void* const* d_in, const int* in_sizes, int n_in,
                              void* d_out, int out_size)
{
    const float* x       = (const float*)d_in[0];
    const float* context = (const float*)d_in[1];
    const float* mask    = (const float*)d_in[2];
    const float* ln_w    = (const float*)d_in[3];
    const float* Wq      = (const float*)d_in[4];
    const float* Wkv     = (const float*)d_in[5];
    const float* Wo      = (const float*)d_in[6];
    float* out = (float*)d_out;

    float *xn, *q, *kvb, *ao;
    cudaGetSymbolAddress((void**)&xn,  g_xn);
    cudaGetSymbolAddress((void**)&q,   g_q);
    cudaGetSymbolAddress((void**)&kvb, g_kv);
    cudaGetSymbolAddress((void**)&ao,  g_ao);

    const int attn_smem = ATTN_SM_FLOATS * sizeof(float);   // 106496 B
    cudaFuncSetAttribute(attn_mma_kernel,
                         cudaFuncAttributeMaxDynamicSharedMemorySize, attn_smem);

    // 1. layernorm
    ln_kernel<<<ROWS_TOTAL, 256>>>(x, ln_w, xn);

    // 2. q = ln(x) @ Wq  -> tf32 bits, pre-scaled by SCALE (out_mode=2)
    gemm_tc_kernel<<<dim3(INNER / 128, ROWS_TOTAL / 128), 256>>>(
        xn, Wq, q, ROWS_TOTAL, INNER, DIM, 2);

    // 3. kv = context @ Wkv -> tf32 bits (out_mode=1)
    gemm_tc_kernel<<<dim3(128 / 128, ROWS_TOTAL / 128), 256>>>(
        context, Wkv, kvb, ROWS_TOTAL, 128, DIM, 1);

    // 4. attention (tf32 mma.sync flash, cp.async, 2 CTAs/SM)
    attn_mma_kernel<<<dim3(SEQ_N / 128, HEADS, BATCH), 256, attn_smem>>>(
        q, kvb, mask, ao);

    // 5. out = ao @ Wo (fp32 out)
    gemm_tc_kernel<<<dim3(DIM / 128, ROWS_TOTAL / 128), 256>>>(
        ao, Wo, out, ROWS_TOTAL, DIM, INNER, 0);
}

// round 11
// speedup vs baseline: 5.8646x; 1.4296x over previous
#include <cuda_runtime.h>
#include <cuda_fp16.h>
#include <cstdint>
#include <math.h>

// Problem constants
#define BATCH   4
#define SEQ_N   2048
#define SEQ_J   2048
#define DIM     768
#define HEADS   12
#define DHEAD   64
#define INNER   (HEADS * DHEAD)   // 768
#define SCALE   0.125f            // 64^-0.5

#define ROWS_TOTAL (BATCH * SEQ_N) // 8192

// ---------------------------------------------------------------------------
// Scratch (static device allocations; no cudaMalloc allowed)
// ---------------------------------------------------------------------------
__device__ float  g_xn[(size_t)ROWS_TOTAL * DIM];     // layernorm(x), fp32
__device__ __half g_qh[(size_t)ROWS_TOTAL * INNER];   // q, fp16, pre-scaled
__device__ __half g_kvh[(size_t)ROWS_TOTAL * 128];    // [k|v] fp16
__device__ float  g_ao[(size_t)ROWS_TOTAL * INNER];   // attn output, fp32

// ===========================================================================
// helpers (sm_80+ portable PTX — compiles for plain sm_103)
// ===========================================================================
__device__ __forceinline__ uint32_t f2tf32(float f) {
    uint32_t r;
    asm("cvt.rna.tf32.f32 %0, %1;" : "=r"(r) : "f"(f));
    return r;
}
__device__ __forceinline__ uint4 cvt4(float4 v) {
    uint4 r;
    r.x = f2tf32(v.x); r.y = f2tf32(v.y); r.z = f2tf32(v.z); r.w = f2tf32(v.w);
    return r;
}
__device__ __forceinline__ void mma_tf32(float* d, const uint32_t* a,
                                         const uint32_t* b) {
    asm volatile(
        "mma.sync.aligned.m16n8k8.row.col.f32.tf32.tf32.f32 "
        "{%0,%1,%2,%3}, {%4,%5,%6,%7}, {%8,%9}, {%0,%1,%2,%3};"
        : "+f"(d[0]), "+f"(d[1]), "+f"(d[2]), "+f"(d[3])
        : "r"(a[0]), "r"(a[1]), "r"(a[2]), "r"(a[3]), "r"(b[0]), "r"(b[1]));
}
// fp16 m16n8k16, fp32 accumulate
__device__ __forceinline__ void mma_f16(float* d, const uint32_t* a,
                                        uint32_t b0, uint32_t b1) {
    asm volatile(
        "mma.sync.aligned.m16n8k16.row.col.f32.f16.f16.f32 "
        "{%0,%1,%2,%3}, {%4,%5,%6,%7}, {%8,%9}, {%0,%1,%2,%3};"
        : "+f"(d[0]), "+f"(d[1]), "+f"(d[2]), "+f"(d[3])
        : "r"(a[0]), "r"(a[1]), "r"(a[2]), "r"(a[3]), "r"(b0), "r"(b1));
}
__device__ __forceinline__ uint32_t fbits(float f) { return __float_as_uint(f); }
__device__ __forceinline__ uint32_t smem_to_u32(const void* p) {
    uint32_t a;
    asm("{ .reg .u64 t; cvta.to.shared.u64 t, %1; cvt.u32.u64 %0, t; }"
        : "=r"(a) : "l"(p));
    return a;
}
#define CP_ASYNC16(dst_u32, src_ptr) \
    asm volatile("cp.async.cg.shared.global [%0], [%1], 16;" \
        :: "r"(dst_u32), "l"(src_ptr))
#define CP_COMMIT() asm volatile("cp.async.commit_group;" ::: "memory")
#define CP_WAIT_ALL() asm volatile("cp.async.wait_group 0;" ::: "memory")

#define LDSM_X4(r0, r1, r2, r3, addr) \
    asm volatile("ldmatrix.sync.aligned.m8n8.x4.shared.b16 {%0,%1,%2,%3}, [%4];" \
        : "=r"(r0), "=r"(r1), "=r"(r2), "=r"(r3) : "r"(addr))
#define LDSM_X4_T(r0, r1, r2, r3, addr) \
    asm volatile("ldmatrix.sync.aligned.m8n8.x4.trans.shared.b16 {%0,%1,%2,%3}, [%4];" \
        : "=r"(r0), "=r"(r1), "=r"(r2), "=r"(r3) : "r"(addr))

// ---------------------------------------------------------------------------
// LayerNorm: one block per row of 768
// ---------------------------------------------------------------------------
__global__ void ln_kernel(const float* __restrict__ x,
                          const float* __restrict__ w,
                          float* __restrict__ y)
{
    const int row = blockIdx.x;
    const float* xr = x + (size_t)row * DIM;
    float v[3];
    float s = 0.f, s2 = 0.f;
#pragma unroll
    for (int t = 0; t < 3; t++) {
        int i = threadIdx.x + t * 256;
        float vv = xr[i];
        v[t] = vv;
        s += vv; s2 += vv * vv;
    }
#pragma unroll
    for (int o = 16; o > 0; o >>= 1) {
        s  += __shfl_xor_sync(0xffffffffu, s,  o);
        s2 += __shfl_xor_sync(0xffffffffu, s2, o);
    }
    __shared__ float rs[8], rs2[8];
    int wid = threadIdx.x >> 5, lid = threadIdx.x & 31;
    if (lid == 0) { rs[wid] = s; rs2[wid] = s2; }
    __syncthreads();
    if (wid == 0) {
        s  = (lid < 8) ? rs[lid]  : 0.f;
        s2 = (lid < 8) ? rs2[lid] : 0.f;
#pragma unroll
        for (int o = 4; o > 0; o >>= 1) {
            s  += __shfl_xor_sync(0xffffffffu, s,  o);
            s2 += __shfl_xor_sync(0xffffffffu, s2, o);
        }
        if (lid == 0) { rs[0] = s; rs2[0] = s2; }
    }
    __syncthreads();
    const float mu   = rs[0] * (1.f / DIM);
    const float var  = rs2[0] * (1.f / DIM) - mu * mu;
    const float rstd = rsqrtf(var + 1e-5f);
    float* yr = y + (size_t)row * DIM;
#pragma unroll
    for (int t = 0; t < 3; t++) {
        int i = threadIdx.x + t * 256;
        yr[i] = (v[t] - mu) * rstd * w[i];
    }
}

// ---------------------------------------------------------------------------
// tf32 tensor-core GEMM: C[M,N] = A[M,K] @ B[K,N].
// out_mode: 0 = fp32 out, 1 = fp16 out, 2 = fp16 out of (acc * SCALE).
// BM=128, BN=128, BK=16, 256 threads = 8 warps (4x2), warp tile 32x64.
// ---------------------------------------------------------------------------
#define GA_ST 20
#define GB_ST 136

__global__ __launch_bounds__(256)
void gemm_tc_kernel(const float* __restrict__ A, const float* __restrict__ B,
                    float* __restrict__ C, int M, int N, int K, int out_mode)
{
    __shared__ float As[2][128 * GA_ST];
    __shared__ float Bs[2][16 * GB_ST];

    const int tid  = threadIdx.x;
    const int wid  = tid >> 5;
    const int lane = tid & 31;
    const int gr   = lane >> 2;
    const int gq   = lane & 3;
    const int wm   = (wid & 3) * 32;
    const int wn   = (wid >> 2) * 64;
    const int m0   = blockIdx.y * 128;
    const int n0   = blockIdx.x * 128;

    float acc[2][8][4];
#pragma unroll
    for (int ms = 0; ms < 2; ms++)
#pragma unroll
        for (int nt = 0; nt < 8; nt++)
#pragma unroll
            for (int i = 0; i < 4; i++) acc[ms][nt][i] = 0.f;

    uint4 pa[2], pb[2];
    const int am[2] = { (tid + 0) >> 2, (tid + 256) >> 2 };
    const int ak[2] = { ((tid + 0) & 3) * 4, ((tid + 256) & 3) * 4 };
    const int br[2] = { (tid + 0) >> 5, (tid + 256) >> 5 };
    const int bc[2] = { ((tid + 0) & 31) * 4, ((tid + 256) & 31) * 4 };

#pragma unroll
    for (int t = 0; t < 2; t++) {
        pa[t] = cvt4(*reinterpret_cast<const float4*>(
            &A[(size_t)(m0 + am[t]) * K + ak[t]]));
        pb[t] = cvt4(*reinterpret_cast<const float4*>(
            &B[(size_t)br[t] * N + n0 + bc[t]]));
    }

    int ib = 0;
    for (int kt = 0; kt < K; kt += 16, ib ^= 1) {
        float* Asb = As[ib];
        float* Bsb = Bs[ib];
#pragma unroll
        for (int t = 0; t < 2; t++) {
            *reinterpret_cast<uint4*>(&Asb[am[t] * GA_ST + ak[t]]) = pa[t];
            *reinterpret_cast<uint4*>(&Bsb[br[t] * GB_ST + bc[t]]) = pb[t];
        }
        __syncthreads();

        if (kt + 16 < K) {
#pragma unroll
            for (int t = 0; t < 2; t++) {
                pa[t] = cvt4(*reinterpret_cast<const float4*>(
                    &A[(size_t)(m0 + am[t]) * K + kt + 16 + ak[t]]));
                pb[t] = cvt4(*reinterpret_cast<const float4*>(
                    &B[(size_t)(kt + 16 + br[t]) * N + n0 + bc[t]]));
            }
        }

#pragma unroll
        for (int ks = 0; ks < 2; ks++) {
            const int k8 = ks * 8;
            uint32_t af[2][4];
#pragma unroll
            for (int ms = 0; ms < 2; ms++) {
                const int mb = wm + ms * 16;
                af[ms][0] = fbits(Asb[(mb + gr    ) * GA_ST + k8 + gq]);
                af[ms][1] = fbits(Asb[(mb + gr + 8) * GA_ST + k8 + gq]);
                af[ms][2] = fbits(Asb[(mb + gr    ) * GA_ST + k8 + 4 + gq]);
                af[ms][3] = fbits(Asb[(mb + gr + 8) * GA_ST + k8 + 4 + gq]);
            }
#pragma unroll
            for (int nt = 0; nt < 8; nt++) {
                uint32_t bf[2];
                bf[0] = fbits(Bsb[(k8 + gq    ) * GB_ST + wn + nt * 8 + gr]);
                bf[1] = fbits(Bsb[(k8 + 4 + gq) * GB_ST + wn + nt * 8 + gr]);
#pragma unroll
                for (int ms = 0; ms < 2; ms++)
                    mma_tf32(acc[ms][nt], af[ms], bf);
            }
        }
    }

    const float alpha = (out_mode == 2) ? SCALE : 1.0f;
    __half* Ch = reinterpret_cast<__half*>(C);
#pragma unroll
    for (int ms = 0; ms < 2; ms++) {
        const int mrow0 = m0 + wm + ms * 16 + gr;
#pragma unroll
        for (int nt = 0; nt < 8; nt++) {
            const int col = n0 + wn + nt * 8 + 2 * gq;
            if (out_mode == 0) {
                *reinterpret_cast<float2*>(&C[(size_t)mrow0 * N + col]) =
                    make_float2(acc[ms][nt][0], acc[ms][nt][1]);
                *reinterpret_cast<float2*>(&C[(size_t)(mrow0 + 8) * N + col]) =
                    make_float2(acc[ms][nt][2], acc[ms][nt][3]);
            } else {
                *reinterpret_cast<__half2*>(&Ch[(size_t)mrow0 * N + col]) =
                    __floats2half2_rn(acc[ms][nt][0] * alpha,
                                      acc[ms][nt][1] * alpha);
                *reinterpret_cast<__half2*>(&Ch[(size_t)(mrow0 + 8) * N + col]) =
                    __floats2half2_rn(acc[ms][nt][2] * alpha,
                                      acc[ms][nt][3] * alpha);
            }
        }
    }
}

// ---------------------------------------------------------------------------
// fp16 mma.sync flash attention with ldmatrix + cp.async double buffering.
// CTA = 128 q-rows of one (b,h), 256 threads = 8 warps; warp owns 16 rows.
// j-tile = 64. All operands fp16 (10 mantissa bits == tf32), fp32 accum.
// Smem rows are 128 B, XOR-swizzled (byte ^= (row&7)<<4) so every LDSM and
// the cp.async 16B chunks are conflict-free.
// Smem: K0 8K | V0 8K | K1 16K.. | V1 | Ps 16K = 49152 B. 2 CTAs/SM.
// ---------------------------------------------------------------------------
#define KOFF0 0
#define VOFF0 8192
#define KOFF1 16384
#define VOFF1 24576
#define POFF  32768
#define ATTN_SMEM_BYTES 49152
#define NTILES (SEQ_J / 64)            // 32

__device__ __forceinline__ void stage_kv_f16(uint32_t sbase, int buf,
                                             const __half* kv_tile, int tid)
{
    const uint32_t kb = sbase + (buf ? KOFF1 : KOFF0);
    const uint32_t vb = sbase + (buf ? VOFF1 : VOFF0);
#pragma unroll
    for (int t = 0; t < 4; t++) {
        const int e   = tid + t * 256;   // 0..1023 16B chunks
        const int jj  = e >> 4;          // kv row (64 rows x 256B)
        const int c16 = e & 15;          // 16B chunk within row
        const char* src = reinterpret_cast<const char*>(kv_tile)
                          + (size_t)jj * 256 + c16 * 16;
        const uint32_t sw = (uint32_t)(jj & 7) << 4;
        const uint32_t dst = (c16 < 8)
            ? kb + (uint32_t)jj * 128 + (((uint32_t)c16 * 16) ^ sw)
            : vb + (uint32_t)jj * 128 + (((uint32_t)(c16 - 8) * 16) ^ sw);
        CP_ASYNC16(dst, src);
    }
    CP_COMMIT();
}

__global__ __launch_bounds__(256, 2)
void attn_f16_kernel(const __half* __restrict__ q,
                     const __half* __restrict__ kv,
                     const float* __restrict__ mask, float* __restrict__ o)
{
    extern __shared__ char smc[];
    const uint32_t sbase = smem_to_u32(smc);
    char* Ps = smc + POFF;

    const int tid  = threadIdx.x;
    const int wid  = tid >> 5;
    const int lane = tid & 31;
    const int gr   = lane >> 2;
    const int gq   = lane & 3;
    const int g8   = lane >> 3;      // ldmatrix lane group 0..3
    const int r8   = lane & 7;       // row within group
    const int h    = blockIdx.y;
    const int b    = blockIdx.z;
    const int row0 = blockIdx.x * 128;
    const int qrb  = row0 + wid * 16;

    // ---- Q fragments: fp16, pre-scaled by Wq epilogue. 4 k-steps x 4 regs.
    uint32_t qf[4][4];
    {
        const __half* qb = q + ((size_t)(b * SEQ_N) + qrb) * INNER + h * DHEAD;
#pragma unroll
        for (int c = 0; c < 4; c++) {
            qf[c][0] = *reinterpret_cast<const uint32_t*>(
                &qb[(size_t)(gr    ) * INNER + c * 16 + 2 * gq]);
            qf[c][1] = *reinterpret_cast<const uint32_t*>(
                &qb[(size_t)(gr + 8) * INNER + c * 16 + 2 * gq]);
            qf[c][2] = *reinterpret_cast<const uint32_t*>(
                &qb[(size_t)(gr    ) * INNER + c * 16 + 8 + 2 * gq]);
            qf[c][3] = *reinterpret_cast<const uint32_t*>(
                &qb[(size_t)(gr + 8) * INNER + c * 16 + 8 + 2 * gq]);
        }
    }

    float oacc[8][4];
#pragma unroll
    for (int nt = 0; nt < 8; nt++)
#pragma unroll
        for (int i = 0; i < 4; i++) oacc[nt][i] = 0.f;
    float l0 = 0.f, l1 = 0.f;

    const float* m0p = mask + ((size_t)(b * SEQ_N) + qrb + gr) * SEQ_J + 2 * gq;
    const __half* kv_base = kv + (size_t)b * SEQ_J * 128;

    // ---- ldmatrix lane-address components ----
    // K (non-trans): matrix g: j = ntp*16 + ((g>>1)<<3) + r8 ; 16B-col = (c*2+(g&1)) ^ r8
    const uint32_t kj    = (uint32_t)(((g8 >> 1) << 3) + r8);
    const uint32_t kcsel = (uint32_t)(g8 & 1);
    // V (trans): matrix g: j = c*16 + ((g&1)<<3) + r8 ; 16B-col = (ntp*2+(g>>1)) ^ r8
    const uint32_t vj    = (uint32_t)(((g8 & 1) << 3) + r8);
    const uint32_t vcsel = (uint32_t)(g8 >> 1);
    // P (non-trans, A-op): row = wid*16 + ((g&1)<<3) + r8 ; 16B-col = (c*2+(g>>1)) ^ r8
    const uint32_t prow  = (uint32_t)(wid * 16 + ((g8 & 1) << 3) + r8);
    const uint32_t pbaseA = sbase + POFF + prow * 128;
    const uint32_t pcsel  = (uint32_t)(g8 >> 1);

    // P store bases (softmax): rows wid*16+gr and +8; swizzle XOR = gr<<4
    const uint32_t psw = (uint32_t)gr << 4;
    char* ps0 = Ps + (wid * 16 + gr) * 128;
    char* ps1 = ps0 + 8 * 128;

    // ---- prologue: stage tile 0 ----
    stage_kv_f16(sbase, 0, kv_base, tid);

#pragma unroll 1
    for (int t = 0; t < NTILES; t++) {
        const int cur = t & 1;

        CP_WAIT_ALL();
        __syncthreads();

        if (t + 1 < NTILES)
            stage_kv_f16(sbase, cur ^ 1,
                         kv_base + (size_t)(t + 1) * 64 * 128, tid);

        const uint32_t Kb = sbase + (cur ? KOFF1 : KOFF0);
        const uint32_t Vb = sbase + (cur ? VOFF1 : VOFF0);

        // ---- S = Q @ K^T : 4 k-steps of 16 ----
        float sacc[8][4];
#pragma unroll
        for (int nt = 0; nt < 8; nt++)
#pragma unroll
            for (int i = 0; i < 4; i++) sacc[nt][i] = 0.f;

#pragma unroll
        for (int c = 0; c < 4; c++) {
            uint32_t kb2[8][2];
#pragma unroll
            for (int ntp = 0; ntp < 4; ntp++) {
                const uint32_t a = Kb + (ntp * 16 + kj) * 128
                    + ((((uint32_t)(c * 2) + kcsel) ^ (uint32_t)r8) << 4);
                LDSM_X4(kb2[2 * ntp][0], kb2[2 * ntp][1],
                        kb2[2 * ntp + 1][0], kb2[2 * ntp + 1][1], a);
            }
#pragma unroll
            for (int nt = 0; nt < 8; nt++)
                mma_f16(sacc[nt], qf[c], kb2[nt][0], kb2[nt][1]);
        }

        // ---- softmax (unstabilized) with inline mask loads; P -> smem fp16
        {
            const float* mrow = m0p + t * 64;
#pragma unroll
            for (int nt = 0; nt < 8; nt++) {
                float2 mk0 = *reinterpret_cast<const float2*>(&mrow[nt * 8]);
                float2 mk1 = *reinterpret_cast<const float2*>(
                    &mrow[(size_t)8 * SEQ_J + nt * 8]);
                float p00 = __expf(sacc[nt][0] + mk0.x);
                float p01 = __expf(sacc[nt][1] + mk0.y);
                float p10 = __expf(sacc[nt][2] + mk1.x);
                float p11 = __expf(sacc[nt][3] + mk1.y);
                l0 += p00 + p01;
                l1 += p10 + p11;
                const uint32_t off = ((uint32_t)(nt * 16 + gq * 4)) ^ psw;
                *reinterpret_cast<__half2*>(ps0 + off) =
                    __floats2half2_rn(p00, p01);
                *reinterpret_cast<__half2*>(ps1 + off) =
                    __floats2half2_rn(p10, p11);
            }
        }
        __syncwarp();

        // ---- O += P @ V : 4 k-steps of 16 ----
#pragma unroll
        for (int c = 0; c < 4; c++) {
            uint32_t pa[4];
            {
                const uint32_t a = pbaseA
                    + ((((uint32_t)(c * 2) + pcsel) ^ (uint32_t)r8) << 4);
                LDSM_X4(pa[0], pa[1], pa[2], pa[3], a);
            }
            uint32_t vb2[8][2];
#pragma unroll
            for (int ntp = 0; ntp < 4; ntp++) {
                const uint32_t a = Vb + (c * 16 + vj) * 128
                    + ((((uint32_t)(ntp * 2) + vcsel) ^ (uint32_t)r8) << 4);
                LDSM_X4_T(vb2[2 * ntp][0], vb2[2 * ntp][1],
                          vb2[2 * ntp + 1][0], vb2[2 * ntp + 1][1], a);
            }
#pragma unroll
            for (int nt = 0; nt < 8; nt++)
                mma_f16(oacc[nt], pa, vb2[nt][0], vb2[nt][1]);
        }
    }

    // ---- finalize: reduce l over quad lanes, normalize, store ----
    l0 += __shfl_xor_sync(0xffffffffu, l0, 1);
    l0 += __shfl_xor_sync(0xffffffffu, l0, 2);
    l1 += __shfl_xor_sync(0xffffffffu, l1, 1);
    l1 += __shfl_xor_sync(0xffffffffu, l1, 2);
    const float inv0 = 1.f / l0;
    const float inv1 = 1.f / l1;

    float* ob = o + ((size_t)(b * SEQ_N) + qrb) * INNER + h * DHEAD;
#pragma unroll
    for (int nt = 0; nt < 8; nt++) {
        const int cb = nt * 8 + 2 * gq;
        *reinterpret_cast<float2*>(&ob[(size_t)gr * INNER + cb]) =
            make_float2(oacc[nt][0] * inv0, oacc[nt][1] * inv0);
        *reinterpret_cast<float2*>(&ob[(size_t)(gr + 8) * INNER + cb]) =
            make_float2(oacc[nt][2] * inv1, oacc[nt][3] * inv1);
    }
}

// ---------------------------------------------------------------------------
// Launch
// ---------------------------------------------------------------------------
extern "C" void kernel_launch(void* const* d_in, const int* in_sizes, int n_in,
                              void* d_out, int out_size)
{
    const float* x       = (const float*)d_in[0];
    const float* context = (const float*)d_in[1];
    const float* mask    = (const float*)d_in[2];
    const float* ln_w    = (const float*)d_in[3];
    const float* Wq      = (const float*)d_in[4];
    const float* Wkv     = (const float*)d_in[5];
    const float* Wo      = (const float*)d_in[6];
    float* out = (float*)d_out;

    float *xn, *ao;
    __half *qh, *kvh;
    cudaGetSymbolAddress((void**)&xn,  g_xn);
    cudaGetSymbolAddress((void**)&qh,  g_qh);
    cudaGetSymbolAddress((void**)&kvh, g_kvh);
    cudaGetSymbolAddress((void**)&ao,  g_ao);

    cudaFuncSetAttribute(attn_f16_kernel,
                         cudaFuncAttributeMaxDynamicSharedMemorySize,
                         ATTN_SMEM_BYTES);

    // 1. layernorm
    ln_kernel<<<ROWS_TOTAL, 256>>>(x, ln_w, xn);

    // 2. q = ln(x) @ Wq -> fp16, pre-scaled (out_mode=2)
    gemm_tc_kernel<<<dim3(INNER / 128, ROWS_TOTAL / 128), 256>>>(
        xn, Wq, (float*)qh, ROWS_TOTAL, INNER, DIM, 2);

    // 3. kv = context @ Wkv -> fp16 (out_mode=1)
    gemm_tc_kernel<<<dim3(128 / 128, ROWS_TOTAL / 128), 256>>>(
        context, Wkv, (float*)kvh, ROWS_TOTAL, 128, DIM, 1);

    // 4. attention (fp16 mma.sync + ldmatrix, cp.async, 2 CTAs/SM)
    attn_f16_kernel<<<dim3(SEQ_N / 128, HEADS, BATCH), 256, ATTN_SMEM_BYTES>>>(
        qh, kvh, mask, ao);

    // 5. out = ao @ Wo (fp32 out)
    gemm_tc_kernel<<<dim3(DIM / 128, ROWS_TOTAL / 128), 256>>>(
        ao, Wo, out, ROWS_TOTAL, DIM, INNER, 0);
}

// round 12
// speedup vs baseline: 7.0890x; 1.2088x over previous
#include <cuda_runtime.h>
#include <cuda_fp16.h>
#include <cstdint>
#include <math.h>

// Problem constants
#define BATCH   4
#define SEQ_N   2048
#define SEQ_J   2048
#define DIM     768
#define HEADS   12
#define DHEAD   64
#define INNER   (HEADS * DHEAD)   // 768
#define SCALE   0.125f            // 64^-0.5

#define ROWS_TOTAL (BATCH * SEQ_N) // 8192

// ---------------------------------------------------------------------------
// Scratch (static device allocations; no cudaMalloc allowed)
// ---------------------------------------------------------------------------
__device__ __half g_xnh [(size_t)ROWS_TOTAL * DIM];    // layernorm(x), fp16
__device__ __half g_ctxh[(size_t)ROWS_TOTAL * DIM];    // context, fp16
__device__ __half g_qh  [(size_t)ROWS_TOTAL * INNER];  // q, fp16, pre-scaled
__device__ __half g_kvh [(size_t)ROWS_TOTAL * 128];    // [k|v] fp16
__device__ __half g_aoh [(size_t)ROWS_TOTAL * INNER];  // attn output, fp16

// ===========================================================================
// helpers (sm_80+ portable PTX — compiles for plain sm_103)
// ===========================================================================
__device__ __forceinline__ void mma_f16(float* d, const uint32_t* a,
                                        uint32_t b0, uint32_t b1) {
    asm volatile(
        "mma.sync.aligned.m16n8k16.row.col.f32.f16.f16.f32 "
        "{%0,%1,%2,%3}, {%4,%5,%6,%7}, {%8,%9}, {%0,%1,%2,%3};"
        : "+f"(d[0]), "+f"(d[1]), "+f"(d[2]), "+f"(d[3])
        : "r"(a[0]), "r"(a[1]), "r"(a[2]), "r"(a[3]), "r"(b0), "r"(b1));
}
__device__ __forceinline__ uint32_t smem_to_u32(const void* p) {
    uint32_t a;
    asm("{ .reg .u64 t; cvta.to.shared.u64 t, %1; cvt.u32.u64 %0, t; }"
        : "=r"(a) : "l"(p));
    return a;
}
__device__ __forceinline__ uint32_t h2bits(__half2 h) {
    return *reinterpret_cast<uint32_t*>(&h);
}
#define CP_ASYNC16(dst_u32, src_ptr) \
    asm volatile("cp.async.cg.shared.global [%0], [%1], 16;" \
        :: "r"(dst_u32), "l"(src_ptr))
#define CP_COMMIT() asm volatile("cp.async.commit_group;" ::: "memory")
#define CP_WAIT_ALL() asm volatile("cp.async.wait_group 0;" ::: "memory")

#define LDSM_X4(r0, r1, r2, r3, addr) \
    asm volatile("ldmatrix.sync.aligned.m8n8.x4.shared.b16 {%0,%1,%2,%3}, [%4];" \
        : "=r"(r0), "=r"(r1), "=r"(r2), "=r"(r3) : "r"(addr))
#define LDSM_X4_T(r0, r1, r2, r3, addr) \
    asm volatile("ldmatrix.sync.aligned.m8n8.x4.trans.shared.b16 {%0,%1,%2,%3}, [%4];" \
        : "=r"(r0), "=r"(r1), "=r"(r2), "=r"(r3) : "r"(addr))

// ---------------------------------------------------------------------------
// LayerNorm: one block per row of 768, fp16 output
// ---------------------------------------------------------------------------
__global__ void ln_kernel(const float* __restrict__ x,
                          const float* __restrict__ w,
                          __half* __restrict__ y)
{
    const int row = blockIdx.x;
    const float* xr = x + (size_t)row * DIM;
    float v[3];
    float s = 0.f, s2 = 0.f;
#pragma unroll
    for (int t = 0; t < 3; t++) {
        int i = threadIdx.x + t * 256;
        float vv = xr[i];
        v[t] = vv;
        s += vv; s2 += vv * vv;
    }
#pragma unroll
    for (int o = 16; o > 0; o >>= 1) {
        s  += __shfl_xor_sync(0xffffffffu, s,  o);
        s2 += __shfl_xor_sync(0xffffffffu, s2, o);
    }
    __shared__ float rs[8], rs2[8];
    int wid = threadIdx.x >> 5, lid = threadIdx.x & 31;
    if (lid == 0) { rs[wid] = s; rs2[wid] = s2; }
    __syncthreads();
    if (wid == 0) {
        s  = (lid < 8) ? rs[lid]  : 0.f;
        s2 = (lid < 8) ? rs2[lid] : 0.f;
#pragma unroll
        for (int o = 4; o > 0; o >>= 1) {
            s  += __shfl_xor_sync(0xffffffffu, s,  o);
            s2 += __shfl_xor_sync(0xffffffffu, s2, o);
        }
        if (lid == 0) { rs[0] = s; rs2[0] = s2; }
    }
    __syncthreads();
    const float mu   = rs[0] * (1.f / DIM);
    const float var  = rs2[0] * (1.f / DIM) - mu * mu;
    const float rstd = rsqrtf(var + 1e-5f);
    __half* yr = y + (size_t)row * DIM;
#pragma unroll
    for (int t = 0; t < 3; t++) {
        int i = threadIdx.x + t * 256;
        yr[i] = __float2half_rn((v[t] - mu) * rstd * w[i]);
    }
}

// ---------------------------------------------------------------------------
// fp32 -> fp16 elementwise convert (for context)
// ---------------------------------------------------------------------------
__global__ void f32_to_f16_kernel(const float* __restrict__ src,
                                  __half* __restrict__ dst, int n4)
{
    int i = blockIdx.x * blockDim.x + threadIdx.x;
    if (i < n4) {
        float4 v = reinterpret_cast<const float4*>(src)[i];
        __half2 h0 = __floats2half2_rn(v.x, v.y);
        __half2 h1 = __floats2half2_rn(v.z, v.w);
        reinterpret_cast<uint2*>(dst)[i] = make_uint2(h2bits(h0), h2bits(h1));
    }
}

// ---------------------------------------------------------------------------
// fp16 tensor-core GEMM: C[M,N] = A[M,K](fp16) @ B[K,N](fp32->fp16 staged).
// out_mode: 0 = fp32 out, 1 = fp16 out, 2 = fp16 out of (acc * SCALE).
// BM=128, BN=128, BK=32, 256 threads = 8 warps (4x2), warp tile 32x64.
// A smem: [128][40] halfs (80B rows, LDSM-conflict-free). B smem: [32][128]
// halfs, 256B rows, chunk ^= (k&7) swizzle (validated in attn V path).
// ---------------------------------------------------------------------------
#define AST 40   // halfs per A smem row (80 bytes)

__global__ __launch_bounds__(256)
void gemm_f16_kernel(const __half* __restrict__ A, const float* __restrict__ B,
                     void* __restrict__ Cv, int M, int N, int K, int out_mode)
{
    __shared__ __half As[2][128 * AST];
    __shared__ __half Bs[2][32 * 128];

    const int tid  = threadIdx.x;
    const int wid  = tid >> 5;
    const int lane = tid & 31;
    const int g8   = lane >> 3;
    const int r8   = lane & 7;
    const int gr   = lane >> 2;
    const int gq   = lane & 3;
    const int wm   = (wid & 3) * 32;
    const int wn   = (wid >> 2) * 64;
    const int m0   = blockIdx.y * 128;
    const int n0   = blockIdx.x * 128;

    const uint32_t asb[2] = { smem_to_u32(As[0]), smem_to_u32(As[1]) };
    const uint32_t bsb[2] = { smem_to_u32(Bs[0]), smem_to_u32(Bs[1]) };

    float acc[2][8][4];
#pragma unroll
    for (int ms = 0; ms < 2; ms++)
#pragma unroll
        for (int nt = 0; nt < 8; nt++)
#pragma unroll
            for (int i = 0; i < 4; i++) acc[ms][nt][i] = 0.f;

    // staging indices (512 16B-chunks each for A and B)
    int am_[2], aj_[2], bk_[2], bc_[2];
#pragma unroll
    for (int t = 0; t < 2; t++) {
        const int e = tid + t * 256;
        am_[t] = e >> 2;  aj_[t] = e & 3;    // A: row, 16B chunk (8 halfs)
        bk_[t] = e >> 4;  bc_[t] = e & 15;   // B: k row, 16B chunk (8 halfs)
    }

    // prefetch regs
    uint4 pa[2], pbh[2];
    auto load_b_chunk = [&](int t, int kt) {
        const float* src = &B[(size_t)(kt + bk_[t]) * N + n0 + bc_[t] * 8];
        float4 f0 = *reinterpret_cast<const float4*>(src);
        float4 f1 = *reinterpret_cast<const float4*>(src + 4);
        pbh[t] = make_uint4(h2bits(__floats2half2_rn(f0.x, f0.y)),
                            h2bits(__floats2half2_rn(f0.z, f0.w)),
                            h2bits(__floats2half2_rn(f1.x, f1.y)),
                            h2bits(__floats2half2_rn(f1.z, f1.w)));
    };
#pragma unroll
    for (int t = 0; t < 2; t++) {
        pa[t] = *reinterpret_cast<const uint4*>(
            &A[(size_t)(m0 + am_[t]) * K + aj_[t] * 8]);
        load_b_chunk(t, 0);
    }

    // A fragment lane address components
    const uint32_t arow = (uint32_t)(wm + ((g8 & 1) << 3) + r8);   // + ms*16
    const uint32_t akc  = (uint32_t)(g8 >> 1);                     // + c*2
    // B fragment lane address components (trans)
    const uint32_t bkrow = (uint32_t)(((g8 & 1) << 3) + r8);       // + c*16
    const uint32_t bnc   = (uint32_t)((wn >> 3) + (g8 >> 1));      // + ntp*2

    int ib = 0;
    for (int kt = 0; kt < K; kt += 32, ib ^= 1) {
        // store staged chunks
#pragma unroll
        for (int t = 0; t < 2; t++) {
            *reinterpret_cast<uint4*>(&As[ib][am_[t] * AST + aj_[t] * 8]) = pa[t];
            *reinterpret_cast<uint4*>(
                &Bs[ib][bk_[t] * 128 + ((bc_[t] ^ (bk_[t] & 7)) * 8)]) = pbh[t];
        }
        __syncthreads();

        if (kt + 32 < K) {
#pragma unroll
            for (int t = 0; t < 2; t++) {
                pa[t] = *reinterpret_cast<const uint4*>(
                    &A[(size_t)(m0 + am_[t]) * K + kt + 32 + aj_[t] * 8]);
                load_b_chunk(t, kt + 32);
            }
        }

#pragma unroll
        for (int c = 0; c < 2; c++) {
            uint32_t af[2][4];
#pragma unroll
            for (int ms = 0; ms < 2; ms++) {
                const uint32_t a = asb[ib] + (arow + ms * 16) * (AST * 2)
                                 + (c * 2 + akc) * 16;
                LDSM_X4(af[ms][0], af[ms][1], af[ms][2], af[ms][3], a);
            }
            uint32_t bf[8][2];
#pragma unroll
            for (int ntp = 0; ntp < 4; ntp++) {
                const uint32_t row = (uint32_t)(c * 16) + bkrow;
                const uint32_t a = bsb[ib] + row * 256
                                 + (((bnc + ntp * 2) ^ (uint32_t)r8) << 4);
                LDSM_X4_T(bf[2 * ntp][0], bf[2 * ntp][1],
                          bf[2 * ntp + 1][0], bf[2 * ntp + 1][1], a);
            }
#pragma unroll
            for (int nt = 0; nt < 8; nt++)
#pragma unroll
                for (int ms = 0; ms < 2; ms++)
                    mma_f16(acc[ms][nt], af[ms], bf[nt][0], bf[nt][1]);
        }
        __syncthreads();
    }

    const float alpha = (out_mode == 2) ? SCALE : 1.0f;
    float*  Cf = reinterpret_cast<float*>(Cv);
    __half* Ch = reinterpret_cast<__half*>(Cv);
#pragma unroll
    for (int ms = 0; ms < 2; ms++) {
        const int mrow0 = m0 + wm + ms * 16 + gr;
#pragma unroll
        for (int nt = 0; nt < 8; nt++) {
            const int col = n0 + wn + nt * 8 + 2 * gq;
            if (out_mode == 0) {
                *reinterpret_cast<float2*>(&Cf[(size_t)mrow0 * N + col]) =
                    make_float2(acc[ms][nt][0], acc[ms][nt][1]);
                *reinterpret_cast<float2*>(&Cf[(size_t)(mrow0 + 8) * N + col]) =
                    make_float2(acc[ms][nt][2], acc[ms][nt][3]);
            } else {
                *reinterpret_cast<__half2*>(&Ch[(size_t)mrow0 * N + col]) =
                    __floats2half2_rn(acc[ms][nt][0] * alpha,
                                      acc[ms][nt][1] * alpha);
                *reinterpret_cast<__half2*>(&Ch[(size_t)(mrow0 + 8) * N + col]) =
                    __floats2half2_rn(acc[ms][nt][2] * alpha,
                                      acc[ms][nt][3] * alpha);
            }
        }
    }
}

// ---------------------------------------------------------------------------
// fp16 mma.sync flash attention (unchanged from round 11 except fp16 output).
// ---------------------------------------------------------------------------
#define KOFF0 0
#define VOFF0 8192
#define KOFF1 16384
#define VOFF1 24576
#define POFF  32768
#define ATTN_SMEM_BYTES 49152
#define NTILES (SEQ_J / 64)            // 32

__device__ __forceinline__ void stage_kv_f16(uint32_t sbase, int buf,
                                             const __half* kv_tile, int tid)
{
    const uint32_t kb = sbase + (buf ? KOFF1 : KOFF0);
    const uint32_t vb = sbase + (buf ? VOFF1 : VOFF0);
#pragma unroll
    for (int t = 0; t < 4; t++) {
        const int e   = tid + t * 256;
        const int jj  = e >> 4;
        const int c16 = e & 15;
        const char* src = reinterpret_cast<const char*>(kv_tile)
                          + (size_t)jj * 256 + c16 * 16;
        const uint32_t sw = (uint32_t)(jj & 7) << 4;
        const uint32_t dst = (c16 < 8)
            ? kb + (uint32_t)jj * 128 + (((uint32_t)c16 * 16) ^ sw)
            : vb + (uint32_t)jj * 128 + (((uint32_t)(c16 - 8) * 16) ^ sw);
        CP_ASYNC16(dst, src);
    }
    CP_COMMIT();
}

__global__ __launch_bounds__(256, 2)
void attn_f16_kernel(const __half* __restrict__ q,
                     const __half* __restrict__ kv,
                     const float* __restrict__ mask, __half* __restrict__ o)
{
    extern __shared__ char smc[];
    const uint32_t sbase = smem_to_u32(smc);
    char* Ps = smc + POFF;

    const int tid  = threadIdx.x;
    const int wid  = tid >> 5;
    const int lane = tid & 31;
    const int gr   = lane >> 2;
    const int gq   = lane & 3;
    const int g8   = lane >> 3;
    const int r8   = lane & 7;
    const int h    = blockIdx.y;
    const int b    = blockIdx.z;
    const int row0 = blockIdx.x * 128;
    const int qrb  = row0 + wid * 16;

    uint32_t qf[4][4];
    {
        const __half* qb = q + ((size_t)(b * SEQ_N) + qrb) * INNER + h * DHEAD;
#pragma unroll
        for (int c = 0; c < 4; c++) {
            qf[c][0] = *reinterpret_cast<const uint32_t*>(
                &qb[(size_t)(gr    ) * INNER + c * 16 + 2 * gq]);
            qf[c][1] = *reinterpret_cast<const uint32_t*>(
                &qb[(size_t)(gr + 8) * INNER + c * 16 + 2 * gq]);
            qf[c][2] = *reinterpret_cast<const uint32_t*>(
                &qb[(size_t)(gr    ) * INNER + c * 16 + 8 + 2 * gq]);
            qf[c][3] = *reinterpret_cast<const uint32_t*>(
                &qb[(size_t)(gr + 8) * INNER + c * 16 + 8 + 2 * gq]);
        }
    }

    float oacc[8][4];
#pragma unroll
    for (int nt = 0; nt < 8; nt++)
#pragma unroll
        for (int i = 0; i < 4; i++) oacc[nt][i] = 0.f;
    float l0 = 0.f, l1 = 0.f;

    const float* m0p = mask + ((size_t)(b * SEQ_N) + qrb + gr) * SEQ_J + 2 * gq;
    const __half* kv_base = kv + (size_t)b * SEQ_J * 128;

    const uint32_t kj    = (uint32_t)(((g8 >> 1) << 3) + r8);
    const uint32_t kcsel = (uint32_t)(g8 & 1);
    const uint32_t vj    = (uint32_t)(((g8 & 1) << 3) + r8);
    const uint32_t vcsel = (uint32_t)(g8 >> 1);
    const uint32_t prow  = (uint32_t)(wid * 16 + ((g8 & 1) << 3) + r8);
    const uint32_t pbaseA = sbase + POFF + prow * 128;
    const uint32_t pcsel  = (uint32_t)(g8 >> 1);

    const uint32_t psw = (uint32_t)gr << 4;
    char* ps0 = Ps + (wid * 16 + gr) * 128;
    char* ps1 = ps0 + 8 * 128;

    stage_kv_f16(sbase, 0, kv_base, tid);

#pragma unroll 1
    for (int t = 0; t < NTILES; t++) {
        const int cur = t & 1;

        CP_WAIT_ALL();
        __syncthreads();

        if (t + 1 < NTILES)
            stage_kv_f16(sbase, cur ^ 1,
                         kv_base + (size_t)(t + 1) * 64 * 128, tid);

        const uint32_t Kb = sbase + (cur ? KOFF1 : KOFF0);
        const uint32_t Vb = sbase + (cur ? VOFF1 : VOFF0);

        float sacc[8][4];
#pragma unroll
        for (int nt = 0; nt < 8; nt++)
#pragma unroll
            for (int i = 0; i < 4; i++) sacc[nt][i] = 0.f;

#pragma unroll
        for (int c = 0; c < 4; c++) {
            uint32_t kb2[8][2];
#pragma unroll
            for (int ntp = 0; ntp < 4; ntp++) {
                const uint32_t a = Kb + (ntp * 16 + kj) * 128
                    + ((((uint32_t)(c * 2) + kcsel) ^ (uint32_t)r8) << 4);
                LDSM_X4(kb2[2 * ntp][0], kb2[2 * ntp][1],
                        kb2[2 * ntp + 1][0], kb2[2 * ntp + 1][1], a);
            }
#pragma unroll
            for (int nt = 0; nt < 8; nt++)
                mma_f16(sacc[nt], qf[c], kb2[nt][0], kb2[nt][1]);
        }

        {
            const float* mrow = m0p + t * 64;
#pragma unroll
            for (int nt = 0; nt < 8; nt++) {
                float2 mk0 = *reinterpret_cast<const float2*>(&mrow[nt * 8]);
                float2 mk1 = *reinterpret_cast<const float2*>(
                    &mrow[(size_t)8 * SEQ_J + nt * 8]);
                float p00 = __expf(sacc[nt][0] + mk0.x);
                float p01 = __expf(sacc[nt][1] + mk0.y);
                float p10 = __expf(sacc[nt][2] + mk1.x);
                float p11 = __expf(sacc[nt][3] + mk1.y);
                l0 += p00 + p01;
                l1 += p10 + p11;
                const uint32_t off = ((uint32_t)(nt * 16 + gq * 4)) ^ psw;
                *reinterpret_cast<__half2*>(ps0 + off) =
                    __floats2half2_rn(p00, p01);
                *reinterpret_cast<__half2*>(ps1 + off) =
                    __floats2half2_rn(p10, p11);
            }
        }
        __syncwarp();

#pragma unroll
        for (int c = 0; c < 4; c++) {
            uint32_t pa[4];
            {
                const uint32_t a = pbaseA
                    + ((((uint32_t)(c * 2) + pcsel) ^ (uint32_t)r8) << 4);
                LDSM_X4(pa[0], pa[1], pa[2], pa[3], a);
            }
            uint32_t vb2[8][2];
#pragma unroll
            for (int ntp = 0; ntp < 4; ntp++) {
                const uint32_t a = Vb + (c * 16 + vj) * 128
                    + ((((uint32_t)(ntp * 2) + vcsel) ^ (uint32_t)r8) << 4);
                LDSM_X4_T(vb2[2 * ntp][0], vb2[2 * ntp][1],
                          vb2[2 * ntp + 1][0], vb2[2 * ntp + 1][1], a);
            }
#pragma unroll
            for (int nt = 0; nt < 8; nt++)
                mma_f16(oacc[nt], pa, vb2[nt][0], vb2[nt][1]);
        }
    }

    l0 += __shfl_xor_sync(0xffffffffu, l0, 1);
    l0 += __shfl_xor_sync(0xffffffffu, l0, 2);
    l1 += __shfl_xor_sync(0xffffffffu, l1, 1);
    l1 += __shfl_xor_sync(0xffffffffu, l1, 2);
    const float inv0 = 1.f / l0;
    const float inv1 = 1.f / l1;

    __half* ob = o + ((size_t)(b * SEQ_N) + qrb) * INNER + h * DHEAD;
#pragma unroll
    for (int nt = 0; nt < 8; nt++) {
        const int cb = nt * 8 + 2 * gq;
        *reinterpret_cast<__half2*>(&ob[(size_t)gr * INNER + cb]) =
            __floats2half2_rn(oacc[nt][0] * inv0, oacc[nt][1] * inv0);
        *reinterpret_cast<__half2*>(&ob[(size_t)(gr + 8) * INNER + cb]) =
            __floats2half2_rn(oacc[nt][2] * inv1, oacc[nt][3] * inv1);
    }
}

// ---------------------------------------------------------------------------
// Launch
// ---------------------------------------------------------------------------
extern "C" void kernel_launch(void* const* d_in, const int* in_sizes, int n_in,
                              void* d_out, int out_size)
{
    const float* x       = (const float*)d_in[0];
    const float* context = (const float*)d_in[1];
    const float* mask    = (const float*)d_in[2];
    const float* ln_w    = (const float*)d_in[3];
    const float* Wq      = (const float*)d_in[4];
    const float* Wkv     = (const float*)d_in[5];
    const float* Wo      = (const float*)d_in[6];
    float* out = (float*)d_out;

    __half *xnh, *ctxh, *qh, *kvh, *aoh;
    cudaGetSymbolAddress((void**)&xnh,  g_xnh);
    cudaGetSymbolAddress((void**)&ctxh, g_ctxh);
    cudaGetSymbolAddress((void**)&qh,   g_qh);
    cudaGetSymbolAddress((void**)&kvh,  g_kvh);
    cudaGetSymbolAddress((void**)&aoh,  g_aoh);

    cudaFuncSetAttribute(attn_f16_kernel,
                         cudaFuncAttributeMaxDynamicSharedMemorySize,
                         ATTN_SMEM_BYTES);

    // 1. layernorm -> fp16
    ln_kernel<<<ROWS_TOTAL, 256>>>(x, ln_w, xnh);

    // 1b. context -> fp16
    {
        const int n4 = ROWS_TOTAL * DIM / 4;
        f32_to_f16_kernel<<<(n4 + 255) / 256, 256>>>(context, ctxh, n4);
    }

    // 2. q = ln(x) @ Wq -> fp16, pre-scaled (out_mode=2)
    gemm_f16_kernel<<<dim3(INNER / 128, ROWS_TOTAL / 128), 256>>>(
        xnh, Wq, qh, ROWS_TOTAL, INNER, DIM, 2);

    // 3. kv = context @ Wkv -> fp16 (out_mode=1)
    gemm_f16_kernel<<<dim3(128 / 128, ROWS_TOTAL / 128), 256>>>(
        ctxh, Wkv, kvh, ROWS_TOTAL, 128, DIM, 1);

    // 4. attention (fp16 mma.sync + ldmatrix, cp.async, 2 CTAs/SM) -> fp16
    attn_f16_kernel<<<dim3(SEQ_N / 128, HEADS, BATCH), 256, ATTN_SMEM_BYTES>>>(
        qh, kvh, mask, aoh);

    // 5. out = ao @ Wo -> fp32
    gemm_f16_kernel<<<dim3(DIM / 128, ROWS_TOTAL / 128), 256>>>(
        aoh, Wo, out, ROWS_TOTAL, DIM, INNER, 0);
}

// round 13
// speedup vs baseline: 8.0938x; 1.1417x over previous
#include <cuda_runtime.h>
#include <cuda_fp16.h>
#include <cstdint>
#include <math.h>

// Problem constants
#define BATCH   4
#define SEQ_N   2048
#define SEQ_J   2048
#define DIM     768
#define HEADS   12
#define DHEAD   64
#define INNER   (HEADS * DHEAD)   // 768
#define SCALE   0.125f            // 64^-0.5

#define ROWS_TOTAL (BATCH * SEQ_N) // 8192

// ---------------------------------------------------------------------------
// Scratch (static device allocations; no cudaMalloc allowed)
// ---------------------------------------------------------------------------
__device__ __half g_xnh [(size_t)ROWS_TOTAL * DIM];    // layernorm(x), fp16
__device__ __half g_qh  [(size_t)ROWS_TOTAL * INNER];  // q, fp16, pre-scaled
__device__ __half g_kvh [(size_t)ROWS_TOTAL * 128];    // [k|v] fp16
__device__ __half g_aoh [(size_t)ROWS_TOTAL * INNER];  // attn output, fp16

// ===========================================================================
// helpers (sm_80+ portable PTX — compiles for plain sm_103)
// ===========================================================================
__device__ __forceinline__ void mma_f16(float* d, const uint32_t* a,
                                        uint32_t b0, uint32_t b1) {
    asm volatile(
        "mma.sync.aligned.m16n8k16.row.col.f32.f16.f16.f32 "
        "{%0,%1,%2,%3}, {%4,%5,%6,%7}, {%8,%9}, {%0,%1,%2,%3};"
        : "+f"(d[0]), "+f"(d[1]), "+f"(d[2]), "+f"(d[3])
        : "r"(a[0]), "r"(a[1]), "r"(a[2]), "r"(a[3]), "r"(b0), "r"(b1));
}
__device__ __forceinline__ uint32_t smem_to_u32(const void* p) {
    uint32_t a;
    asm("{ .reg .u64 t; cvta.to.shared.u64 t, %1; cvt.u32.u64 %0, t; }"
        : "=r"(a) : "l"(p));
    return a;
}
__device__ __forceinline__ uint32_t h2bits(__half2 h) {
    return *reinterpret_cast<uint32_t*>(&h);
}
#define CP_ASYNC16(dst_u32, src_ptr) \
    asm volatile("cp.async.cg.shared.global [%0], [%1], 16;" \
        :: "r"(dst_u32), "l"(src_ptr))
#define CP_COMMIT() asm volatile("cp.async.commit_group;" ::: "memory")
#define CP_WAIT_ALL() asm volatile("cp.async.wait_group 0;" ::: "memory")

#define LDSM_X4(r0, r1, r2, r3, addr) \
    asm volatile("ldmatrix.sync.aligned.m8n8.x4.shared.b16 {%0,%1,%2,%3}, [%4];" \
        : "=r"(r0), "=r"(r1), "=r"(r2), "=r"(r3) : "r"(addr))
#define LDSM_X4_T(r0, r1, r2, r3, addr) \
    asm volatile("ldmatrix.sync.aligned.m8n8.x4.trans.shared.b16 {%0,%1,%2,%3}, [%4];" \
        : "=r"(r0), "=r"(r1), "=r"(r2), "=r"(r3) : "r"(addr))

// ---------------------------------------------------------------------------
// LayerNorm: one block per row of 768, fp16 output
// ---------------------------------------------------------------------------
__global__ void ln_kernel(const float* __restrict__ x,
                          const float* __restrict__ w,
                          __half* __restrict__ y)
{
    const int row = blockIdx.x;
    const float* xr = x + (size_t)row * DIM;
    float v[3];
    float s = 0.f, s2 = 0.f;
#pragma unroll
    for (int t = 0; t < 3; t++) {
        int i = threadIdx.x + t * 256;
        float vv = xr[i];
        v[t] = vv;
        s += vv; s2 += vv * vv;
    }
#pragma unroll
    for (int o = 16; o > 0; o >>= 1) {
        s  += __shfl_xor_sync(0xffffffffu, s,  o);
        s2 += __shfl_xor_sync(0xffffffffu, s2, o);
    }
    __shared__ float rs[8], rs2[8];
    int wid = threadIdx.x >> 5, lid = threadIdx.x & 31;
    if (lid == 0) { rs[wid] = s; rs2[wid] = s2; }
    __syncthreads();
    if (wid == 0) {
        s  = (lid < 8) ? rs[lid]  : 0.f;
        s2 = (lid < 8) ? rs2[lid] : 0.f;
#pragma unroll
        for (int o = 4; o > 0; o >>= 1) {
            s  += __shfl_xor_sync(0xffffffffu, s,  o);
            s2 += __shfl_xor_sync(0xffffffffu, s2, o);
        }
        if (lid == 0) { rs[0] = s; rs2[0] = s2; }
    }
    __syncthreads();
    const float mu   = rs[0] * (1.f / DIM);
    const float var  = rs2[0] * (1.f / DIM) - mu * mu;
    const float rstd = rsqrtf(var + 1e-5f);
    __half* yr = y + (size_t)row * DIM;
#pragma unroll
    for (int t = 0; t < 3; t++) {
        int i = threadIdx.x + t * 256;
        yr[i] = __float2half_rn((v[t] - mu) * rstd * w[i]);
    }
}

// ---------------------------------------------------------------------------
// fp16 tensor-core GEMM, dual-job: blockIdx.x < nx0 -> job0, else job1.
// C[M,N] = A[M,K] @ B[K,N]; A fp16 (or fp32 with in-staging convert),
// B fp32 converted in staging. out_mode: 0 fp32, 1 fp16, 2 fp16*(SCALE).
// BM=128, BN=128, BK=32, 256 threads = 8 warps (4x2), warp tile 32x64.
// ---------------------------------------------------------------------------
#define AST 40   // halfs per A smem row (80 bytes)

struct GemmJob {
    const __half* Ah;
    const float*  Af;    // used when a_f32 != 0
    const float*  B;
    void*         C;
    int N, K, out_mode, a_f32;
};

__global__ __launch_bounds__(256)
void gemm_dual_kernel(GemmJob j0, int nx0, GemmJob j1)
{
    __shared__ __half As[2][128 * AST];
    __shared__ __half Bs[2][32 * 128];

    GemmJob jb;
    int bx;
    if ((int)blockIdx.x < nx0) { jb = j0; bx = blockIdx.x; }
    else                       { jb = j1; bx = blockIdx.x - nx0; }
    const int N = jb.N;
    const int K = jb.K;

    const int tid  = threadIdx.x;
    const int wid  = tid >> 5;
    const int lane = tid & 31;
    const int g8   = lane >> 3;
    const int r8   = lane & 7;
    const int gr   = lane >> 2;
    const int gq   = lane & 3;
    const int wm   = (wid & 3) * 32;
    const int wn   = (wid >> 2) * 64;
    const int m0   = blockIdx.y * 128;
    const int n0   = bx * 128;

    const uint32_t asb[2] = { smem_to_u32(As[0]), smem_to_u32(As[1]) };
    const uint32_t bsb[2] = { smem_to_u32(Bs[0]), smem_to_u32(Bs[1]) };

    float acc[2][8][4];
#pragma unroll
    for (int ms = 0; ms < 2; ms++)
#pragma unroll
        for (int nt = 0; nt < 8; nt++)
#pragma unroll
            for (int i = 0; i < 4; i++) acc[ms][nt][i] = 0.f;

    int am_[2], aj_[2], bk_[2], bc_[2];
#pragma unroll
    for (int t = 0; t < 2; t++) {
        const int e = tid + t * 256;
        am_[t] = e >> 2;  aj_[t] = e & 3;
        bk_[t] = e >> 4;  bc_[t] = e & 15;
    }

    uint4 pa[2], pbh[2];
    auto load_a_chunk = [&](int t, int kt) {
        if (jb.a_f32) {
            const float* src = &jb.Af[(size_t)(m0 + am_[t]) * K + kt + aj_[t] * 8];
            float4 f0 = *reinterpret_cast<const float4*>(src);
            float4 f1 = *reinterpret_cast<const float4*>(src + 4);
            pa[t] = make_uint4(h2bits(__floats2half2_rn(f0.x, f0.y)),
                               h2bits(__floats2half2_rn(f0.z, f0.w)),
                               h2bits(__floats2half2_rn(f1.x, f1.y)),
                               h2bits(__floats2half2_rn(f1.z, f1.w)));
        } else {
            pa[t] = *reinterpret_cast<const uint4*>(
                &jb.Ah[(size_t)(m0 + am_[t]) * K + kt + aj_[t] * 8]);
        }
    };
    auto load_b_chunk = [&](int t, int kt) {
        const float* src = &jb.B[(size_t)(kt + bk_[t]) * N + n0 + bc_[t] * 8];
        float4 f0 = *reinterpret_cast<const float4*>(src);
        float4 f1 = *reinterpret_cast<const float4*>(src + 4);
        pbh[t] = make_uint4(h2bits(__floats2half2_rn(f0.x, f0.y)),
                            h2bits(__floats2half2_rn(f0.z, f0.w)),
                            h2bits(__floats2half2_rn(f1.x, f1.y)),
                            h2bits(__floats2half2_rn(f1.z, f1.w)));
    };
#pragma unroll
    for (int t = 0; t < 2; t++) {
        load_a_chunk(t, 0);
        load_b_chunk(t, 0);
    }

    const uint32_t arow  = (uint32_t)(wm + ((g8 & 1) << 3) + r8);
    const uint32_t akc   = (uint32_t)(g8 >> 1);
    const uint32_t bkrow = (uint32_t)(((g8 & 1) << 3) + r8);
    const uint32_t bnc   = (uint32_t)((wn >> 3) + (g8 >> 1));

    int ib = 0;
    for (int kt = 0; kt < K; kt += 32, ib ^= 1) {
#pragma unroll
        for (int t = 0; t < 2; t++) {
            *reinterpret_cast<uint4*>(&As[ib][am_[t] * AST + aj_[t] * 8]) = pa[t];
            *reinterpret_cast<uint4*>(
                &Bs[ib][bk_[t] * 128 + ((bc_[t] ^ (bk_[t] & 7)) * 8)]) = pbh[t];
        }
        __syncthreads();

        if (kt + 32 < K) {
#pragma unroll
            for (int t = 0; t < 2; t++) {
                load_a_chunk(t, kt + 32);
                load_b_chunk(t, kt + 32);
            }
        }

#pragma unroll
        for (int c = 0; c < 2; c++) {
            uint32_t af[2][4];
#pragma unroll
            for (int ms = 0; ms < 2; ms++) {
                const uint32_t a = asb[ib] + (arow + ms * 16) * (AST * 2)
                                 + (c * 2 + akc) * 16;
                LDSM_X4(af[ms][0], af[ms][1], af[ms][2], af[ms][3], a);
            }
            uint32_t bf[8][2];
#pragma unroll
            for (int ntp = 0; ntp < 4; ntp++) {
                const uint32_t row = (uint32_t)(c * 16) + bkrow;
                const uint32_t a = bsb[ib] + row * 256
                                 + (((bnc + ntp * 2) ^ (uint32_t)r8) << 4);
                LDSM_X4_T(bf[2 * ntp][0], bf[2 * ntp][1],
                          bf[2 * ntp + 1][0], bf[2 * ntp + 1][1], a);
            }
#pragma unroll
            for (int nt = 0; nt < 8; nt++)
#pragma unroll
                for (int ms = 0; ms < 2; ms++)
                    mma_f16(acc[ms][nt], af[ms], bf[nt][0], bf[nt][1]);
        }
        __syncthreads();
    }

    const float alpha = (jb.out_mode == 2) ? SCALE : 1.0f;
    float*  Cf = reinterpret_cast<float*>(jb.C);
    __half* Ch = reinterpret_cast<__half*>(jb.C);
#pragma unroll
    for (int ms = 0; ms < 2; ms++) {
        const int mrow0 = m0 + wm + ms * 16 + gr;
#pragma unroll
        for (int nt = 0; nt < 8; nt++) {
            const int col = n0 + wn + nt * 8 + 2 * gq;
            if (jb.out_mode == 0) {
                *reinterpret_cast<float2*>(&Cf[(size_t)mrow0 * N + col]) =
                    make_float2(acc[ms][nt][0], acc[ms][nt][1]);
                *reinterpret_cast<float2*>(&Cf[(size_t)(mrow0 + 8) * N + col]) =
                    make_float2(acc[ms][nt][2], acc[ms][nt][3]);
            } else {
                *reinterpret_cast<__half2*>(&Ch[(size_t)mrow0 * N + col]) =
                    __floats2half2_rn(acc[ms][nt][0] * alpha,
                                      acc[ms][nt][1] * alpha);
                *reinterpret_cast<__half2*>(&Ch[(size_t)(mrow0 + 8) * N + col]) =
                    __floats2half2_rn(acc[ms][nt][2] * alpha,
                                      acc[ms][nt][3] * alpha);
            }
        }
    }
}

// ---------------------------------------------------------------------------
// fp16 mma.sync flash attention, P kept in registers (FA2 fragment reuse):
// the S C-fragment layout IS the PV A-fragment layout, so softmax packs
// p into half2 registers and PV consumes them directly. No P smem, no
// extra syncs. K/V cp.async double-buffered. Smem = 32 KB, 2 CTAs/SM.
// ---------------------------------------------------------------------------
#define KOFF0 0
#define VOFF0 8192
#define KOFF1 16384
#define VOFF1 24576
#define ATTN_SMEM_BYTES 32768
#define NTILES (SEQ_J / 64)            // 32

__device__ __forceinline__ void stage_kv_f16(uint32_t sbase, int buf,
                                             const __half* kv_tile, int tid)
{
    const uint32_t kb = sbase + (buf ? KOFF1 : KOFF0);
    const uint32_t vb = sbase + (buf ? VOFF1 : VOFF0);
#pragma unroll
    for (int t = 0; t < 4; t++) {
        const int e   = tid + t * 256;
        const int jj  = e >> 4;
        const int c16 = e & 15;
        const char* src = reinterpret_cast<const char*>(kv_tile)
                          + (size_t)jj * 256 + c16 * 16;
        const uint32_t sw = (uint32_t)(jj & 7) << 4;
        const uint32_t dst = (c16 < 8)
            ? kb + (uint32_t)jj * 128 + (((uint32_t)c16 * 16) ^ sw)
            : vb + (uint32_t)jj * 128 + (((uint32_t)(c16 - 8) * 16) ^ sw);
        CP_ASYNC16(dst, src);
    }
    CP_COMMIT();
}

__global__ __launch_bounds__(256, 2)
void attn_f16_kernel(const __half* __restrict__ q,
                     const __half* __restrict__ kv,
                     const float* __restrict__ mask, __half* __restrict__ o)
{
    extern __shared__ char smc[];
    const uint32_t sbase = smem_to_u32(smc);

    const int tid  = threadIdx.x;
    const int wid  = tid >> 5;
    const int lane = tid & 31;
    const int gr   = lane >> 2;
    const int gq   = lane & 3;
    const int g8   = lane >> 3;
    const int r8   = lane & 7;
    const int h    = blockIdx.y;
    const int b    = blockIdx.z;
    const int row0 = blockIdx.x * 128;
    const int qrb  = row0 + wid * 16;

    // ---- Q fragments: fp16, pre-scaled by Wq epilogue. 4 k-steps x 4 regs.
    uint32_t qf[4][4];
    {
        const __half* qb = q + ((size_t)(b * SEQ_N) + qrb) * INNER + h * DHEAD;
#pragma unroll
        for (int c = 0; c < 4; c++) {
            qf[c][0] = *reinterpret_cast<const uint32_t*>(
                &qb[(size_t)(gr    ) * INNER + c * 16 + 2 * gq]);
            qf[c][1] = *reinterpret_cast<const uint32_t*>(
                &qb[(size_t)(gr + 8) * INNER + c * 16 + 2 * gq]);
            qf[c][2] = *reinterpret_cast<const uint32_t*>(
                &qb[(size_t)(gr    ) * INNER + c * 16 + 8 + 2 * gq]);
            qf[c][3] = *reinterpret_cast<const uint32_t*>(
                &qb[(size_t)(gr + 8) * INNER + c * 16 + 8 + 2 * gq]);
        }
    }

    float oacc[8][4];
#pragma unroll
    for (int nt = 0; nt < 8; nt++)
#pragma unroll
        for (int i = 0; i < 4; i++) oacc[nt][i] = 0.f;
    float l0 = 0.f, l1 = 0.f;

    const float* m0p = mask + ((size_t)(b * SEQ_N) + qrb + gr) * SEQ_J + 2 * gq;
    const __half* kv_base = kv + (size_t)b * SEQ_J * 128;

    const uint32_t kj    = (uint32_t)(((g8 >> 1) << 3) + r8);
    const uint32_t kcsel = (uint32_t)(g8 & 1);
    const uint32_t vj    = (uint32_t)(((g8 & 1) << 3) + r8);
    const uint32_t vcsel = (uint32_t)(g8 >> 1);

    stage_kv_f16(sbase, 0, kv_base, tid);

#pragma unroll 1
    for (int t = 0; t < NTILES; t++) {
        const int cur = t & 1;

        CP_WAIT_ALL();
        __syncthreads();

        if (t + 1 < NTILES)
            stage_kv_f16(sbase, cur ^ 1,
                         kv_base + (size_t)(t + 1) * 64 * 128, tid);

        const uint32_t Kb = sbase + (cur ? KOFF1 : KOFF0);
        const uint32_t Vb = sbase + (cur ? VOFF1 : VOFF0);

        // ---- mask prefetch (hidden under S MMAs) ----
        float2 mk0[8], mk1[8];
        {
            const float* mrow = m0p + t * 64;
#pragma unroll
            for (int nt = 0; nt < 8; nt++) {
                mk0[nt] = *reinterpret_cast<const float2*>(&mrow[nt * 8]);
                mk1[nt] = *reinterpret_cast<const float2*>(
                    &mrow[(size_t)8 * SEQ_J + nt * 8]);
            }
        }

        // ---- S = Q @ K^T : 4 k-steps of 16 ----
        float sacc[8][4];
#pragma unroll
        for (int nt = 0; nt < 8; nt++)
#pragma unroll
            for (int i = 0; i < 4; i++) sacc[nt][i] = 0.f;

#pragma unroll
        for (int c = 0; c < 4; c++) {
            uint32_t kb2[8][2];
#pragma unroll
            for (int ntp = 0; ntp < 4; ntp++) {
                const uint32_t a = Kb + (ntp * 16 + kj) * 128
                    + ((((uint32_t)(c * 2) + kcsel) ^ (uint32_t)r8) << 4);
                LDSM_X4(kb2[2 * ntp][0], kb2[2 * ntp][1],
                        kb2[2 * ntp + 1][0], kb2[2 * ntp + 1][1], a);
            }
#pragma unroll
            for (int nt = 0; nt < 8; nt++)
                mma_f16(sacc[nt], qf[c], kb2[nt][0], kb2[nt][1]);
        }

        // ---- softmax (unstabilized) -> P as PV A-fragments in registers ----
        uint32_t pah[8][2];
#pragma unroll
        for (int nt = 0; nt < 8; nt++) {
            float p00 = __expf(sacc[nt][0] + mk0[nt].x);
            float p01 = __expf(sacc[nt][1] + mk0[nt].y);
            float p10 = __expf(sacc[nt][2] + mk1[nt].x);
            float p11 = __expf(sacc[nt][3] + mk1[nt].y);
            l0 += p00 + p01;
            l1 += p10 + p11;
            pah[nt][0] = h2bits(__floats2half2_rn(p00, p01));
            pah[nt][1] = h2bits(__floats2half2_rn(p10, p11));
        }

        // ---- O += P @ V : 4 k-steps of 16, P straight from registers ----
#pragma unroll
        for (int c = 0; c < 4; c++) {
            uint32_t pa[4] = { pah[2 * c][0], pah[2 * c][1],
                               pah[2 * c + 1][0], pah[2 * c + 1][1] };
            uint32_t vb2[8][2];
#pragma unroll
            for (int ntp = 0; ntp < 4; ntp++) {
                const uint32_t a = Vb + (c * 16 + vj) * 128
                    + ((((uint32_t)(ntp * 2) + vcsel) ^ (uint32_t)r8) << 4);
                LDSM_X4_T(vb2[2 * ntp][0], vb2[2 * ntp][1],
                          vb2[2 * ntp + 1][0], vb2[2 * ntp + 1][1], a);
            }
#pragma unroll
            for (int nt = 0; nt < 8; nt++)
                mma_f16(oacc[nt], pa, vb2[nt][0], vb2[nt][1]);
        }
    }

    // ---- finalize: reduce l over quad lanes, normalize, store ----
    l0 += __shfl_xor_sync(0xffffffffu, l0, 1);
    l0 += __shfl_xor_sync(0xffffffffu, l0, 2);
    l1 += __shfl_xor_sync(0xffffffffu, l1, 1);
    l1 += __shfl_xor_sync(0xffffffffu, l1, 2);
    const float inv0 = 1.f / l0;
    const float inv1 = 1.f / l1;

    __half* ob = o + ((size_t)(b * SEQ_N) + qrb) * INNER + h * DHEAD;
#pragma unroll
    for (int nt = 0; nt < 8; nt++) {
        const int cb = nt * 8 + 2 * gq;
        *reinterpret_cast<__half2*>(&ob[(size_t)gr * INNER + cb]) =
            __floats2half2_rn(oacc[nt][0] * inv0, oacc[nt][1] * inv0);
        *reinterpret_cast<__half2*>(&ob[(size_t)(gr + 8) * INNER + cb]) =
            __floats2half2_rn(oacc[nt][2] * inv1, oacc[nt][3] * inv1);
    }
}

// ---------------------------------------------------------------------------
// Launch
// ---------------------------------------------------------------------------
extern "C" void kernel_launch(void* const* d_in, const int* in_sizes, int n_in,
                              void* d_out, int out_size)
{
    const float* x       = (const float*)d_in[0];
    const float* context = (const float*)d_in[1];
    const float* mask    = (const float*)d_in[2];
    const float* ln_w    = (const float*)d_in[3];
    const float* Wq      = (const float*)d_in[4];
    const float* Wkv     = (const float*)d_in[5];
    const float* Wo      = (const float*)d_in[6];
    float* out = (float*)d_out;

    __half *xnh, *qh, *kvh, *aoh;
    cudaGetSymbolAddress((void**)&xnh, g_xnh);
    cudaGetSymbolAddress((void**)&qh,  g_qh);
    cudaGetSymbolAddress((void**)&kvh, g_kvh);
    cudaGetSymbolAddress((void**)&aoh, g_aoh);

    cudaFuncSetAttribute(attn_f16_kernel,
                         cudaFuncAttributeMaxDynamicSharedMemorySize,
                         ATTN_SMEM_BYTES);

    // 1. layernorm -> fp16
    ln_kernel<<<ROWS_TOTAL, 256>>>(x, ln_w, xnh);

    // 2+3. fused launch: Wq projection (6 x-tiles) + kv projection (1 x-tile,
    //      fp32 A with in-staging convert — no separate convert kernel)
    {
        GemmJob jq;
        jq.Ah = xnh;  jq.Af = nullptr; jq.B = Wq;  jq.C = qh;
        jq.N = INNER; jq.K = DIM; jq.out_mode = 2; jq.a_f32 = 0;
        GemmJob jkv;
        jkv.Ah = nullptr; jkv.Af = context; jkv.B = Wkv; jkv.C = kvh;
        jkv.N = 128; jkv.K = DIM; jkv.out_mode = 1; jkv.a_f32 = 1;
        gemm_dual_kernel<<<dim3(7, ROWS_TOTAL / 128), 256>>>(jq, 6, jkv);
    }

    // 4. attention (fp16 mma.sync + ldmatrix, P in registers, 2 CTAs/SM)
    attn_f16_kernel<<<dim3(SEQ_N / 128, HEADS, BATCH), 256, ATTN_SMEM_BYTES>>>(
        qh, kvh, mask, aoh);

    // 5. out = ao @ Wo -> fp32
    {
        GemmJob jo;
        jo.Ah = aoh; jo.Af = nullptr; jo.B = Wo; jo.C = out;
        jo.N = DIM; jo.K = INNER; jo.out_mode = 0; jo.a_f32 = 0;
        gemm_dual_kernel<<<dim3(6, ROWS_TOTAL / 128), 256>>>(jo, 6, jo);
    }
}

// round 14
// speedup vs baseline: 9.4385x; 1.1661x over previous
#include <cuda_runtime.h>
#include <cuda_fp16.h>
#include <cstdint>
#include <math.h>

// Problem constants
#define BATCH   4
#define SEQ_N   2048
#define SEQ_J   2048
#define DIM     768
#define HEADS   12
#define DHEAD   64
#define INNER   (HEADS * DHEAD)   // 768
#define SCALE   0.125f            // 64^-0.5

#define ROWS_TOTAL (BATCH * SEQ_N) // 8192

// ---------------------------------------------------------------------------
// Scratch (static device allocations; no cudaMalloc allowed)
// ---------------------------------------------------------------------------
__device__ __half g_xnh [(size_t)ROWS_TOTAL * DIM];    // layernorm(x), fp16
__device__ __half g_ctxh[(size_t)ROWS_TOTAL * DIM];    // context, fp16
__device__ __half g_qh  [(size_t)ROWS_TOTAL * INNER];  // q, fp16, pre-scaled
__device__ __half g_kvh [(size_t)ROWS_TOTAL * 128];    // [k|v] fp16
__device__ __half g_aoh [(size_t)ROWS_TOTAL * INNER];  // attn output, fp16
__device__ __half g_wqh [DIM * INNER];                 // Wq fp16
__device__ __half g_wkvh[DIM * 128];                   // Wkv fp16
__device__ __half g_woh [INNER * DIM];                 // Wo fp16

// ===========================================================================
// helpers (sm_80+ portable PTX — compiles for plain sm_103)
// ===========================================================================
__device__ __forceinline__ void mma_f16(float* d, const uint32_t* a,
                                        uint32_t b0, uint32_t b1) {
    asm volatile(
        "mma.sync.aligned.m16n8k16.row.col.f32.f16.f16.f32 "
        "{%0,%1,%2,%3}, {%4,%5,%6,%7}, {%8,%9}, {%0,%1,%2,%3};"
        : "+f"(d[0]), "+f"(d[1]), "+f"(d[2]), "+f"(d[3])
        : "r"(a[0]), "r"(a[1]), "r"(a[2]), "r"(a[3]), "r"(b0), "r"(b1));
}
__device__ __forceinline__ uint32_t smem_to_u32(const void* p) {
    uint32_t a;
    asm("{ .reg .u64 t; cvta.to.shared.u64 t, %1; cvt.u32.u64 %0, t; }"
        : "=r"(a) : "l"(p));
    return a;
}
__device__ __forceinline__ uint32_t h2bits(__half2 h) {
    return *reinterpret_cast<uint32_t*>(&h);
}
#define CP_ASYNC16(dst_u32, src_ptr) \
    asm volatile("cp.async.cg.shared.global [%0], [%1], 16;" \
        :: "r"(dst_u32), "l"(src_ptr))
#define CP_COMMIT() asm volatile("cp.async.commit_group;" ::: "memory")
#define CP_WAIT_ALL() asm volatile("cp.async.wait_group 0;" ::: "memory")
#define CP_WAIT_1()   asm volatile("cp.async.wait_group 1;" ::: "memory")

#define LDSM_X4(r0, r1, r2, r3, addr) \
    asm volatile("ldmatrix.sync.aligned.m8n8.x4.shared.b16 {%0,%1,%2,%3}, [%4];" \
        : "=r"(r0), "=r"(r1), "=r"(r2), "=r"(r3) : "r"(addr))
#define LDSM_X4_T(r0, r1, r2, r3, addr) \
    asm volatile("ldmatrix.sync.aligned.m8n8.x4.trans.shared.b16 {%0,%1,%2,%3}, [%4];" \
        : "=r"(r0), "=r"(r1), "=r"(r2), "=r"(r3) : "r"(addr))

// ---------------------------------------------------------------------------
// LayerNorm: one block per row of 768, fp16 output
// ---------------------------------------------------------------------------
__global__ void ln_kernel(const float* __restrict__ x,
                          const float* __restrict__ w,
                          __half* __restrict__ y)
{
    const int row = blockIdx.x;
    const float* xr = x + (size_t)row * DIM;
    float v[3];
    float s = 0.f, s2 = 0.f;
#pragma unroll
    for (int t = 0; t < 3; t++) {
        int i = threadIdx.x + t * 256;
        float vv = xr[i];
        v[t] = vv;
        s += vv; s2 += vv * vv;
    }
#pragma unroll
    for (int o = 16; o > 0; o >>= 1) {
        s  += __shfl_xor_sync(0xffffffffu, s,  o);
        s2 += __shfl_xor_sync(0xffffffffu, s2, o);
    }
    __shared__ float rs[8], rs2[8];
    int wid = threadIdx.x >> 5, lid = threadIdx.x & 31;
    if (lid == 0) { rs[wid] = s; rs2[wid] = s2; }
    __syncthreads();
    if (wid == 0) {
        s  = (lid < 8) ? rs[lid]  : 0.f;
        s2 = (lid < 8) ? rs2[lid] : 0.f;
#pragma unroll
        for (int o = 4; o > 0; o >>= 1) {
            s  += __shfl_xor_sync(0xffffffffu, s,  o);
            s2 += __shfl_xor_sync(0xffffffffu, s2, o);
        }
        if (lid == 0) { rs[0] = s; rs2[0] = s2; }
    }
    __syncthreads();
    const float mu   = rs[0] * (1.f / DIM);
    const float var  = rs2[0] * (1.f / DIM) - mu * mu;
    const float rstd = rsqrtf(var + 1e-5f);
    __half* yr = y + (size_t)row * DIM;
#pragma unroll
    for (int t = 0; t < 3; t++) {
        int i = threadIdx.x + t * 256;
        yr[i] = __float2half_rn((v[t] - mu) * rstd * w[i]);
    }
}

// ---------------------------------------------------------------------------
// fp32 -> fp16 elementwise convert
// ---------------------------------------------------------------------------
__global__ void f32_to_f16_kernel(const float* __restrict__ src,
                                  __half* __restrict__ dst, int n4)
{
    int i = blockIdx.x * blockDim.x + threadIdx.x;
    if (i < n4) {
        float4 v = reinterpret_cast<const float4*>(src)[i];
        reinterpret_cast<uint2*>(dst)[i] =
            make_uint2(h2bits(__floats2half2_rn(v.x, v.y)),
                       h2bits(__floats2half2_rn(v.z, v.w)));
    }
}

// ---------------------------------------------------------------------------
// fp16 tensor-core GEMM (all operands fp16), cp.async 3-stage pipeline.
// Dual-job: blockIdx.x < nx0 -> job0, else job1.
// BM=128, BN=128, BK=32, 256 threads = 8 warps (4x2), warp tile 32x64.
// out_mode: 0 fp32 out, 1 fp16 out, 2 fp16*(SCALE) out.
// Smem per stage: A 128x40 halfs (10240 B) + B 32x128 halfs (8192 B).
// 3 stages = 55296 B dynamic. 2 CTAs/SM.
// ---------------------------------------------------------------------------
#define AST 40
#define A_STG_B 10240
#define B_STG_B 8192
#define GEMM_SMEM_BYTES (3 * (A_STG_B + B_STG_B))   // 55296

struct GemmJob {
    const __half* A;
    const __half* B;
    void*         C;
    int N, K, out_mode;
};

__device__ __forceinline__ void gemm_stage(uint32_t sbase, int stg,
                                           const __half* A, const __half* B,
                                           int m0, int n0, int kt,
                                           int N, int K, int tid)
{
    const uint32_t ab = sbase + stg * (A_STG_B + B_STG_B);
    const uint32_t bb = ab + A_STG_B;
#pragma unroll
    for (int t = 0; t < 2; t++) {
        const int e = tid + t * 256;
        // A chunk: row = e>>2, kchunk = e&3
        const int ar = e >> 2, ac = e & 3;
        CP_ASYNC16(ab + (uint32_t)(ar * 80 + ac * 16),
                   &A[(size_t)(m0 + ar) * K + kt + ac * 8]);
        // B chunk: k = e>>4, c16 = e&15 (swizzled)
        const int bk = e >> 4, bc = e & 15;
        CP_ASYNC16(bb + (uint32_t)(bk * 256 + ((bc ^ (bk & 7)) * 16)),
                   &B[(size_t)(kt + bk) * N + n0 + bc * 8]);
    }
    CP_COMMIT();
}

__global__ __launch_bounds__(256, 2)
void gemm_dual_kernel(GemmJob j0, int nx0, GemmJob j1)
{
    extern __shared__ char gsm[];
    const uint32_t sbase = smem_to_u32(gsm);

    GemmJob jb;
    int bx;
    if ((int)blockIdx.x < nx0) { jb = j0; bx = blockIdx.x; }
    else                       { jb = j1; bx = blockIdx.x - nx0; }
    const int N = jb.N;
    const int K = jb.K;

    const int tid  = threadIdx.x;
    const int wid  = tid >> 5;
    const int lane = tid & 31;
    const int g8   = lane >> 3;
    const int r8   = lane & 7;
    const int gr   = lane >> 2;
    const int gq   = lane & 3;
    const int wm   = (wid & 3) * 32;
    const int wn   = (wid >> 2) * 64;
    const int m0   = blockIdx.y * 128;
    const int n0   = bx * 128;

    float acc[2][8][4];
#pragma unroll
    for (int ms = 0; ms < 2; ms++)
#pragma unroll
        for (int nt = 0; nt < 8; nt++)
#pragma unroll
            for (int i = 0; i < 4; i++) acc[ms][nt][i] = 0.f;

    const uint32_t arow  = (uint32_t)(wm + ((g8 & 1) << 3) + r8);
    const uint32_t akc   = (uint32_t)(g8 >> 1);
    const uint32_t bkrow = (uint32_t)(((g8 & 1) << 3) + r8);
    const uint32_t bnc   = (uint32_t)((wn >> 3) + (g8 >> 1));

    const int niter = K / 32;   // 24 for K=768

    // prologue: stages 0 and 1 in flight
    gemm_stage(sbase, 0, jb.A, jb.B, m0, n0, 0,  N, K, tid);
    gemm_stage(sbase, 1, jb.A, jb.B, m0, n0, 32, N, K, tid);

    int stg = 0;
    for (int it = 0; it < niter; it++) {
        CP_WAIT_1();          // stage `it` landed
        __syncthreads();      // visible; all warps done with stage it-1's buf

        if (it + 2 < niter)
            gemm_stage(sbase, (stg + 2) % 3, jb.A, jb.B, m0, n0,
                       (it + 2) * 32, N, K, tid);

        const uint32_t ab = sbase + stg * (A_STG_B + B_STG_B);
        const uint32_t bb = ab + A_STG_B;

#pragma unroll
        for (int c = 0; c < 2; c++) {
            uint32_t af[2][4];
#pragma unroll
            for (int ms = 0; ms < 2; ms++) {
                const uint32_t a = ab + (arow + ms * 16) * 80
                                 + (c * 2 + akc) * 16;
                LDSM_X4(af[ms][0], af[ms][1], af[ms][2], af[ms][3], a);
            }
            uint32_t bf[8][2];
#pragma unroll
            for (int ntp = 0; ntp < 4; ntp++) {
                const uint32_t row = (uint32_t)(c * 16) + bkrow;
                const uint32_t a = bb + row * 256
                                 + (((bnc + ntp * 2) ^ (uint32_t)r8) << 4);
                LDSM_X4_T(bf[2 * ntp][0], bf[2 * ntp][1],
                          bf[2 * ntp + 1][0], bf[2 * ntp + 1][1], a);
            }
#pragma unroll
            for (int nt = 0; nt < 8; nt++)
#pragma unroll
                for (int ms = 0; ms < 2; ms++)
                    mma_f16(acc[ms][nt], af[ms], bf[nt][0], bf[nt][1]);
        }
        stg = (stg + 1) % 3;
    }

    const float alpha = (jb.out_mode == 2) ? SCALE : 1.0f;
    float*  Cf = reinterpret_cast<float*>(jb.C);
    __half* Ch = reinterpret_cast<__half*>(jb.C);
#pragma unroll
    for (int ms = 0; ms < 2; ms++) {
        const int mrow0 = m0 + wm + ms * 16 + gr;
#pragma unroll
        for (int nt = 0; nt < 8; nt++) {
            const int col = n0 + wn + nt * 8 + 2 * gq;
            if (jb.out_mode == 0) {
                *reinterpret_cast<float2*>(&Cf[(size_t)mrow0 * N + col]) =
                    make_float2(acc[ms][nt][0], acc[ms][nt][1]);
                *reinterpret_cast<float2*>(&Cf[(size_t)(mrow0 + 8) * N + col]) =
                    make_float2(acc[ms][nt][2], acc[ms][nt][3]);
            } else {
                *reinterpret_cast<__half2*>(&Ch[(size_t)mrow0 * N + col]) =
                    __floats2half2_rn(acc[ms][nt][0] * alpha,
                                      acc[ms][nt][1] * alpha);
                *reinterpret_cast<__half2*>(&Ch[(size_t)(mrow0 + 8) * N + col]) =
                    __floats2half2_rn(acc[ms][nt][2] * alpha,
                                      acc[ms][nt][3] * alpha);
            }
        }
    }
}

// ---------------------------------------------------------------------------
// fp16 mma.sync flash attention, P in registers (unchanged from round 13).
// ---------------------------------------------------------------------------
#define KOFF0 0
#define VOFF0 8192
#define KOFF1 16384
#define VOFF1 24576
#define ATTN_SMEM_BYTES 32768
#define NTILES (SEQ_J / 64)            // 32

__device__ __forceinline__ void stage_kv_f16(uint32_t sbase, int buf,
                                             const __half* kv_tile, int tid)
{
    const uint32_t kb = sbase + (buf ? KOFF1 : KOFF0);
    const uint32_t vb = sbase + (buf ? VOFF1 : VOFF0);
#pragma unroll
    for (int t = 0; t < 4; t++) {
        const int e   = tid + t * 256;
        const int jj  = e >> 4;
        const int c16 = e & 15;
        const char* src = reinterpret_cast<const char*>(kv_tile)
                          + (size_t)jj * 256 + c16 * 16;
        const uint32_t sw = (uint32_t)(jj & 7) << 4;
        const uint32_t dst = (c16 < 8)
            ? kb + (uint32_t)jj * 128 + (((uint32_t)c16 * 16) ^ sw)
            : vb + (uint32_t)jj * 128 + (((uint32_t)(c16 - 8) * 16) ^ sw);
        CP_ASYNC16(dst, src);
    }
    CP_COMMIT();
}

__global__ __launch_bounds__(256, 2)
void attn_f16_kernel(const __half* __restrict__ q,
                     const __half* __restrict__ kv,
                     const float* __restrict__ mask, __half* __restrict__ o)
{
    extern __shared__ char smc[];
    const uint32_t sbase = smem_to_u32(smc);

    const int tid  = threadIdx.x;
    const int wid  = tid >> 5;
    const int lane = tid & 31;
    const int gr   = lane >> 2;
    const int gq   = lane & 3;
    const int g8   = lane >> 3;
    const int r8   = lane & 7;
    const int h    = blockIdx.y;
    const int b    = blockIdx.z;
    const int row0 = blockIdx.x * 128;
    const int qrb  = row0 + wid * 16;

    uint32_t qf[4][4];
    {
        const __half* qb = q + ((size_t)(b * SEQ_N) + qrb) * INNER + h * DHEAD;
#pragma unroll
        for (int c = 0; c < 4; c++) {
            qf[c][0] = *reinterpret_cast<const uint32_t*>(
                &qb[(size_t)(gr    ) * INNER + c * 16 + 2 * gq]);
            qf[c][1] = *reinterpret_cast<const uint32_t*>(
                &qb[(size_t)(gr + 8) * INNER + c * 16 + 2 * gq]);
            qf[c][2] = *reinterpret_cast<const uint32_t*>(
                &qb[(size_t)(gr    ) * INNER + c * 16 + 8 + 2 * gq]);
            qf[c][3] = *reinterpret_cast<const uint32_t*>(
                &qb[(size_t)(gr + 8) * INNER + c * 16 + 8 + 2 * gq]);
        }
    }

    float oacc[8][4];
#pragma unroll
    for (int nt = 0; nt < 8; nt++)
#pragma unroll
        for (int i = 0; i < 4; i++) oacc[nt][i] = 0.f;
    float l0 = 0.f, l1 = 0.f;

    const float* m0p = mask + ((size_t)(b * SEQ_N) + qrb + gr) * SEQ_J + 2 * gq;
    const __half* kv_base = kv + (size_t)b * SEQ_J * 128;

    const uint32_t kj    = (uint32_t)(((g8 >> 1) << 3) + r8);
    const uint32_t kcsel = (uint32_t)(g8 & 1);
    const uint32_t vj    = (uint32_t)(((g8 & 1) << 3) + r8);
    const uint32_t vcsel = (uint32_t)(g8 >> 1);

    stage_kv_f16(sbase, 0, kv_base, tid);

#pragma unroll 1
    for (int t = 0; t < NTILES; t++) {
        const int cur = t & 1;

        CP_WAIT_ALL();
        __syncthreads();

        if (t + 1 < NTILES)
            stage_kv_f16(sbase, cur ^ 1,
                         kv_base + (size_t)(t + 1) * 64 * 128, tid);

        const uint32_t Kb = sbase + (cur ? KOFF1 : KOFF0);
        const uint32_t Vb = sbase + (cur ? VOFF1 : VOFF0);

        float2 mk0[8], mk1[8];
        {
            const float* mrow = m0p + t * 64;
#pragma unroll
            for (int nt = 0; nt < 8; nt++) {
                mk0[nt] = *reinterpret_cast<const float2*>(&mrow[nt * 8]);
                mk1[nt] = *reinterpret_cast<const float2*>(
                    &mrow[(size_t)8 * SEQ_J + nt * 8]);
            }
        }

        float sacc[8][4];
#pragma unroll
        for (int nt = 0; nt < 8; nt++)
#pragma unroll
            for (int i = 0; i < 4; i++) sacc[nt][i] = 0.f;

#pragma unroll
        for (int c = 0; c < 4; c++) {
            uint32_t kb2[8][2];
#pragma unroll
            for (int ntp = 0; ntp < 4; ntp++) {
                const uint32_t a = Kb + (ntp * 16 + kj) * 128
                    + ((((uint32_t)(c * 2) + kcsel) ^ (uint32_t)r8) << 4);
                LDSM_X4(kb2[2 * ntp][0], kb2[2 * ntp][1],
                        kb2[2 * ntp + 1][0], kb2[2 * ntp + 1][1], a);
            }
#pragma unroll
            for (int nt = 0; nt < 8; nt++)
                mma_f16(sacc[nt], qf[c], kb2[nt][0], kb2[nt][1]);
        }

        uint32_t pah[8][2];
#pragma unroll
        for (int nt = 0; nt < 8; nt++) {
            float p00 = __expf(sacc[nt][0] + mk0[nt].x);
            float p01 = __expf(sacc[nt][1] + mk0[nt].y);
            float p10 = __expf(sacc[nt][2] + mk1[nt].x);
            float p11 = __expf(sacc[nt][3] + mk1[nt].y);
            l0 += p00 + p01;
            l1 += p10 + p11;
            pah[nt][0] = h2bits(__floats2half2_rn(p00, p01));
            pah[nt][1] = h2bits(__floats2half2_rn(p10, p11));
        }

#pragma unroll
        for (int c = 0; c < 4; c++) {
            uint32_t pa[4] = { pah[2 * c][0], pah[2 * c][1],
                               pah[2 * c + 1][0], pah[2 * c + 1][1] };
            uint32_t vb2[8][2];
#pragma unroll
            for (int ntp = 0; ntp < 4; ntp++) {
                const uint32_t a = Vb + (c * 16 + vj) * 128
                    + ((((uint32_t)(ntp * 2) + vcsel) ^ (uint32_t)r8) << 4);
                LDSM_X4_T(vb2[2 * ntp][0], vb2[2 * ntp][1],
                          vb2[2 * ntp + 1][0], vb2[2 * ntp + 1][1], a);
            }
#pragma unroll
            for (int nt = 0; nt < 8; nt++)
                mma_f16(oacc[nt], pa, vb2[nt][0], vb2[nt][1]);
        }
    }

    l0 += __shfl_xor_sync(0xffffffffu, l0, 1);
    l0 += __shfl_xor_sync(0xffffffffu, l0, 2);
    l1 += __shfl_xor_sync(0xffffffffu, l1, 1);
    l1 += __shfl_xor_sync(0xffffffffu, l1, 2);
    const float inv0 = 1.f / l0;
    const float inv1 = 1.f / l1;

    __half* ob = o + ((size_t)(b * SEQ_N) + qrb) * INNER + h * DHEAD;
#pragma unroll
    for (int nt = 0; nt < 8; nt++) {
        const int cb = nt * 8 + 2 * gq;
        *reinterpret_cast<__half2*>(&ob[(size_t)gr * INNER + cb]) =
            __floats2half2_rn(oacc[nt][0] * inv0, oacc[nt][1] * inv0);
        *reinterpret_cast<__half2*>(&ob[(size_t)(gr + 8) * INNER + cb]) =
            __floats2half2_rn(oacc[nt][2] * inv1, oacc[nt][3] * inv1);
    }
}

// ---------------------------------------------------------------------------
// Launch
// ---------------------------------------------------------------------------
extern "C" void kernel_launch(void* const* d_in, const int* in_sizes, int n_in,
                              void* d_out, int out_size)
{
    const float* x       = (const float*)d_in[0];
    const float* context = (const float*)d_in[1];
    const float* mask    = (const float*)d_in[2];
    const float* ln_w    = (const float*)d_in[3];
    const float* Wq      = (const float*)d_in[4];
    const float* Wkv     = (const float*)d_in[5];
    const float* Wo      = (const float*)d_in[6];
    float* out = (float*)d_out;

    __half *xnh, *ctxh, *qh, *kvh, *aoh, *wqh, *wkvh, *woh;
    cudaGetSymbolAddress((void**)&xnh,  g_xnh);
    cudaGetSymbolAddress((void**)&ctxh, g_ctxh);
    cudaGetSymbolAddress((void**)&qh,   g_qh);
    cudaGetSymbolAddress((void**)&kvh,  g_kvh);
    cudaGetSymbolAddress((void**)&aoh,  g_aoh);
    cudaGetSymbolAddress((void**)&wqh,  g_wqh);
    cudaGetSymbolAddress((void**)&wkvh, g_wkvh);
    cudaGetSymbolAddress((void**)&woh,  g_woh);

    cudaFuncSetAttribute(attn_f16_kernel,
                         cudaFuncAttributeMaxDynamicSharedMemorySize,
                         ATTN_SMEM_BYTES);
    cudaFuncSetAttribute(gemm_dual_kernel,
                         cudaFuncAttributeMaxDynamicSharedMemorySize,
                         GEMM_SMEM_BYTES);

    // 0. converts: weights + context -> fp16
    {
        int n4;
        n4 = DIM * INNER / 4;
        f32_to_f16_kernel<<<(n4 + 255) / 256, 256>>>(Wq, wqh, n4);
        n4 = DIM * 128 / 4;
        f32_to_f16_kernel<<<(n4 + 255) / 256, 256>>>(Wkv, wkvh, n4);
        n4 = INNER * DIM / 4;
        f32_to_f16_kernel<<<(n4 + 255) / 256, 256>>>(Wo, woh, n4);
        n4 = ROWS_TOTAL * DIM / 4;
        f32_to_f16_kernel<<<(n4 + 255) / 256, 256>>>(context, ctxh, n4);
    }

    // 1. layernorm -> fp16
    ln_kernel<<<ROWS_TOTAL, 256>>>(x, ln_w, xnh);

    // 2+3. fused: Wq projection (6 x-tiles) + kv projection (1 x-tile)
    {
        GemmJob jq  = { xnh,  wqh,  qh,  INNER, DIM, 2 };
        GemmJob jkv = { ctxh, wkvh, kvh, 128,   DIM, 1 };
        gemm_dual_kernel<<<dim3(7, ROWS_TOTAL / 128), 256, GEMM_SMEM_BYTES>>>(
            jq, 6, jkv);
    }

    // 4. attention (fp16 mma.sync + ldmatrix, P in registers, 2 CTAs/SM)
    attn_f16_kernel<<<dim3(SEQ_N / 128, HEADS, BATCH), 256, ATTN_SMEM_BYTES>>>(
        qh, kvh, mask, aoh);

    // 5. out = ao @ Wo -> fp32
    {
        GemmJob jo = { aoh, woh, out, DIM, INNER, 0 };
        gemm_dual_kernel<<<dim3(6, ROWS_TOTAL / 128), 256, GEMM_SMEM_BYTES>>>(
            jo, 6, jo);
    }
}

// round 15
// speedup vs baseline: 10.7411x; 1.1380x over previous
#include <cuda_runtime.h>
#include <cuda_fp16.h>
#include <cstdint>
#include <math.h>

// Problem constants
#define BATCH   4
#define SEQ_N   2048
#define SEQ_J   2048
#define DIM     768
#define HEADS   12
#define DHEAD   64
#define INNER   (HEADS * DHEAD)   // 768
#define SCALE   0.125f            // 64^-0.5

#define ROWS_TOTAL (BATCH * SEQ_N) // 8192

// ---------------------------------------------------------------------------
// Scratch (static device allocations; no cudaMalloc allowed)
// ---------------------------------------------------------------------------
__device__ __half g_xnh [(size_t)ROWS_TOTAL * DIM];    // layernorm(x), fp16
__device__ __half g_ctxh[(size_t)ROWS_TOTAL * DIM];    // context, fp16
__device__ __half g_qh  [(size_t)ROWS_TOTAL * INNER];  // q, fp16, pre-scaled
__device__ __half g_kvh [(size_t)ROWS_TOTAL * 128];    // [k|v] fp16
__device__ __half g_aoh [(size_t)ROWS_TOTAL * INNER];  // attn output, fp16
__device__ __half g_wqh [DIM * INNER];                 // Wq fp16
__device__ __half g_wkvh[DIM * 128];                   // Wkv fp16
__device__ __half g_woh [INNER * DIM];                 // Wo fp16

// ===========================================================================
// helpers (sm_80+ portable PTX — compiles for plain sm_103)
// ===========================================================================
__device__ __forceinline__ void mma_f16(float* d, const uint32_t* a,
                                        uint32_t b0, uint32_t b1) {
    asm volatile(
        "mma.sync.aligned.m16n8k16.row.col.f32.f16.f16.f32 "
        "{%0,%1,%2,%3}, {%4,%5,%6,%7}, {%8,%9}, {%0,%1,%2,%3};"
        : "+f"(d[0]), "+f"(d[1]), "+f"(d[2]), "+f"(d[3])
        : "r"(a[0]), "r"(a[1]), "r"(a[2]), "r"(a[3]), "r"(b0), "r"(b1));
}
__device__ __forceinline__ uint32_t smem_to_u32(const void* p) {
    uint32_t a;
    asm("{ .reg .u64 t; cvta.to.shared.u64 t, %1; cvt.u32.u64 %0, t; }"
        : "=r"(a) : "l"(p));
    return a;
}
__device__ __forceinline__ uint32_t h2bits(__half2 h) {
    return *reinterpret_cast<uint32_t*>(&h);
}
#define CP_ASYNC16(dst_u32, src_ptr) \
    asm volatile("cp.async.cg.shared.global [%0], [%1], 16;" \
        :: "r"(dst_u32), "l"(src_ptr))
#define CP_COMMIT() asm volatile("cp.async.commit_group;" ::: "memory")
#define CP_WAIT_ALL() asm volatile("cp.async.wait_group 0;" ::: "memory")
#define CP_WAIT_1()   asm volatile("cp.async.wait_group 1;" ::: "memory")

#define LDSM_X4(r0, r1, r2, r3, addr) \
    asm volatile("ldmatrix.sync.aligned.m8n8.x4.shared.b16 {%0,%1,%2,%3}, [%4];" \
        : "=r"(r0), "=r"(r1), "=r"(r2), "=r"(r3) : "r"(addr))
#define LDSM_X4_T(r0, r1, r2, r3, addr) \
    asm volatile("ldmatrix.sync.aligned.m8n8.x4.trans.shared.b16 {%0,%1,%2,%3}, [%4];" \
        : "=r"(r0), "=r"(r1), "=r"(r2), "=r"(r3) : "r"(addr))

// ---------------------------------------------------------------------------
// LayerNorm: one block per row of 768, fp16 output
// ---------------------------------------------------------------------------
__global__ void ln_kernel(const float* __restrict__ x,
                          const float* __restrict__ w,
                          __half* __restrict__ y)
{
    const int row = blockIdx.x;
    const float* xr = x + (size_t)row * DIM;
    float v[3];
    float s = 0.f, s2 = 0.f;
#pragma unroll
    for (int t = 0; t < 3; t++) {
        int i = threadIdx.x + t * 256;
        float vv = xr[i];
        v[t] = vv;
        s += vv; s2 += vv * vv;
    }
#pragma unroll
    for (int o = 16; o > 0; o >>= 1) {
        s  += __shfl_xor_sync(0xffffffffu, s,  o);
        s2 += __shfl_xor_sync(0xffffffffu, s2, o);
    }
    __shared__ float rs[8], rs2[8];
    int wid = threadIdx.x >> 5, lid = threadIdx.x & 31;
    if (lid == 0) { rs[wid] = s; rs2[wid] = s2; }
    __syncthreads();
    if (wid == 0) {
        s  = (lid < 8) ? rs[lid]  : 0.f;
        s2 = (lid < 8) ? rs2[lid] : 0.f;
#pragma unroll
        for (int o = 4; o > 0; o >>= 1) {
            s  += __shfl_xor_sync(0xffffffffu, s,  o);
            s2 += __shfl_xor_sync(0xffffffffu, s2, o);
        }
        if (lid == 0) { rs[0] = s; rs2[0] = s2; }
    }
    __syncthreads();
    const float mu   = rs[0] * (1.f / DIM);
    const float var  = rs2[0] * (1.f / DIM) - mu * mu;
    const float rstd = rsqrtf(var + 1e-5f);
    __half* yr = y + (size_t)row * DIM;
#pragma unroll
    for (int t = 0; t < 3; t++) {
        int i = threadIdx.x + t * 256;
        yr[i] = __float2half_rn((v[t] - mu) * rstd * w[i]);
    }
}

// ---------------------------------------------------------------------------
// fp32 -> fp16 elementwise convert
// ---------------------------------------------------------------------------
__global__ void f32_to_f16_kernel(const float* __restrict__ src,
                                  __half* __restrict__ dst, int n4)
{
    int i = blockIdx.x * blockDim.x + threadIdx.x;
    if (i < n4) {
        float4 v = reinterpret_cast<const float4*>(src)[i];
        reinterpret_cast<uint2*>(dst)[i] =
            make_uint2(h2bits(__floats2half2_rn(v.x, v.y)),
                       h2bits(__floats2half2_rn(v.z, v.w)));
    }
}

// ---------------------------------------------------------------------------
// fp16 tensor-core GEMM (all operands fp16), cp.async 3-stage pipeline.
// Dual-job: blockIdx.x < nx0 -> job0, else job1.  (unchanged from round 14)
// ---------------------------------------------------------------------------
#define AST 40
#define A_STG_B 10240
#define B_STG_B 8192
#define GEMM_SMEM_BYTES (3 * (A_STG_B + B_STG_B))   // 55296

struct GemmJob {
    const __half* A;
    const __half* B;
    void*         C;
    int N, K, out_mode;
};

__device__ __forceinline__ void gemm_stage(uint32_t sbase, int stg,
                                           const __half* A, const __half* B,
                                           int m0, int n0, int kt,
                                           int N, int K, int tid)
{
    const uint32_t ab = sbase + stg * (A_STG_B + B_STG_B);
    const uint32_t bb = ab + A_STG_B;
#pragma unroll
    for (int t = 0; t < 2; t++) {
        const int e = tid + t * 256;
        const int ar = e >> 2, ac = e & 3;
        CP_ASYNC16(ab + (uint32_t)(ar * 80 + ac * 16),
                   &A[(size_t)(m0 + ar) * K + kt + ac * 8]);
        const int bk = e >> 4, bc = e & 15;
        CP_ASYNC16(bb + (uint32_t)(bk * 256 + ((bc ^ (bk & 7)) * 16)),
                   &B[(size_t)(kt + bk) * N + n0 + bc * 8]);
    }
    CP_COMMIT();
}

__global__ __launch_bounds__(256, 2)
void gemm_dual_kernel(GemmJob j0, int nx0, GemmJob j1)
{
    extern __shared__ char gsm[];
    const uint32_t sbase = smem_to_u32(gsm);

    GemmJob jb;
    int bx;
    if ((int)blockIdx.x < nx0) { jb = j0; bx = blockIdx.x; }
    else                       { jb = j1; bx = blockIdx.x - nx0; }
    const int N = jb.N;
    const int K = jb.K;

    const int tid  = threadIdx.x;
    const int wid  = tid >> 5;
    const int lane = tid & 31;
    const int g8   = lane >> 3;
    const int r8   = lane & 7;
    const int gr   = lane >> 2;
    const int gq   = lane & 3;
    const int wm   = (wid & 3) * 32;
    const int wn   = (wid >> 2) * 64;
    const int m0   = blockIdx.y * 128;
    const int n0   = bx * 128;

    float acc[2][8][4];
#pragma unroll
    for (int ms = 0; ms < 2; ms++)
#pragma unroll
        for (int nt = 0; nt < 8; nt++)
#pragma unroll
            for (int i = 0; i < 4; i++) acc[ms][nt][i] = 0.f;

    const uint32_t arow  = (uint32_t)(wm + ((g8 & 1) << 3) + r8);
    const uint32_t akc   = (uint32_t)(g8 >> 1);
    const uint32_t bkrow = (uint32_t)(((g8 & 1) << 3) + r8);
    const uint32_t bnc   = (uint32_t)((wn >> 3) + (g8 >> 1));

    const int niter = K / 32;

    gemm_stage(sbase, 0, jb.A, jb.B, m0, n0, 0,  N, K, tid);
    gemm_stage(sbase, 1, jb.A, jb.B, m0, n0, 32, N, K, tid);

    int stg = 0;
    for (int it = 0; it < niter; it++) {
        CP_WAIT_1();
        __syncthreads();

        if (it + 2 < niter)
            gemm_stage(sbase, (stg + 2) % 3, jb.A, jb.B, m0, n0,
                       (it + 2) * 32, N, K, tid);

        const uint32_t ab = sbase + stg * (A_STG_B + B_STG_B);
        const uint32_t bb = ab + A_STG_B;

#pragma unroll
        for (int c = 0; c < 2; c++) {
            uint32_t af[2][4];
#pragma unroll
            for (int ms = 0; ms < 2; ms++) {
                const uint32_t a = ab + (arow + ms * 16) * 80
                                 + (c * 2 + akc) * 16;
                LDSM_X4(af[ms][0], af[ms][1], af[ms][2], af[ms][3], a);
            }
            uint32_t bf[8][2];
#pragma unroll
            for (int ntp = 0; ntp < 4; ntp++) {
                const uint32_t row = (uint32_t)(c * 16) + bkrow;
                const uint32_t a = bb + row * 256
                                 + (((bnc + ntp * 2) ^ (uint32_t)r8) << 4);
                LDSM_X4_T(bf[2 * ntp][0], bf[2 * ntp][1],
                          bf[2 * ntp + 1][0], bf[2 * ntp + 1][1], a);
            }
#pragma unroll
            for (int nt = 0; nt < 8; nt++)
#pragma unroll
                for (int ms = 0; ms < 2; ms++)
                    mma_f16(acc[ms][nt], af[ms], bf[nt][0], bf[nt][1]);
        }
        stg = (stg + 1) % 3;
    }

    const float alpha = (jb.out_mode == 2) ? SCALE : 1.0f;
    float*  Cf = reinterpret_cast<float*>(jb.C);
    __half* Ch = reinterpret_cast<__half*>(jb.C);
#pragma unroll
    for (int ms = 0; ms < 2; ms++) {
        const int mrow0 = m0 + wm + ms * 16 + gr;
#pragma unroll
        for (int nt = 0; nt < 8; nt++) {
            const int col = n0 + wn + nt * 8 + 2 * gq;
            if (jb.out_mode == 0) {
                *reinterpret_cast<float2*>(&Cf[(size_t)mrow0 * N + col]) =
                    make_float2(acc[ms][nt][0], acc[ms][nt][1]);
                *reinterpret_cast<float2*>(&Cf[(size_t)(mrow0 + 8) * N + col]) =
                    make_float2(acc[ms][nt][2], acc[ms][nt][3]);
            } else {
                *reinterpret_cast<__half2*>(&Ch[(size_t)mrow0 * N + col]) =
                    __floats2half2_rn(acc[ms][nt][0] * alpha,
                                      acc[ms][nt][1] * alpha);
                *reinterpret_cast<__half2*>(&Ch[(size_t)(mrow0 + 8) * N + col]) =
                    __floats2half2_rn(acc[ms][nt][2] * alpha,
                                      acc[ms][nt][3] * alpha);
            }
        }
    }
}

// ---------------------------------------------------------------------------
// fp16 mma.sync flash attention — multi-query head sharing.
// CTA = (b, 32 q-rows, 4-head group). Warp w: rows (w&1)*16..+15 of head
// hg*4 + (w>>1). K/V staged once per CTA serve 4 heads; the fp32 MASK TILE
// (32x64, stride 68 floats) is cp.async-staged and read via LDS by all
// head-warps — 4x less mask global traffic, no strided mask LDGs.
// P stays in registers (FA2). Double-buffered stages of 25088 B; 2 CTAs/SM.
// ---------------------------------------------------------------------------
#define MOFF   16384
#define MROWB  272                     // mask row stride bytes (68 floats)
#define STG_B  (16384 + 32 * MROWB)    // 25088
#define ATTN_SMEM_BYTES (2 * STG_B)    // 50176
#define NTILES (SEQ_J / 64)            // 32

__device__ __forceinline__ void stage_kvm(uint32_t sbase, int buf,
                                          const __half* kv_tile,
                                          const float* mask_tile, int tid)
{
    const uint32_t base = sbase + buf * STG_B;
    // K/V: 64 rows x 256B = 1024 chunks
#pragma unroll
    for (int t = 0; t < 4; t++) {
        const int e   = tid + t * 256;
        const int jj  = e >> 4;
        const int c16 = e & 15;
        const char* src = reinterpret_cast<const char*>(kv_tile)
                          + (size_t)jj * 256 + c16 * 16;
        const uint32_t sw = (uint32_t)(jj & 7) << 4;
        const uint32_t dst = (c16 < 8)
            ? base + (uint32_t)jj * 128 + (((uint32_t)c16 * 16) ^ sw)
            : base + 8192 + (uint32_t)jj * 128 + (((uint32_t)(c16 - 8) * 16) ^ sw);
        CP_ASYNC16(dst, src);
    }
    // mask: 32 rows x 256B = 512 chunks
#pragma unroll
    for (int t = 0; t < 2; t++) {
        const int e = tid + t * 256;
        const int r = e >> 4;
        const int c = e & 15;
        CP_ASYNC16(base + MOFF + (uint32_t)(r * MROWB + c * 16),
                   &mask_tile[(size_t)r * SEQ_J + c * 4]);
    }
    CP_COMMIT();
}

__global__ __launch_bounds__(256, 2)
void attn_f16_kernel(const __half* __restrict__ q,
                     const __half* __restrict__ kv,
                     const float* __restrict__ mask, __half* __restrict__ o)
{
    extern __shared__ char smc[];
    const uint32_t sbase = smem_to_u32(smc);

    const int tid  = threadIdx.x;
    const int wid  = tid >> 5;
    const int lane = tid & 31;
    const int gr   = lane >> 2;
    const int gq   = lane & 3;
    const int g8   = lane >> 3;
    const int r8   = lane & 7;
    const int h    = blockIdx.y * 4 + (wid >> 1);   // this warp's head
    const int b    = blockIdx.z;
    const int row0 = blockIdx.x * 32;
    const int qrb  = row0 + (wid & 1) * 16;         // warp's first q row

    // ---- Q fragments: fp16, pre-scaled by Wq epilogue. 4 k-steps x 4 regs.
    uint32_t qf[4][4];
    {
        const __half* qb = q + ((size_t)(b * SEQ_N) + qrb) * INNER + h * DHEAD;
#pragma unroll
        for (int c = 0; c < 4; c++) {
            qf[c][0] = *reinterpret_cast<const uint32_t*>(
                &qb[(size_t)(gr    ) * INNER + c * 16 + 2 * gq]);
            qf[c][1] = *reinterpret_cast<const uint32_t*>(
                &qb[(size_t)(gr + 8) * INNER + c * 16 + 2 * gq]);
            qf[c][2] = *reinterpret_cast<const uint32_t*>(
                &qb[(size_t)(gr    ) * INNER + c * 16 + 8 + 2 * gq]);
            qf[c][3] = *reinterpret_cast<const uint32_t*>(
                &qb[(size_t)(gr + 8) * INNER + c * 16 + 8 + 2 * gq]);
        }
    }

    float oacc[8][4];
#pragma unroll
    for (int nt = 0; nt < 8; nt++)
#pragma unroll
        for (int i = 0; i < 4; i++) oacc[nt][i] = 0.f;
    float l0 = 0.f, l1 = 0.f;

    const __half* kv_base = kv + (size_t)b * SEQ_J * 128;
    const float* mask_base = mask + ((size_t)(b * SEQ_N) + row0) * SEQ_J;

    const uint32_t kj    = (uint32_t)(((g8 >> 1) << 3) + r8);
    const uint32_t kcsel = (uint32_t)(g8 & 1);
    const uint32_t vj    = (uint32_t)(((g8 & 1) << 3) + r8);
    const uint32_t vcsel = (uint32_t)(g8 >> 1);

    // mask smem row offsets for this warp's two row-groups
    const uint32_t mrow0_off = (uint32_t)(((wid & 1) * 16 + gr) * MROWB + gq * 8);
    const uint32_t mrow1_off = mrow0_off + 8 * MROWB;

    stage_kvm(sbase, 0, kv_base, mask_base, tid);

#pragma unroll 1
    for (int t = 0; t < NTILES; t++) {
        const int cur = t & 1;

        CP_WAIT_ALL();
        __syncthreads();

        if (t + 1 < NTILES)
            stage_kvm(sbase, cur ^ 1,
                      kv_base + (size_t)(t + 1) * 64 * 128,
                      mask_base + (size_t)(t + 1) * 64, tid);

        const uint32_t Kb = sbase + cur * STG_B;
        const uint32_t Vb = Kb + 8192;
        const char* Mb = smc + cur * STG_B + MOFF;

        // ---- S = Q @ K^T : 4 k-steps of 16 ----
        float sacc[8][4];
#pragma unroll
        for (int nt = 0; nt < 8; nt++)
#pragma unroll
            for (int i = 0; i < 4; i++) sacc[nt][i] = 0.f;

#pragma unroll
        for (int c = 0; c < 4; c++) {
            uint32_t kb2[8][2];
#pragma unroll
            for (int ntp = 0; ntp < 4; ntp++) {
                const uint32_t a = Kb + (ntp * 16 + kj) * 128
                    + ((((uint32_t)(c * 2) + kcsel) ^ (uint32_t)r8) << 4);
                LDSM_X4(kb2[2 * ntp][0], kb2[2 * ntp][1],
                        kb2[2 * ntp + 1][0], kb2[2 * ntp + 1][1], a);
            }
#pragma unroll
            for (int nt = 0; nt < 8; nt++)
                mma_f16(sacc[nt], qf[c], kb2[nt][0], kb2[nt][1]);
        }

        // ---- softmax (unstabilized), mask from smem; P -> A-fragments ----
        uint32_t pah[8][2];
#pragma unroll
        for (int nt = 0; nt < 8; nt++) {
            float2 mk0 = *reinterpret_cast<const float2*>(
                Mb + mrow0_off + nt * 32);
            float2 mk1 = *reinterpret_cast<const float2*>(
                Mb + mrow1_off + nt * 32);
            float p00 = __expf(sacc[nt][0] + mk0.x);
            float p01 = __expf(sacc[nt][1] + mk0.y);
            float p10 = __expf(sacc[nt][2] + mk1.x);
            float p11 = __expf(sacc[nt][3] + mk1.y);
            l0 += p00 + p01;
            l1 += p10 + p11;
            pah[nt][0] = h2bits(__floats2half2_rn(p00, p01));
            pah[nt][1] = h2bits(__floats2half2_rn(p10, p11));
        }

        // ---- O += P @ V : 4 k-steps of 16, P straight from registers ----
#pragma unroll
        for (int c = 0; c < 4; c++) {
            uint32_t pa[4] = { pah[2 * c][0], pah[2 * c][1],
                               pah[2 * c + 1][0], pah[2 * c + 1][1] };
            uint32_t vb2[8][2];
#pragma unroll
            for (int ntp = 0; ntp < 4; ntp++) {
                const uint32_t a = Vb + (c * 16 + vj) * 128
                    + ((((uint32_t)(ntp * 2) + vcsel) ^ (uint32_t)r8) << 4);
                LDSM_X4_T(vb2[2 * ntp][0], vb2[2 * ntp][1],
                          vb2[2 * ntp + 1][0], vb2[2 * ntp + 1][1], a);
            }
#pragma unroll
            for (int nt = 0; nt < 8; nt++)
                mma_f16(oacc[nt], pa, vb2[nt][0], vb2[nt][1]);
        }
    }

    // ---- finalize: reduce l over quad lanes, normalize, store ----
    l0 += __shfl_xor_sync(0xffffffffu, l0, 1);
    l0 += __shfl_xor_sync(0xffffffffu, l0, 2);
    l1 += __shfl_xor_sync(0xffffffffu, l1, 1);
    l1 += __shfl_xor_sync(0xffffffffu, l1, 2);
    const float inv0 = 1.f / l0;
    const float inv1 = 1.f / l1;

    __half* ob = o + ((size_t)(b * SEQ_N) + qrb) * INNER + h * DHEAD;
#pragma unroll
    for (int nt = 0; nt < 8; nt++) {
        const int cb = nt * 8 + 2 * gq;
        *reinterpret_cast<__half2*>(&ob[(size_t)gr * INNER + cb]) =
            __floats2half2_rn(oacc[nt][0] * inv0, oacc[nt][1] * inv0);
        *reinterpret_cast<__half2*>(&ob[(size_t)(gr + 8) * INNER + cb]) =
            __floats2half2_rn(oacc[nt][2] * inv1, oacc[nt][3] * inv1);
    }
}

// ---------------------------------------------------------------------------
// Launch
// ---------------------------------------------------------------------------
extern "C" void kernel_launch(void* const* d_in, const int* in_sizes, int n_in,
                              void* d_out, int out_size)
{
    const float* x       = (const float*)d_in[0];
    const float* context = (const float*)d_in[1];
    const float* mask    = (const float*)d_in[2];
    const float* ln_w    = (const float*)d_in[3];
    const float* Wq      = (const float*)d_in[4];
    const float* Wkv     = (const float*)d_in[5];
    const float* Wo      = (const float*)d_in[6];
    float* out = (float*)d_out;

    __half *xnh, *ctxh, *qh, *kvh, *aoh, *wqh, *wkvh, *woh;
    cudaGetSymbolAddress((void**)&xnh,  g_xnh);
    cudaGetSymbolAddress((void**)&ctxh, g_ctxh);
    cudaGetSymbolAddress((void**)&qh,   g_qh);
    cudaGetSymbolAddress((void**)&kvh,  g_kvh);
    cudaGetSymbolAddress((void**)&aoh,  g_aoh);
    cudaGetSymbolAddress((void**)&wqh,  g_wqh);
    cudaGetSymbolAddress((void**)&wkvh, g_wkvh);
    cudaGetSymbolAddress((void**)&woh,  g_woh);

    cudaFuncSetAttribute(attn_f16_kernel,
                         cudaFuncAttributeMaxDynamicSharedMemorySize,
                         ATTN_SMEM_BYTES);
    cudaFuncSetAttribute(gemm_dual_kernel,
                         cudaFuncAttributeMaxDynamicSharedMemorySize,
                         GEMM_SMEM_BYTES);

    // 0. converts: weights + context -> fp16
    {
        int n4;
        n4 = DIM * INNER / 4;
        f32_to_f16_kernel<<<(n4 + 255) / 256, 256>>>(Wq, wqh, n4);
        n4 = DIM * 128 / 4;
        f32_to_f16_kernel<<<(n4 + 255) / 256, 256>>>(Wkv, wkvh, n4);
        n4 = INNER * DIM / 4;
        f32_to_f16_kernel<<<(n4 + 255) / 256, 256>>>(Wo, woh, n4);
        n4 = ROWS_TOTAL * DIM / 4;
        f32_to_f16_kernel<<<(n4 + 255) / 256, 256>>>(context, ctxh, n4);
    }

    // 1. layernorm -> fp16
    ln_kernel<<<ROWS_TOTAL, 256>>>(x, ln_w, xnh);

    // 2+3. fused: Wq projection (6 x-tiles) + kv projection (1 x-tile)
    {
        GemmJob jq  = { xnh,  wqh,  qh,  INNER, DIM, 2 };
        GemmJob jkv = { ctxh, wkvh, kvh, 128,   DIM, 1 };
        gemm_dual_kernel<<<dim3(7, ROWS_TOTAL / 128), 256, GEMM_SMEM_BYTES>>>(
            jq, 6, jkv);
    }

    // 4. attention: CTA = (b, 32 q-rows, 4-head group); K/V + mask shared
    attn_f16_kernel<<<dim3(SEQ_N / 32, HEADS / 4, BATCH), 256,
                      ATTN_SMEM_BYTES>>>(qh, kvh, mask, aoh);

    // 5. out = ao @ Wo -> fp32
    {
        GemmJob jo = { aoh, woh, out, DIM, INNER, 0 };
        gemm_dual_kernel<<<dim3(6, ROWS_TOTAL / 128), 256, GEMM_SMEM_BYTES>>>(
            jo, 6, jo);
    }
}

// round 16
// speedup vs baseline: 12.2045x; 1.1362x over previous
#include <cuda_runtime.h>
#include <cuda_fp16.h>
#include <cstdint>
#include <math.h>

// Problem constants
#define BATCH   4
#define SEQ_N   2048
#define SEQ_J   2048
#define DIM     768
#define HEADS   12
#define DHEAD   64
#define INNER   (HEADS * DHEAD)   // 768
#define SCALE   0.125f            // 64^-0.5

#define ROWS_TOTAL (BATCH * SEQ_N) // 8192

// ---------------------------------------------------------------------------
// Scratch (static device allocations; no cudaMalloc allowed)
// ---------------------------------------------------------------------------
__device__ __half g_xnh [(size_t)ROWS_TOTAL * DIM];    // layernorm(x), fp16
__device__ __half g_ctxh[(size_t)ROWS_TOTAL * DIM];    // context, fp16
__device__ __half g_qh  [(size_t)ROWS_TOTAL * INNER];  // q, fp16, pre-scaled
__device__ __half g_kvh [(size_t)ROWS_TOTAL * 128];    // [k|v] fp16
__device__ __half g_aoh [(size_t)ROWS_TOTAL * INNER];  // attn output, fp16
__device__ __half g_wqh [DIM * INNER];                 // Wq fp16
__device__ __half g_wkvh[DIM * 128];                   // Wkv fp16
__device__ __half g_woh [INNER * DIM];                 // Wo fp16

// ===========================================================================
// helpers (sm_80+ portable PTX — compiles for plain sm_103)
// ===========================================================================
__device__ __forceinline__ void mma_f16(float* d, const uint32_t* a,
                                        uint32_t b0, uint32_t b1) {
    asm volatile(
        "mma.sync.aligned.m16n8k16.row.col.f32.f16.f16.f32 "
        "{%0,%1,%2,%3}, {%4,%5,%6,%7}, {%8,%9}, {%0,%1,%2,%3};"
        : "+f"(d[0]), "+f"(d[1]), "+f"(d[2]), "+f"(d[3])
        : "r"(a[0]), "r"(a[1]), "r"(a[2]), "r"(a[3]), "r"(b0), "r"(b1));
}
__device__ __forceinline__ uint32_t smem_to_u32(const void* p) {
    uint32_t a;
    asm("{ .reg .u64 t; cvta.to.shared.u64 t, %1; cvt.u32.u64 %0, t; }"
        : "=r"(a) : "l"(p));
    return a;
}
__device__ __forceinline__ uint32_t h2bits(__half2 h) {
    return *reinterpret_cast<uint32_t*>(&h);
}
#define CP_ASYNC16(dst_u32, src_ptr) \
    asm volatile("cp.async.cg.shared.global [%0], [%1], 16;" \
        :: "r"(dst_u32), "l"(src_ptr))
#define CP_COMMIT() asm volatile("cp.async.commit_group;" ::: "memory")
#define CP_WAIT_ALL() asm volatile("cp.async.wait_group 0;" ::: "memory")
#define CP_WAIT_1()   asm volatile("cp.async.wait_group 1;" ::: "memory")

#define LDSM_X4(r0, r1, r2, r3, addr) \
    asm volatile("ldmatrix.sync.aligned.m8n8.x4.shared.b16 {%0,%1,%2,%3}, [%4];" \
        : "=r"(r0), "=r"(r1), "=r"(r2), "=r"(r3) : "r"(addr))
#define LDSM_X4_T(r0, r1, r2, r3, addr) \
    asm volatile("ldmatrix.sync.aligned.m8n8.x4.trans.shared.b16 {%0,%1,%2,%3}, [%4];" \
        : "=r"(r0), "=r"(r1), "=r"(r2), "=r"(r3) : "r"(addr))

// ---------------------------------------------------------------------------
// LayerNorm: one block per row of 768, fp16 output
// ---------------------------------------------------------------------------
__global__ void ln_kernel(const float* __restrict__ x,
                          const float* __restrict__ w,
                          __half* __restrict__ y)
{
    const int row = blockIdx.x;
    const float* xr = x + (size_t)row * DIM;
    float v[3];
    float s = 0.f, s2 = 0.f;
#pragma unroll
    for (int t = 0; t < 3; t++) {
        int i = threadIdx.x + t * 256;
        float vv = xr[i];
        v[t] = vv;
        s += vv; s2 += vv * vv;
    }
#pragma unroll
    for (int o = 16; o > 0; o >>= 1) {
        s  += __shfl_xor_sync(0xffffffffu, s,  o);
        s2 += __shfl_xor_sync(0xffffffffu, s2, o);
    }
    __shared__ float rs[8], rs2[8];
    int wid = threadIdx.x >> 5, lid = threadIdx.x & 31;
    if (lid == 0) { rs[wid] = s; rs2[wid] = s2; }
    __syncthreads();
    if (wid == 0) {
        s  = (lid < 8) ? rs[lid]  : 0.f;
        s2 = (lid < 8) ? rs2[lid] : 0.f;
#pragma unroll
        for (int o = 4; o > 0; o >>= 1) {
            s  += __shfl_xor_sync(0xffffffffu, s,  o);
            s2 += __shfl_xor_sync(0xffffffffu, s2, o);
        }
        if (lid == 0) { rs[0] = s; rs2[0] = s2; }
    }
    __syncthreads();
    const float mu   = rs[0] * (1.f / DIM);
    const float var  = rs2[0] * (1.f / DIM) - mu * mu;
    const float rstd = rsqrtf(var + 1e-5f);
    __half* yr = y + (size_t)row * DIM;
#pragma unroll
    for (int t = 0; t < 3; t++) {
        int i = threadIdx.x + t * 256;
        yr[i] = __float2half_rn((v[t] - mu) * rstd * w[i]);
    }
}

// ---------------------------------------------------------------------------
// fp32 -> fp16 elementwise convert
// ---------------------------------------------------------------------------
__global__ void f32_to_f16_kernel(const float* __restrict__ src,
                                  __half* __restrict__ dst, int n4)
{
    int i = blockIdx.x * blockDim.x + threadIdx.x;
    if (i < n4) {
        float4 v = reinterpret_cast<const float4*>(src)[i];
        reinterpret_cast<uint2*>(dst)[i] =
            make_uint2(h2bits(__floats2half2_rn(v.x, v.y)),
                       h2bits(__floats2half2_rn(v.z, v.w)));
    }
}

// ---------------------------------------------------------------------------
// fp16 tensor-core GEMM (all operands fp16), cp.async 3-stage pipeline.
// Dual-job: blockIdx.x < nx0 -> job0, else job1.  (unchanged from round 14)
// ---------------------------------------------------------------------------
#define AST 40
#define A_STG_B 10240
#define B_STG_B 8192
#define GEMM_SMEM_BYTES (3 * (A_STG_B + B_STG_B))   // 55296

struct GemmJob {
    const __half* A;
    const __half* B;
    void*         C;
    int N, K, out_mode;
};

__device__ __forceinline__ void gemm_stage(uint32_t sbase, int stg,
                                           const __half* A, const __half* B,
                                           int m0, int n0, int kt,
                                           int N, int K, int tid)
{
    const uint32_t ab = sbase + stg * (A_STG_B + B_STG_B);
    const uint32_t bb = ab + A_STG_B;
#pragma unroll
    for (int t = 0; t < 2; t++) {
        const int e = tid + t * 256;
        const int ar = e >> 2, ac = e & 3;
        CP_ASYNC16(ab + (uint32_t)(ar * 80 + ac * 16),
                   &A[(size_t)(m0 + ar) * K + kt + ac * 8]);
        const int bk = e >> 4, bc = e & 15;
        CP_ASYNC16(bb + (uint32_t)(bk * 256 + ((bc ^ (bk & 7)) * 16)),
                   &B[(size_t)(kt + bk) * N + n0 + bc * 8]);
    }
    CP_COMMIT();
}

__global__ __launch_bounds__(256, 2)
void gemm_dual_kernel(GemmJob j0, int nx0, GemmJob j1)
{
    extern __shared__ char gsm[];
    const uint32_t sbase = smem_to_u32(gsm);

    GemmJob jb;
    int bx;
    if ((int)blockIdx.x < nx0) { jb = j0; bx = blockIdx.x; }
    else                       { jb = j1; bx = blockIdx.x - nx0; }
    const int N = jb.N;
    const int K = jb.K;

    const int tid  = threadIdx.x;
    const int wid  = tid >> 5;
    const int lane = tid & 31;
    const int g8   = lane >> 3;
    const int r8   = lane & 7;
    const int gr   = lane >> 2;
    const int gq   = lane & 3;
    const int wm   = (wid & 3) * 32;
    const int wn   = (wid >> 2) * 64;
    const int m0   = blockIdx.y * 128;
    const int n0   = bx * 128;

    float acc[2][8][4];
#pragma unroll
    for (int ms = 0; ms < 2; ms++)
#pragma unroll
        for (int nt = 0; nt < 8; nt++)
#pragma unroll
            for (int i = 0; i < 4; i++) acc[ms][nt][i] = 0.f;

    const uint32_t arow  = (uint32_t)(wm + ((g8 & 1) << 3) + r8);
    const uint32_t akc   = (uint32_t)(g8 >> 1);
    const uint32_t bkrow = (uint32_t)(((g8 & 1) << 3) + r8);
    const uint32_t bnc   = (uint32_t)((wn >> 3) + (g8 >> 1));

    const int niter = K / 32;

    gemm_stage(sbase, 0, jb.A, jb.B, m0, n0, 0,  N, K, tid);
    gemm_stage(sbase, 1, jb.A, jb.B, m0, n0, 32, N, K, tid);

    int stg = 0;
    for (int it = 0; it < niter; it++) {
        CP_WAIT_1();
        __syncthreads();

        if (it + 2 < niter)
            gemm_stage(sbase, (stg + 2) % 3, jb.A, jb.B, m0, n0,
                       (it + 2) * 32, N, K, tid);

        const uint32_t ab = sbase + stg * (A_STG_B + B_STG_B);
        const uint32_t bb = ab + A_STG_B;

#pragma unroll
        for (int c = 0; c < 2; c++) {
            uint32_t af[2][4];
#pragma unroll
            for (int ms = 0; ms < 2; ms++) {
                const uint32_t a = ab + (arow + ms * 16) * 80
                                 + (c * 2 + akc) * 16;
                LDSM_X4(af[ms][0], af[ms][1], af[ms][2], af[ms][3], a);
            }
            uint32_t bf[8][2];
#pragma unroll
            for (int ntp = 0; ntp < 4; ntp++) {
                const uint32_t row = (uint32_t)(c * 16) + bkrow;
                const uint32_t a = bb + row * 256
                                 + (((bnc + ntp * 2) ^ (uint32_t)r8) << 4);
                LDSM_X4_T(bf[2 * ntp][0], bf[2 * ntp][1],
                          bf[2 * ntp + 1][0], bf[2 * ntp + 1][1], a);
            }
#pragma unroll
            for (int nt = 0; nt < 8; nt++)
#pragma unroll
                for (int ms = 0; ms < 2; ms++)
                    mma_f16(acc[ms][nt], af[ms], bf[nt][0], bf[nt][1]);
        }
        stg = (stg + 1) % 3;
    }

    const float alpha = (jb.out_mode == 2) ? SCALE : 1.0f;
    float*  Cf = reinterpret_cast<float*>(jb.C);
    __half* Ch = reinterpret_cast<__half*>(jb.C);
#pragma unroll
    for (int ms = 0; ms < 2; ms++) {
        const int mrow0 = m0 + wm + ms * 16 + gr;
#pragma unroll
        for (int nt = 0; nt < 8; nt++) {
            const int col = n0 + wn + nt * 8 + 2 * gq;
            if (jb.out_mode == 0) {
                *reinterpret_cast<float2*>(&Cf[(size_t)mrow0 * N + col]) =
                    make_float2(acc[ms][nt][0], acc[ms][nt][1]);
                *reinterpret_cast<float2*>(&Cf[(size_t)(mrow0 + 8) * N + col]) =
                    make_float2(acc[ms][nt][2], acc[ms][nt][3]);
            } else {
                *reinterpret_cast<__half2*>(&Ch[(size_t)mrow0 * N + col]) =
                    __floats2half2_rn(acc[ms][nt][0] * alpha,
                                      acc[ms][nt][1] * alpha);
                *reinterpret_cast<__half2*>(&Ch[(size_t)(mrow0 + 8) * N + col]) =
                    __floats2half2_rn(acc[ms][nt][2] * alpha,
                                      acc[ms][nt][3] * alpha);
            }
        }
    }
}

// ---------------------------------------------------------------------------
// fp16 mma.sync flash attention — multi-query, 32 rows per warp.
// CTA = (b, 32 q-rows, 4-head group), 128 threads = 4 warps.
// Warp w owns head hg*4+w, all 32 rows (two 16-row M-tiles). Each K/V
// fragment LDSM now feeds BOTH M-tiles -> per-row smem traffic halves.
// Mask tile (32x64 fp32) cp.async-staged, shared by all head-warps.
// P in registers (FA2). launch_bounds(128,2): 256-reg budget, 2 CTAs/SM.
// ---------------------------------------------------------------------------
#define MOFF   16384
#define MROWB  272                     // mask row stride bytes (68 floats)
#define STG_B  (16384 + 32 * MROWB)    // 25088
#define ATTN_SMEM_BYTES (2 * STG_B)    // 50176
#define NTILES (SEQ_J / 64)            // 32

__device__ __forceinline__ void stage_kvm(uint32_t sbase, int buf,
                                          const __half* kv_tile,
                                          const float* mask_tile, int tid)
{
    const uint32_t base = sbase + buf * STG_B;
    // K/V: 64 rows x 256B = 1024 chunks, 128 threads -> 8 each
#pragma unroll
    for (int t = 0; t < 8; t++) {
        const int e   = tid + t * 128;
        const int jj  = e >> 4;
        const int c16 = e & 15;
        const char* src = reinterpret_cast<const char*>(kv_tile)
                          + (size_t)jj * 256 + c16 * 16;
        const uint32_t sw = (uint32_t)(jj & 7) << 4;
        const uint32_t dst = (c16 < 8)
            ? base + (uint32_t)jj * 128 + (((uint32_t)c16 * 16) ^ sw)
            : base + 8192 + (uint32_t)jj * 128 + (((uint32_t)(c16 - 8) * 16) ^ sw);
        CP_ASYNC16(dst, src);
    }
    // mask: 32 rows x 256B = 512 chunks -> 4 each
#pragma unroll
    for (int t = 0; t < 4; t++) {
        const int e = tid + t * 128;
        const int r = e >> 4;
        const int c = e & 15;
        CP_ASYNC16(base + MOFF + (uint32_t)(r * MROWB + c * 16),
                   &mask_tile[(size_t)r * SEQ_J + c * 4]);
    }
    CP_COMMIT();
}

__global__ __launch_bounds__(128, 2)
void attn_f16_kernel(const __half* __restrict__ q,
                     const __half* __restrict__ kv,
                     const float* __restrict__ mask, __half* __restrict__ o)
{
    extern __shared__ char smc[];
    const uint32_t sbase = smem_to_u32(smc);

    const int tid  = threadIdx.x;
    const int wid  = tid >> 5;           // 0..3 == head within group
    const int lane = tid & 31;
    const int gr   = lane >> 2;
    const int gq   = lane & 3;
    const int g8   = lane >> 3;
    const int r8   = lane & 7;
    const int h    = blockIdx.y * 4 + wid;
    const int b    = blockIdx.z;
    const int row0 = blockIdx.x * 32;

    // ---- Q fragments: 2 M-tiles x 4 k-steps x 4 regs ----
    uint32_t qf[2][4][4];
#pragma unroll
    for (int ms = 0; ms < 2; ms++) {
        const __half* qb = q + ((size_t)(b * SEQ_N) + row0 + ms * 16) * INNER
                           + h * DHEAD;
#pragma unroll
        for (int c = 0; c < 4; c++) {
            qf[ms][c][0] = *reinterpret_cast<const uint32_t*>(
                &qb[(size_t)(gr    ) * INNER + c * 16 + 2 * gq]);
            qf[ms][c][1] = *reinterpret_cast<const uint32_t*>(
                &qb[(size_t)(gr + 8) * INNER + c * 16 + 2 * gq]);
            qf[ms][c][2] = *reinterpret_cast<const uint32_t*>(
                &qb[(size_t)(gr    ) * INNER + c * 16 + 8 + 2 * gq]);
            qf[ms][c][3] = *reinterpret_cast<const uint32_t*>(
                &qb[(size_t)(gr + 8) * INNER + c * 16 + 8 + 2 * gq]);
        }
    }

    float oacc[2][8][4];
#pragma unroll
    for (int ms = 0; ms < 2; ms++)
#pragma unroll
        for (int nt = 0; nt < 8; nt++)
#pragma unroll
            for (int i = 0; i < 4; i++) oacc[ms][nt][i] = 0.f;
    float lsum[2][2] = {{0.f, 0.f}, {0.f, 0.f}};   // [ms][half]

    const __half* kv_base = kv + (size_t)b * SEQ_J * 128;
    const float* mask_base = mask + ((size_t)(b * SEQ_N) + row0) * SEQ_J;

    const uint32_t kj    = (uint32_t)(((g8 >> 1) << 3) + r8);
    const uint32_t kcsel = (uint32_t)(g8 & 1);
    const uint32_t vj    = (uint32_t)(((g8 & 1) << 3) + r8);
    const uint32_t vcsel = (uint32_t)(g8 >> 1);

    stage_kvm(sbase, 0, kv_base, mask_base, tid);

#pragma unroll 1
    for (int t = 0; t < NTILES; t++) {
        const int cur = t & 1;

        CP_WAIT_ALL();
        __syncthreads();

        if (t + 1 < NTILES)
            stage_kvm(sbase, cur ^ 1,
                      kv_base + (size_t)(t + 1) * 64 * 128,
                      mask_base + (size_t)(t + 1) * 64, tid);

        const uint32_t Kb = sbase + cur * STG_B;
        const uint32_t Vb = Kb + 8192;
        const char* Mb = smc + cur * STG_B + MOFF;

        // ---- S = Q @ K^T : each K fragment feeds both M-tiles ----
        float sacc[2][8][4];
#pragma unroll
        for (int ms = 0; ms < 2; ms++)
#pragma unroll
            for (int nt = 0; nt < 8; nt++)
#pragma unroll
                for (int i = 0; i < 4; i++) sacc[ms][nt][i] = 0.f;

#pragma unroll
        for (int c = 0; c < 4; c++) {
            uint32_t kb2[8][2];
#pragma unroll
            for (int ntp = 0; ntp < 4; ntp++) {
                const uint32_t a = Kb + (ntp * 16 + kj) * 128
                    + ((((uint32_t)(c * 2) + kcsel) ^ (uint32_t)r8) << 4);
                LDSM_X4(kb2[2 * ntp][0], kb2[2 * ntp][1],
                        kb2[2 * ntp + 1][0], kb2[2 * ntp + 1][1], a);
            }
#pragma unroll
            for (int nt = 0; nt < 8; nt++)
#pragma unroll
                for (int ms = 0; ms < 2; ms++)
                    mma_f16(sacc[ms][nt], qf[ms][c], kb2[nt][0], kb2[nt][1]);
        }

        // ---- softmax (unstabilized), mask from smem; P -> A-fragments ----
        uint32_t pah[2][8][2];
#pragma unroll
        for (int ms = 0; ms < 2; ms++) {
            const uint32_t m0off = (uint32_t)((ms * 16 + gr) * MROWB + gq * 8);
#pragma unroll
            for (int nt = 0; nt < 8; nt++) {
                float2 mk0 = *reinterpret_cast<const float2*>(
                    Mb + m0off + nt * 32);
                float2 mk1 = *reinterpret_cast<const float2*>(
                    Mb + m0off + 8 * MROWB + nt * 32);
                float p00 = __expf(sacc[ms][nt][0] + mk0.x);
                float p01 = __expf(sacc[ms][nt][1] + mk0.y);
                float p10 = __expf(sacc[ms][nt][2] + mk1.x);
                float p11 = __expf(sacc[ms][nt][3] + mk1.y);
                lsum[ms][0] += p00 + p01;
                lsum[ms][1] += p10 + p11;
                pah[ms][nt][0] = h2bits(__floats2half2_rn(p00, p01));
                pah[ms][nt][1] = h2bits(__floats2half2_rn(p10, p11));
            }
        }

        // ---- O += P @ V : each V fragment feeds both M-tiles ----
#pragma unroll
        for (int c = 0; c < 4; c++) {
            uint32_t vb2[8][2];
#pragma unroll
            for (int ntp = 0; ntp < 4; ntp++) {
                const uint32_t a = Vb + (c * 16 + vj) * 128
                    + ((((uint32_t)(ntp * 2) + vcsel) ^ (uint32_t)r8) << 4);
                LDSM_X4_T(vb2[2 * ntp][0], vb2[2 * ntp][1],
                          vb2[2 * ntp + 1][0], vb2[2 * ntp + 1][1], a);
            }
#pragma unroll
            for (int ms = 0; ms < 2; ms++) {
                uint32_t pa[4] = { pah[ms][2 * c][0], pah[ms][2 * c][1],
                                   pah[ms][2 * c + 1][0], pah[ms][2 * c + 1][1] };
#pragma unroll
                for (int nt = 0; nt < 8; nt++)
                    mma_f16(oacc[ms][nt], pa, vb2[nt][0], vb2[nt][1]);
            }
        }
    }

    // ---- finalize: reduce l over quad lanes, normalize, store ----
#pragma unroll
    for (int ms = 0; ms < 2; ms++) {
        float l0 = lsum[ms][0], l1 = lsum[ms][1];
        l0 += __shfl_xor_sync(0xffffffffu, l0, 1);
        l0 += __shfl_xor_sync(0xffffffffu, l0, 2);
        l1 += __shfl_xor_sync(0xffffffffu, l1, 1);
        l1 += __shfl_xor_sync(0xffffffffu, l1, 2);
        const float inv0 = 1.f / l0;
        const float inv1 = 1.f / l1;

        __half* ob = o + ((size_t)(b * SEQ_N) + row0 + ms * 16) * INNER
                     + h * DHEAD;
#pragma unroll
        for (int nt = 0; nt < 8; nt++) {
            const int cb = nt * 8 + 2 * gq;
            *reinterpret_cast<__half2*>(&ob[(size_t)gr * INNER + cb]) =
                __floats2half2_rn(oacc[ms][nt][0] * inv0,
                                  oacc[ms][nt][1] * inv0);
            *reinterpret_cast<__half2*>(&ob[(size_t)(gr + 8) * INNER + cb]) =
                __floats2half2_rn(oacc[ms][nt][2] * inv1,
                                  oacc[ms][nt][3] * inv1);
        }
    }
}

// ---------------------------------------------------------------------------
// Launch
// ---------------------------------------------------------------------------
extern "C" void kernel_launch(void* const* d_in, const int* in_sizes, int n_in,
                              void* d_out, int out_size)
{
    const float* x       = (const float*)d_in[0];
    const float* context = (const float*)d_in[1];
    const float* mask    = (const float*)d_in[2];
    const float* ln_w    = (const float*)d_in[3];
    const float* Wq      = (const float*)d_in[4];
    const float* Wkv     = (const float*)d_in[5];
    const float* Wo      = (const float*)d_in[6];
    float* out = (float*)d_out;

    __half *xnh, *ctxh, *qh, *kvh, *aoh, *wqh, *wkvh, *woh;
    cudaGetSymbolAddress((void**)&xnh,  g_xnh);
    cudaGetSymbolAddress((void**)&ctxh, g_ctxh);
    cudaGetSymbolAddress((void**)&qh,   g_qh);
    cudaGetSymbolAddress((void**)&kvh,  g_kvh);
    cudaGetSymbolAddress((void**)&aoh,  g_aoh);
    cudaGetSymbolAddress((void**)&wqh,  g_wqh);
    cudaGetSymbolAddress((void**)&wkvh, g_wkvh);
    cudaGetSymbolAddress((void**)&woh,  g_woh);

    cudaFuncSetAttribute(attn_f16_kernel,
                         cudaFuncAttributeMaxDynamicSharedMemorySize,
                         ATTN_SMEM_BYTES);
    cudaFuncSetAttribute(gemm_dual_kernel,
                         cudaFuncAttributeMaxDynamicSharedMemorySize,
                         GEMM_SMEM_BYTES);

    // 0. converts: weights + context -> fp16
    {
        int n4;
        n4 = DIM * INNER / 4;
        f32_to_f16_kernel<<<(n4 + 255) / 256, 256>>>(Wq, wqh, n4);
        n4 = DIM * 128 / 4;
        f32_to_f16_kernel<<<(n4 + 255) / 256, 256>>>(Wkv, wkvh, n4);
        n4 = INNER * DIM / 4;
        f32_to_f16_kernel<<<(n4 + 255) / 256, 256>>>(Wo, woh, n4);
        n4 = ROWS_TOTAL * DIM / 4;
        f32_to_f16_kernel<<<(n4 + 255) / 256, 256>>>(context, ctxh, n4);
    }

    // 1. layernorm -> fp16
    ln_kernel<<<ROWS_TOTAL, 256>>>(x, ln_w, xnh);

    // 2+3. fused: Wq projection (6 x-tiles) + kv projection (1 x-tile)
    {
        GemmJob jq  = { xnh,  wqh,  qh,  INNER, DIM, 2 };
        GemmJob jkv = { ctxh, wkvh, kvh, 128,   DIM, 1 };
        gemm_dual_kernel<<<dim3(7, ROWS_TOTAL / 128), 256, GEMM_SMEM_BYTES>>>(
            jq, 6, jkv);
    }

    // 4. attention: 4 warps/CTA, warp = 1 head x 32 rows (K/V LDSM amortized)
    attn_f16_kernel<<<dim3(SEQ_N / 32, HEADS / 4, BATCH), 128,
                      ATTN_SMEM_BYTES>>>(qh, kvh, mask, aoh);

    // 5. out = ao @ Wo -> fp32
    {
        GemmJob jo = { aoh, woh, out, DIM, INNER, 0 };
        gemm_dual_kernel<<<dim3(6, ROWS_TOTAL / 128), 256, GEMM_SMEM_BYTES>>>(
            jo, 6, jo);
    }
}